// round 6
// baseline (speedup 1.0000x reference)
#include <cuda_runtime.h>
#include <cuda_bf16.h>
#include <cstdint>
#include <math.h>

#define Bb     16
#define Hh     56
#define Wd     56
#define Nn     3136
#define Dd     256
#define HEADS  8
#define HD     32
#define WIN    7
#define WIN2   49
#define NWH    8
#define NW     64
#define DISP   3
#define FF     1024
#define CPBH   512
#define EPSLN  1e-5f
#define MROWS  50176   // B * N

// ================= PTX helpers (plain compute_103 features only) =================
__device__ __forceinline__ uint32_t smem_to_u32(const void* p) {
    uint32_t a;
    asm("{ .reg .u64 t; cvta.to.shared.u64 t, %1; cvt.u32.u64 %0, t; }" : "=r"(a) : "l"(p));
    return a;
}
#define CP_ASYNC_CG(dst, src) \
    asm volatile("cp.async.cg.shared.global [%0], [%1], 16;" :: "r"(dst), "l"(src))
#define CP_ASYNC_COMMIT() asm volatile("cp.async.commit_group;" ::: "memory")
#define CP_ASYNC_WAIT(n)  asm volatile("cp.async.wait_group %0;" :: "n"(n) : "memory")

__device__ __forceinline__ void ldsm_x4(uint32_t* r, uint32_t addr) {
    asm volatile("ldmatrix.sync.aligned.m8n8.x4.shared.b16 {%0,%1,%2,%3}, [%4];"
        : "=r"(r[0]), "=r"(r[1]), "=r"(r[2]), "=r"(r[3]) : "r"(addr));
}
__device__ __forceinline__ void mma_bf16(float* c, const uint32_t* a, const uint32_t* b) {
    asm volatile("mma.sync.aligned.m16n8k16.row.col.f32.bf16.bf16.f32 "
        "{%0,%1,%2,%3},{%4,%5,%6,%7},{%8,%9},{%0,%1,%2,%3};"
        : "+f"(c[0]), "+f"(c[1]), "+f"(c[2]), "+f"(c[3])
        : "r"(a[0]), "r"(a[1]), "r"(a[2]), "r"(a[3]), "r"(b[0]), "r"(b[1]));
}

// ================= device scratch =================
__device__ float         g_xm  [MROWS * Dd];
__device__ __nv_bfloat16 g_xmh [MROWS * Dd];
__device__ __nv_bfloat16 g_xml [MROWS * Dd];
__device__ float         g_qkv [MROWS * 3 * Dd];
__device__ __nv_bfloat16 g_ath [MROWS * Dd];
__device__ __nv_bfloat16 g_atl [MROWS * Dd];
__device__ __nv_bfloat16 g_ffh [MROWS * FF];
__device__ __nv_bfloat16 g_ffl [MROWS * FF];
__device__ float         g_cpb [HEADS * WIN2 * WIN2];
// transposed bf16 weights (hi/lo), per layer:
// [0) qkvT 768x256 | 196608) owT 256x256 | 262144) fw1T 1024x256 | 524288) fw2T 256x1024
#define WLSTRIDE 786432
__device__ __nv_bfloat16 g_wth [2 * WLSTRIDE];
__device__ __nv_bfloat16 g_wtl [2 * WLSTRIDE];

// ================= small helpers =================
__device__ __forceinline__ uint32_t pack_bf2(float a, float b) {
    return (uint32_t)__bfloat16_as_ushort(__float2bfloat16(a)) |
           ((uint32_t)__bfloat16_as_ushort(__float2bfloat16(b)) << 16);
}
__device__ __forceinline__ void split_f4(float4 v, uint2& hi, uint2& lo) {
    __nv_bfloat16 hx = __float2bfloat16(v.x), hy = __float2bfloat16(v.y);
    __nv_bfloat16 hz = __float2bfloat16(v.z), hw = __float2bfloat16(v.w);
    hi.x = (uint32_t)__bfloat16_as_ushort(hx) | ((uint32_t)__bfloat16_as_ushort(hy) << 16);
    hi.y = (uint32_t)__bfloat16_as_ushort(hz) | ((uint32_t)__bfloat16_as_ushort(hw) << 16);
    lo.x = pack_bf2(v.x - __bfloat162float(hx), v.y - __bfloat162float(hy));
    lo.y = pack_bf2(v.z - __bfloat162float(hz), v.w - __bfloat162float(hw));
}

// ================= add SPE =================
__global__ void add_spe_kernel(const float* __restrict__ x, const float* __restrict__ spe,
                               float* __restrict__ xm, __nv_bfloat16* __restrict__ xh,
                               __nv_bfloat16* __restrict__ xl, int n4) {
    int i = blockIdx.x * blockDim.x + threadIdx.x;
    if (i < n4) {
        float4 a = ((const float4*)x)[i];
        float4 b = ((const float4*)spe)[i];
        a.x += b.x; a.y += b.y; a.z += b.z; a.w += b.w;
        ((float4*)xm)[i] = a;
        uint2 h, l; split_f4(a, h, l);
        ((uint2*)xh)[i] = h;
        ((uint2*)xl)[i] = l;
    }
}

// ================= weight transpose + bf16 split: W[K,N] -> T[N,K], z = layer =================
__global__ void wtconv_kernel(const float* __restrict__ W, __nv_bfloat16* __restrict__ Th,
                              __nv_bfloat16* __restrict__ Tl, int K, int N,
                              size_t wstride, size_t tstride) {
    W  += (size_t)blockIdx.z * wstride;
    Th += (size_t)blockIdx.z * tstride;
    Tl += (size_t)blockIdx.z * tstride;
    __shared__ float t[32][33];
    int bn = blockIdx.x * 32, bk = blockIdx.y * 32;
    int tx = threadIdx.x, ty = threadIdx.y;
    #pragma unroll
    for (int j = 0; j < 32; j += 8)
        t[ty + j][tx] = W[(size_t)(bk + ty + j) * N + bn + tx];
    __syncthreads();
    #pragma unroll
    for (int j = 0; j < 32; j += 8) {
        float v = t[tx][ty + j];
        __nv_bfloat16 h = __float2bfloat16(v);
        size_t o = (size_t)(bn + ty + j) * K + bk + tx;
        Th[o] = h;
        Tl[o] = __float2bfloat16(v - __bfloat162float(h));
    }
}

// ================= CPB MLP =================
__global__ void cpb_kernel(const float* __restrict__ cw1, const float* __restrict__ cb1,
                           const float* __restrict__ cw2, const float* __restrict__ cb2,
                           float* __restrict__ cpb) {
    int p = blockIdx.x;
    int i = p / WIN2, j = p % WIN2;
    float dy = (float)(j / WIN - i / WIN);
    float dx = (float)(j % WIN - i % WIN);
    float r0 = ((dy > 0.f) - (dy < 0.f)) * log1pf(fabsf(dy));
    float r1 = ((dx > 0.f) - (dx < 0.f)) * log1pf(fabsf(dx));
    int tid = threadIdx.x;
    int c0 = tid, c1 = tid + 256;
    float h0 = fmaxf(r0 * cw1[c0] + r1 * cw1[CPBH + c0] + cb1[c0], 0.f);
    float h1 = fmaxf(r0 * cw1[c1] + r1 * cw1[CPBH + c1] + cb1[c1], 0.f);
    __shared__ float red[256];
    for (int h = 0; h < HEADS; h++) {
        red[tid] = h0 * cw2[c0 * HEADS + h] + h1 * cw2[c1 * HEADS + h];
        __syncthreads();
        for (int s = 128; s > 0; s >>= 1) {
            if (tid < s) red[tid] += red[tid + s];
            __syncthreads();
        }
        if (tid == 0) cpb[h * (WIN2 * WIN2) + p] = red[0] + cb2[h];
        __syncthreads();
    }
}

// ================= HMMA bf16-split GEMM (generic, 256x128 tile) =================
#define SAS      40                         // padded row stride (elems), 80B
#define AH_OFF   0
#define AL_OFF   20480                      // 256*80
#define BH_OFF   40960
#define BL_OFF   51200                      // +128*80
#define STAGE_B  61440
#define STAGES   3
#define GEMM_SMEM (STAGES * STAGE_B)        // 184320 B

template<int ACT, bool GATHER, int OUTMODE>
__global__ void __launch_bounds__(256, 1)
hgemm_kernel(const __nv_bfloat16* __restrict__ Ah, const __nv_bfloat16* __restrict__ Al,
             const __nv_bfloat16* __restrict__ Bth, const __nv_bfloat16* __restrict__ Btl,
             const float* __restrict__ bias, float* __restrict__ Cf,
             __nv_bfloat16* __restrict__ Ch, __nv_bfloat16* __restrict__ Cl,
             int Ntot, int K) {
    extern __shared__ char smem_raw[];
    const uint32_t sbase = smem_to_u32(smem_raw);
    const int tid  = threadIdx.x;
    const int lane = tid & 31, wid = tid >> 5;
    const int warpM = wid >> 1, warpN = wid & 1;   // 4x2
    const int bm = blockIdx.y * 256, bn = blockIdx.x * 128;

    const __nv_bfloat16 *pAh[4], *pAl[4], *pBh[2], *pBl[2];
    uint32_t aoff[4], boff[2];
    #pragma unroll
    for (int l = 0; l < 4; l++) {
        int c = tid + l * 256;
        int r = c >> 2, q = c & 3;
        int gm = bm + r;
        if (GATHER) {
            int b = gm / Nn, rem = gm - b * Nn;
            int h = rem / Wd, w = rem - h * Wd;
            h = (h + DISP) % Hh; w = (w + DISP) % Wd;
            gm = b * Nn + h * Wd + w;
        }
        pAh[l] = Ah + (size_t)gm * K + q * 8;
        pAl[l] = Al + (size_t)gm * K + q * 8;
        aoff[l] = (uint32_t)(r * (SAS * 2) + q * 16);
    }
    #pragma unroll
    for (int l = 0; l < 2; l++) {
        int c = tid + l * 256;
        int r = c >> 2, q = c & 3;
        pBh[l] = Bth + (size_t)(bn + r) * K + q * 8;
        pBl[l] = Btl + (size_t)(bn + r) * K + q * 8;
        boff[l] = (uint32_t)(r * (SAS * 2) + q * 16);
    }

    float acc[4][8][4];
    #pragma unroll
    for (int m = 0; m < 4; m++)
        #pragma unroll
        for (int n = 0; n < 8; n++)
            #pragma unroll
            for (int e = 0; e < 4; e++) acc[m][n][e] = 0.f;

    const int nch = K >> 5;

    auto load_stage = [&](int c, int sc) {
        uint32_t stg = sbase + (uint32_t)sc * STAGE_B;
        int kt = c << 5;
        #pragma unroll
        for (int l = 0; l < 4; l++) {
            CP_ASYNC_CG(stg + AH_OFF + aoff[l], pAh[l] + kt);
            CP_ASYNC_CG(stg + AL_OFF + aoff[l], pAl[l] + kt);
        }
        #pragma unroll
        for (int l = 0; l < 2; l++) {
            CP_ASYNC_CG(stg + BH_OFF + boff[l], pBh[l] + kt);
            CP_ASYNC_CG(stg + BL_OFF + boff[l], pBl[l] + kt);
        }
    };

    const int arow  = (lane & 15);
    const int ahalf = (lane >> 4);
    const int bidx  = lane & 7;
    const int bkh   = (lane >> 3) & 1;
    const int bsub  = lane >> 4;

    load_stage(0, 0);
    CP_ASYNC_COMMIT();
    if (nch > 1) load_stage(1, 1);
    CP_ASYNC_COMMIT();

    int sc = 0, scn = 2;
    for (int c = 0; c < nch; c++) {
        CP_ASYNC_WAIT(1);
        __syncthreads();
        if (c + 2 < nch) load_stage(c + 2, scn);
        CP_ASYNC_COMMIT();

        uint32_t stg = sbase + (uint32_t)sc * STAGE_B;
        #pragma unroll
        for (int ks = 0; ks < 2; ks++) {
            uint32_t ah[4][4], al[4][4], bh[8][2], bl[8][2];
            #pragma unroll
            for (int m = 0; m < 4; m++) {
                uint32_t off = (uint32_t)((warpM * 64 + m * 16 + arow) * (SAS * 2)
                                          + (ks * 16 + ahalf * 8) * 2);
                ldsm_x4(ah[m], stg + AH_OFF + off);
                ldsm_x4(al[m], stg + AL_OFF + off);
            }
            #pragma unroll
            for (int pr = 0; pr < 4; pr++) {
                uint32_t off = (uint32_t)((warpN * 64 + pr * 16 + bsub * 8 + bidx) * (SAS * 2)
                                          + (ks * 16 + bkh * 8) * 2);
                uint32_t t[4];
                ldsm_x4(t, stg + BH_OFF + off);
                bh[pr * 2][0] = t[0]; bh[pr * 2][1] = t[1];
                bh[pr * 2 + 1][0] = t[2]; bh[pr * 2 + 1][1] = t[3];
                ldsm_x4(t, stg + BL_OFF + off);
                bl[pr * 2][0] = t[0]; bl[pr * 2][1] = t[1];
                bl[pr * 2 + 1][0] = t[2]; bl[pr * 2 + 1][1] = t[3];
            }
            #pragma unroll
            for (int m = 0; m < 4; m++)
                #pragma unroll
                for (int n = 0; n < 8; n++) mma_bf16(acc[m][n], ah[m], bh[n]);
            #pragma unroll
            for (int m = 0; m < 4; m++)
                #pragma unroll
                for (int n = 0; n < 8; n++) mma_bf16(acc[m][n], ah[m], bl[n]);
            #pragma unroll
            for (int m = 0; m < 4; m++)
                #pragma unroll
                for (int n = 0; n < 8; n++) mma_bf16(acc[m][n], al[m], bh[n]);
        }
        sc = (sc == 2) ? 0 : sc + 1;
        scn = (scn == 2) ? 0 : scn + 1;
    }

    const int g = lane >> 2, q = lane & 3;
    #pragma unroll
    for (int m = 0; m < 4; m++) {
        #pragma unroll
        for (int n = 0; n < 8; n++) {
            int col = bn + warpN * 64 + n * 8 + 2 * q;
            float b0 = bias ? bias[col] : 0.f;
            float b1 = bias ? bias[col + 1] : 0.f;
            #pragma unroll
            for (int hrow = 0; hrow < 2; hrow++) {
                int row = bm + warpM * 64 + m * 16 + g + hrow * 8;
                float v0 = acc[m][n][hrow * 2 + 0] + b0;
                float v1 = acc[m][n][hrow * 2 + 1] + b1;
                if (ACT == 1) {
                    v0 = v0 * 0.5f * (1.f + erff(v0 * 0.7071067811865476f));
                    v1 = v1 * 0.5f * (1.f + erff(v1 * 0.7071067811865476f));
                }
                if (OUTMODE == 0) {
                    *(float2*)(Cf + (size_t)row * Ntot + col) = make_float2(v0, v1);
                } else {
                    __nv_bfloat16 h0 = __float2bfloat16(v0);
                    __nv_bfloat16 h1 = __float2bfloat16(v1);
                    *(uint32_t*)(Ch + (size_t)row * Ntot + col) =
                        (uint32_t)__bfloat16_as_ushort(h0) |
                        ((uint32_t)__bfloat16_as_ushort(h1) << 16);
                    *(uint32_t*)(Cl + (size_t)row * Ntot + col) =
                        pack_bf2(v0 - __bfloat162float(h0), v1 - __bfloat162float(h1));
                }
            }
        }
    }
}

// ================= HMMA GEMM with fused LN + residual epilogue (128x256 tile) =================
// Computes t = A@B^T + bias (Ntot = 256 = full row), then xm[dst] += LN(t)*g+b,
// re-emitting xm fp32 and bf16 hi/lo. GATHEROUT: dst row = roll(+3,+3) of tile row.
#define F_AH 0
#define F_AL 10240
#define F_BH 20480
#define F_BL 40960

template<bool GATHEROUT>
__global__ void __launch_bounds__(256, 1)
hgemm_ln_kernel(const __nv_bfloat16* __restrict__ Ah, const __nv_bfloat16* __restrict__ Al,
                const __nv_bfloat16* __restrict__ Bth, const __nv_bfloat16* __restrict__ Btl,
                const float* __restrict__ bias,
                const float* __restrict__ lng, const float* __restrict__ lnb,
                float* __restrict__ xm, __nv_bfloat16* __restrict__ xh,
                __nv_bfloat16* __restrict__ xl, int K) {
    extern __shared__ char smem_raw[];
    const uint32_t sbase = smem_to_u32(smem_raw);
    const int tid  = threadIdx.x;
    const int lane = tid & 31, wid = tid >> 5;
    const int warpM = wid >> 2, warpN = wid & 3;   // 2x4
    const int bm = blockIdx.y * 128;

    // A: 128 rows x 4 chunks = 512 -> 2/thread; B: 256 rows x 4 = 1024 -> 4/thread
    const __nv_bfloat16 *pAh[2], *pAl[2], *pBh[4], *pBl[4];
    uint32_t aoff[2], boff[4];
    #pragma unroll
    for (int l = 0; l < 2; l++) {
        int c = tid + l * 256;
        int r = c >> 2, q = c & 3;
        pAh[l] = Ah + (size_t)(bm + r) * K + q * 8;
        pAl[l] = Al + (size_t)(bm + r) * K + q * 8;
        aoff[l] = (uint32_t)(r * (SAS * 2) + q * 16);
    }
    #pragma unroll
    for (int l = 0; l < 4; l++) {
        int c = tid + l * 256;
        int r = c >> 2, q = c & 3;
        pBh[l] = Bth + (size_t)r * K + q * 8;
        pBl[l] = Btl + (size_t)r * K + q * 8;
        boff[l] = (uint32_t)(r * (SAS * 2) + q * 16);
    }

    float acc[4][8][4];
    #pragma unroll
    for (int m = 0; m < 4; m++)
        #pragma unroll
        for (int n = 0; n < 8; n++)
            #pragma unroll
            for (int e = 0; e < 4; e++) acc[m][n][e] = 0.f;

    const int nch = K >> 5;

    auto load_stage = [&](int c, int sc) {
        uint32_t stg = sbase + (uint32_t)sc * STAGE_B;
        int kt = c << 5;
        #pragma unroll
        for (int l = 0; l < 2; l++) {
            CP_ASYNC_CG(stg + F_AH + aoff[l], pAh[l] + kt);
            CP_ASYNC_CG(stg + F_AL + aoff[l], pAl[l] + kt);
        }
        #pragma unroll
        for (int l = 0; l < 4; l++) {
            CP_ASYNC_CG(stg + F_BH + boff[l], pBh[l] + kt);
            CP_ASYNC_CG(stg + F_BL + boff[l], pBl[l] + kt);
        }
    };

    const int arow  = (lane & 15);
    const int ahalf = (lane >> 4);
    const int bidx  = lane & 7;
    const int bkh   = (lane >> 3) & 1;
    const int bsub  = lane >> 4;

    load_stage(0, 0);
    CP_ASYNC_COMMIT();
    if (nch > 1) load_stage(1, 1);
    CP_ASYNC_COMMIT();

    int sc = 0, scn = 2;
    for (int c = 0; c < nch; c++) {
        CP_ASYNC_WAIT(1);
        __syncthreads();
        if (c + 2 < nch) load_stage(c + 2, scn);
        CP_ASYNC_COMMIT();

        uint32_t stg = sbase + (uint32_t)sc * STAGE_B;
        #pragma unroll
        for (int ks = 0; ks < 2; ks++) {
            uint32_t ah[4][4], al[4][4], bh[8][2], bl[8][2];
            #pragma unroll
            for (int m = 0; m < 4; m++) {
                uint32_t off = (uint32_t)((warpM * 64 + m * 16 + arow) * (SAS * 2)
                                          + (ks * 16 + ahalf * 8) * 2);
                ldsm_x4(ah[m], stg + F_AH + off);
                ldsm_x4(al[m], stg + F_AL + off);
            }
            #pragma unroll
            for (int pr = 0; pr < 4; pr++) {
                uint32_t off = (uint32_t)((warpN * 64 + pr * 16 + bsub * 8 + bidx) * (SAS * 2)
                                          + (ks * 16 + bkh * 8) * 2);
                uint32_t t[4];
                ldsm_x4(t, stg + F_BH + off);
                bh[pr * 2][0] = t[0]; bh[pr * 2][1] = t[1];
                bh[pr * 2 + 1][0] = t[2]; bh[pr * 2 + 1][1] = t[3];
                ldsm_x4(t, stg + F_BL + off);
                bl[pr * 2][0] = t[0]; bl[pr * 2][1] = t[1];
                bl[pr * 2 + 1][0] = t[2]; bl[pr * 2 + 1][1] = t[3];
            }
            #pragma unroll
            for (int m = 0; m < 4; m++)
                #pragma unroll
                for (int n = 0; n < 8; n++) mma_bf16(acc[m][n], ah[m], bh[n]);
            #pragma unroll
            for (int m = 0; m < 4; m++)
                #pragma unroll
                for (int n = 0; n < 8; n++) mma_bf16(acc[m][n], ah[m], bl[n]);
            #pragma unroll
            for (int m = 0; m < 4; m++)
                #pragma unroll
                for (int n = 0; n < 8; n++) mma_bf16(acc[m][n], al[m], bh[n]);
        }
        sc = (sc == 2) ? 0 : sc + 1;
        scn = (scn == 2) ? 0 : scn + 1;
    }

    // ================= fused LN + residual epilogue =================
    CP_ASYNC_WAIT(0);
    __syncthreads();                     // smem now reusable for LN partials
    float* lns = (float*)smem_raw;       // [128 rows][8]: sum[0..3]=warpN, sumsq[4..7]

    const int g = lane >> 2, q = lane & 3;

    // per-column bias / gamma / beta (16 cols per thread)
    float bias_v[16], gam[16], bet[16];
    #pragma unroll
    for (int n = 0; n < 8; n++) {
        int col = warpN * 64 + n * 8 + 2 * q;
        float2 bv = *(const float2*)(bias + col);
        float2 gv = *(const float2*)(lng + col);
        float2 ev = *(const float2*)(lnb + col);
        bias_v[2*n] = bv.x; bias_v[2*n+1] = bv.y;
        gam[2*n] = gv.x;    gam[2*n+1] = gv.y;
        bet[2*n] = ev.x;    bet[2*n+1] = ev.y;
    }
    #pragma unroll
    for (int m = 0; m < 4; m++)
        #pragma unroll
        for (int n = 0; n < 8; n++) {
            acc[m][n][0] += bias_v[2*n]; acc[m][n][1] += bias_v[2*n+1];
            acc[m][n][2] += bias_v[2*n]; acc[m][n][3] += bias_v[2*n+1];
        }

    // partial sums per row (16 cols), quad-reduce, write warp partial
    #pragma unroll
    for (int m = 0; m < 4; m++) {
        #pragma unroll
        for (int hrow = 0; hrow < 2; hrow++) {
            float s = 0.f, s2 = 0.f;
            #pragma unroll
            for (int n = 0; n < 8; n++) {
                float v0 = acc[m][n][hrow*2], v1 = acc[m][n][hrow*2+1];
                s += v0 + v1;
                s2 += v0*v0 + v1*v1;
            }
            s  += __shfl_xor_sync(~0u, s, 1);  s  += __shfl_xor_sync(~0u, s, 2);
            s2 += __shfl_xor_sync(~0u, s2, 1); s2 += __shfl_xor_sync(~0u, s2, 2);
            if (q == 0) {
                int rowl = warpM * 64 + m * 16 + hrow * 8 + g;
                lns[rowl * 8 + warpN]     = s;
                lns[rowl * 8 + 4 + warpN] = s2;
            }
        }
    }
    __syncthreads();

    #pragma unroll
    for (int m = 0; m < 4; m++) {
        #pragma unroll
        for (int hrow = 0; hrow < 2; hrow++) {
            int rowl = warpM * 64 + m * 16 + hrow * 8 + g;
            float s  = lns[rowl*8+0] + lns[rowl*8+1] + lns[rowl*8+2] + lns[rowl*8+3];
            float s2 = lns[rowl*8+4] + lns[rowl*8+5] + lns[rowl*8+6] + lns[rowl*8+7];
            float mean = s * (1.f / 256.f);
            float var  = s2 * (1.f / 256.f) - mean * mean;
            float inv  = rsqrtf(var + EPSLN);

            int row = bm + rowl;
            int dst = row;
            if (GATHEROUT) {
                int b = row / Nn, rem = row - b * Nn;
                int h = rem / Wd, w = rem - h * Wd;
                dst = b * Nn + ((h + DISP) % Hh) * Wd + ((w + DISP) % Wd);
            }
            #pragma unroll
            for (int n = 0; n < 8; n++) {
                int col = warpN * 64 + n * 8 + 2 * q;
                float v0 = (acc[m][n][hrow*2]   - mean) * inv * gam[2*n]   + bet[2*n];
                float v1 = (acc[m][n][hrow*2+1] - mean) * inv * gam[2*n+1] + bet[2*n+1];
                size_t off = (size_t)dst * Dd + col;
                float2 r = *(float2*)(xm + off);
                r.x += v0; r.y += v1;
                *(float2*)(xm + off) = r;
                __nv_bfloat16 h0 = __float2bfloat16(r.x);
                __nv_bfloat16 h1 = __float2bfloat16(r.y);
                *(uint32_t*)(xh + off) = (uint32_t)__bfloat16_as_ushort(h0) |
                                         ((uint32_t)__bfloat16_as_ushort(h1) << 16);
                *(uint32_t*)(xl + off) = pack_bf2(r.x - __bfloat162float(h0),
                                                  r.y - __bfloat162float(h1));
            }
        }
    }
}

// ================= window attention (emits bf16 hi/lo) =================
#define QS 34
#define DS 52
__global__ void __launch_bounds__(256)
attn_kernel(const float* __restrict__ qkv, const float* __restrict__ tau,
            const float* __restrict__ cpb, __nv_bfloat16* __restrict__ outh,
            __nv_bfloat16* __restrict__ outl, int shifted) {
    __shared__ float sq[64 * QS];
    __shared__ float sk[64 * QS];
    __shared__ float sv[49 * QS];
    __shared__ float sd[64 * DS];

    const int wi   = blockIdx.x;
    const int head = blockIdx.y;
    const int b    = blockIdx.z;
    const int wh = wi >> 3, ww = wi & 7;
    const int tid = threadIdx.x;

    for (int e = tid; e < 64 * 32; e += 256) {
        int r = e >> 5, d = e & 31;
        if (r < WIN2) {
            int i = r / WIN, j = r % WIN;
            int m = b * Nn + (wh * WIN + i) * Wd + (ww * WIN + j);
            const float* base = qkv + (size_t)m * 768 + head * HD + d;
            sq[r * QS + d] = base[0];
            sk[r * QS + d] = base[256];
            sv[r * QS + d] = base[512];
        } else {
            sq[r * QS + d] = 0.f;
            sk[r * QS + d] = 0.f;
        }
    }
    __syncthreads();

    for (int t = tid; t < 2 * WIN2; t += 256) {
        float* row = (t < WIN2) ? (sq + t * QS) : (sk + (t - WIN2) * QS);
        float s = 0.f;
        #pragma unroll
        for (int d = 0; d < HD; d += 2) {
            float2 v = *(float2*)(row + d);
            s += v.x * v.x + v.y * v.y;
        }
        float inv = 1.f / fmaxf(sqrtf(s), 1e-12f);
        #pragma unroll
        for (int d = 0; d < HD; d += 2) {
            float2 v = *(float2*)(row + d);
            v.x *= inv; v.y *= inv;
            *(float2*)(row + d) = v;
        }
    }
    __syncthreads();

    const float tscale = 1.f / fmaxf(tau[head], 0.01f);
    const int tx = tid & 15, ty = tid >> 4;

    float acc[4][4];
    #pragma unroll
    for (int u = 0; u < 4; u++)
        #pragma unroll
        for (int v = 0; v < 4; v++) acc[u][v] = 0.f;
    #pragma unroll
    for (int kk = 0; kk < HD; kk += 2) {
        float2 a2[4], b2[4];
        #pragma unroll
        for (int u = 0; u < 4; u++) a2[u] = *(float2*)&sq[(ty + u * 16) * QS + kk];
        #pragma unroll
        for (int v = 0; v < 4; v++) b2[v] = *(float2*)&sk[(tx + v * 16) * QS + kk];
        #pragma unroll
        for (int u = 0; u < 4; u++)
            #pragma unroll
            for (int v = 0; v < 4; v++)
                acc[u][v] += a2[u].x * b2[v].x + a2[u].y * b2[v].y;
    }
    #pragma unroll
    for (int u = 0; u < 4; u++) {
        int i = ty + u * 16;
        if (i >= WIN2) continue;
        #pragma unroll
        for (int v = 0; v < 4; v++) {
            int j = tx + v * 16;
            if (j >= WIN2) continue;
            float val = acc[u][v] * tscale + cpb[head * (WIN2 * WIN2) + i * WIN2 + j];
            if (shifted) {
                if (wh == NWH - 1 && ((i >= 28) != (j >= 28))) val = -1e30f;
                if (ww == NWH - 1 && (((i % WIN) >= 4) != ((j % WIN) >= 4))) val = -1e30f;
            }
            sd[i * DS + j] = val;
        }
    }
    __syncthreads();

    const int lane = tid & 31, wrp = tid >> 5;
    for (int r = wrp; r < WIN2; r += 8) {
        float v0 = sd[r * DS + lane];
        float v1 = (lane + 32 < WIN2) ? sd[r * DS + lane + 32] : -3e38f;
        float mx = fmaxf(v0, v1);
        #pragma unroll
        for (int o = 16; o > 0; o >>= 1) mx = fmaxf(mx, __shfl_xor_sync(~0u, mx, o));
        float e0 = __expf(v0 - mx);
        float e1 = (lane + 32 < WIN2) ? __expf(v1 - mx) : 0.f;
        float s = e0 + e1;
        #pragma unroll
        for (int o = 16; o > 0; o >>= 1) s += __shfl_xor_sync(~0u, s, o);
        float inv = 1.f / s;
        sd[r * DS + lane] = e0 * inv;
        if (lane + 32 < WIN2) sd[r * DS + lane + 32] = e1 * inv;
    }
    __syncthreads();

    float o2[4][2];
    #pragma unroll
    for (int u = 0; u < 4; u++) { o2[u][0] = 0.f; o2[u][1] = 0.f; }
    for (int j = 0; j < 48; j += 2) {
        float2 p2[4];
        #pragma unroll
        for (int u = 0; u < 4; u++) p2[u] = *(float2*)&sd[(ty + u * 16) * DS + j];
        float2 va = *(float2*)&sv[j * QS + tx * 2];
        float2 vb = *(float2*)&sv[(j + 1) * QS + tx * 2];
        #pragma unroll
        for (int u = 0; u < 4; u++) {
            o2[u][0] += p2[u].x * va.x + p2[u].y * vb.x;
            o2[u][1] += p2[u].x * va.y + p2[u].y * vb.y;
        }
    }
    {   // j = 48 remainder
        float2 vc = *(float2*)&sv[48 * QS + tx * 2];
        #pragma unroll
        for (int u = 0; u < 4; u++) {
            float p = sd[(ty + u * 16) * DS + 48];
            o2[u][0] += p * vc.x;
            o2[u][1] += p * vc.y;
        }
    }
    #pragma unroll
    for (int u = 0; u < 4; u++) {
        int i = ty + u * 16;
        if (i < WIN2) {
            int ii = i / WIN, jj = i % WIN;
            int m = b * Nn + (wh * WIN + ii) * Wd + (ww * WIN + jj);
            size_t off = (size_t)m * Dd + head * HD + tx * 2;
            __nv_bfloat16 h0 = __float2bfloat16(o2[u][0]);
            __nv_bfloat16 h1 = __float2bfloat16(o2[u][1]);
            *(uint32_t*)(outh + off) = (uint32_t)__bfloat16_as_ushort(h0) |
                                       ((uint32_t)__bfloat16_as_ushort(h1) << 16);
            *(uint32_t*)(outl + off) = pack_bf2(o2[u][0] - __bfloat162float(h0),
                                                o2[u][1] - __bfloat162float(h1));
        }
    }
}

// ================= final LN =================
__global__ void ln_final_kernel(const float* __restrict__ A, const float* __restrict__ g,
                                const float* __restrict__ be, float* __restrict__ out) {
    int row = blockIdx.x * 8 + (threadIdx.x >> 5);
    int lane = threadIdx.x & 31;
    const float4* a4 = (const float4*)(A + (size_t)row * Dd);
    float4 v0 = a4[lane], v1 = a4[lane + 32];
    float s  = v0.x + v0.y + v0.z + v0.w + v1.x + v1.y + v1.z + v1.w;
    float s2 = v0.x*v0.x + v0.y*v0.y + v0.z*v0.z + v0.w*v0.w
             + v1.x*v1.x + v1.y*v1.y + v1.z*v1.z + v1.w*v1.w;
    #pragma unroll
    for (int o = 16; o > 0; o >>= 1) {
        s  += __shfl_xor_sync(~0u, s, o);
        s2 += __shfl_xor_sync(~0u, s2, o);
    }
    float mean = s * (1.f / Dd);
    float var  = s2 * (1.f / Dd) - mean * mean;
    float inv  = rsqrtf(var + EPSLN);
    float4 g0 = ((const float4*)g)[lane],  g1 = ((const float4*)g)[lane + 32];
    float4 b0 = ((const float4*)be)[lane], b1 = ((const float4*)be)[lane + 32];
    float4 o0, o1;
    o0.x = (v0.x - mean) * inv * g0.x + b0.x;
    o0.y = (v0.y - mean) * inv * g0.y + b0.y;
    o0.z = (v0.z - mean) * inv * g0.z + b0.z;
    o0.w = (v0.w - mean) * inv * g0.w + b0.w;
    o1.x = (v1.x - mean) * inv * g1.x + b1.x;
    o1.y = (v1.y - mean) * inv * g1.y + b1.y;
    o1.z = (v1.z - mean) * inv * g1.z + b1.z;
    o1.w = (v1.w - mean) * inv * g1.w + b1.w;
    float4* out4 = (float4*)(out + (size_t)row * Dd);
    out4[lane] = o0; out4[lane + 32] = o1;
}

// ================= launch =================
extern "C" void kernel_launch(void* const* d_in, const int* in_sizes, int n_in,
                              void* d_out, int out_size) {
    const float* x    = (const float*)d_in[0];
    const float* spe  = (const float*)d_in[1];
    const float* qkvw = (const float*)d_in[2];
    const float* tau  = (const float*)d_in[3];
    const float* cw1  = (const float*)d_in[4];
    const float* cb1  = (const float*)d_in[5];
    const float* cw2  = (const float*)d_in[6];
    const float* cb2  = (const float*)d_in[7];
    const float* ow   = (const float*)d_in[8];
    const float* ob   = (const float*)d_in[9];
    const float* ln1g = (const float*)d_in[10];
    const float* ln1b = (const float*)d_in[11];
    const float* fw1  = (const float*)d_in[12];
    const float* fb1  = (const float*)d_in[13];
    const float* fw2  = (const float*)d_in[14];
    const float* fb2  = (const float*)d_in[15];
    const float* ln2g = (const float*)d_in[16];
    const float* ln2b = (const float*)d_in[17];
    const float* ng   = (const float*)d_in[18];
    const float* nb   = (const float*)d_in[19];
    float* out = (float*)d_out;

    float *xm, *qkv, *cpb;
    __nv_bfloat16 *xmh, *xml, *ath, *atl, *ffh, *ffl, *wth, *wtl;
    cudaGetSymbolAddress((void**)&xm,  g_xm);
    cudaGetSymbolAddress((void**)&qkv, g_qkv);
    cudaGetSymbolAddress((void**)&cpb, g_cpb);
    cudaGetSymbolAddress((void**)&xmh, g_xmh);
    cudaGetSymbolAddress((void**)&xml, g_xml);
    cudaGetSymbolAddress((void**)&ath, g_ath);
    cudaGetSymbolAddress((void**)&atl, g_atl);
    cudaGetSymbolAddress((void**)&ffh, g_ffh);
    cudaGetSymbolAddress((void**)&ffl, g_ffl);
    cudaGetSymbolAddress((void**)&wth, g_wth);
    cudaGetSymbolAddress((void**)&wtl, g_wtl);

    cudaFuncSetAttribute(hgemm_kernel<0, false, 0>, cudaFuncAttributeMaxDynamicSharedMemorySize, GEMM_SMEM);
    cudaFuncSetAttribute(hgemm_kernel<0, true,  0>, cudaFuncAttributeMaxDynamicSharedMemorySize, GEMM_SMEM);
    cudaFuncSetAttribute(hgemm_kernel<1, false, 1>, cudaFuncAttributeMaxDynamicSharedMemorySize, GEMM_SMEM);
    cudaFuncSetAttribute(hgemm_ln_kernel<false>, cudaFuncAttributeMaxDynamicSharedMemorySize, GEMM_SMEM);
    cudaFuncSetAttribute(hgemm_ln_kernel<true>,  cudaFuncAttributeMaxDynamicSharedMemorySize, GEMM_SMEM);

    // weight transpose + bf16 split, both layers batched via z
    wtconv_kernel<<<dim3(24, 8, 2), dim3(32, 8)>>>(qkvw, wth,          wtl,          256, 768,
                                                   (size_t)Dd * 768, WLSTRIDE);
    wtconv_kernel<<<dim3(8,  8, 2), dim3(32, 8)>>>(ow,   wth + 196608, wtl + 196608, 256, 256,
                                                   (size_t)Dd * Dd,  WLSTRIDE);
    wtconv_kernel<<<dim3(32, 8, 2), dim3(32, 8)>>>(fw1,  wth + 262144, wtl + 262144, 256, 1024,
                                                   (size_t)Dd * FF,  WLSTRIDE);
    wtconv_kernel<<<dim3(8, 32, 2), dim3(32, 8)>>>(fw2,  wth + 524288, wtl + 524288, 1024, 256,
                                                   (size_t)FF * Dd,  WLSTRIDE);

    // xm = x + spe (+ bf16 split)
    {
        int n4 = MROWS * Dd / 4;
        add_spe_kernel<<<(n4 + 255) / 256, 256>>>(x, spe, xm, xmh, xml, n4);
    }

    const int MT  = MROWS / 256;   // 196
    const int MT2 = MROWS / 128;   // 392
    for (int layer = 0; layer < 2; layer++) {
        int shifted = (layer == 1);
        size_t wo = (size_t)layer * WLSTRIDE;

        cpb_kernel<<<WIN2 * WIN2, 256>>>(cw1 + layer * 2 * CPBH, cb1 + layer * CPBH,
                                         cw2 + layer * CPBH * HEADS, cb2 + layer * HEADS, cpb);

        // qkv = (rolled) xm @ qkv_w -> fp32
        if (shifted)
            hgemm_kernel<0, true, 0><<<dim3(6, MT), 256, GEMM_SMEM>>>(
                xmh, xml, wth + wo, wtl + wo, nullptr, qkv, nullptr, nullptr, 768, 256);
        else
            hgemm_kernel<0, false, 0><<<dim3(6, MT), 256, GEMM_SMEM>>>(
                xmh, xml, wth + wo, wtl + wo, nullptr, qkv, nullptr, nullptr, 768, 256);

        attn_kernel<<<dim3(NW, HEADS, Bb), 256>>>(qkv, tau + layer * HEADS, cpb, ath, atl, shifted);

        // o-proj + fused LN + residual (scatter-rolled if shifted)
        if (shifted)
            hgemm_ln_kernel<true><<<dim3(1, MT2), 256, GEMM_SMEM>>>(
                ath, atl, wth + wo + 196608, wtl + wo + 196608, ob + layer * Dd,
                ln1g + layer * Dd, ln1b + layer * Dd, xm, xmh, xml, 256);
        else
            hgemm_ln_kernel<false><<<dim3(1, MT2), 256, GEMM_SMEM>>>(
                ath, atl, wth + wo + 196608, wtl + wo + 196608, ob + layer * Dd,
                ln1g + layer * Dd, ln1b + layer * Dd, xm, xmh, xml, 256);

        // ffn1: gelu(xm @ fw1 + fb1) -> bf16 hi/lo
        hgemm_kernel<1, false, 1><<<dim3(8, MT), 256, GEMM_SMEM>>>(
            xmh, xml, wth + wo + 262144, wtl + wo + 262144, fb1 + layer * FF,
            nullptr, ffh, ffl, 1024, 256);

        // ffn2 + fused LN + residual
        hgemm_ln_kernel<false><<<dim3(1, MT2), 256, GEMM_SMEM>>>(
            ffh, ffl, wth + wo + 524288, wtl + wo + 524288, fb2 + layer * Dd,
            ln2g + layer * Dd, ln2b + layer * Dd, xm, xmh, xml, 1024);
    }

    ln_final_kernel<<<MROWS / 8, 256>>>(xm, ng, nb, out);
}

// round 7
// speedup vs baseline: 1.0779x; 1.0779x over previous
#include <cuda_runtime.h>
#include <cuda_bf16.h>
#include <cstdint>
#include <math.h>

#define Bb     16
#define Hh     56
#define Wd     56
#define Nn     3136
#define Dd     256
#define HEADS  8
#define HD     32
#define WIN    7
#define WIN2   49
#define NWH    8
#define NW     64
#define DISP   3
#define FF     1024
#define CPBH   512
#define EPSLN  1e-5f
#define MROWS  50176   // B * N

// ================= PTX helpers (plain compute_103 features only) =================
__device__ __forceinline__ uint32_t smem_to_u32(const void* p) {
    uint32_t a;
    asm("{ .reg .u64 t; cvta.to.shared.u64 t, %1; cvt.u32.u64 %0, t; }" : "=r"(a) : "l"(p));
    return a;
}
#define CP_ASYNC_CG(dst, src) \
    asm volatile("cp.async.cg.shared.global [%0], [%1], 16;" :: "r"(dst), "l"(src))
#define CP_ASYNC_COMMIT() asm volatile("cp.async.commit_group;" ::: "memory")
#define CP_ASYNC_WAIT(n)  asm volatile("cp.async.wait_group %0;" :: "n"(n) : "memory")

__device__ __forceinline__ void ldsm_x4(uint32_t* r, uint32_t addr) {
    asm volatile("ldmatrix.sync.aligned.m8n8.x4.shared.b16 {%0,%1,%2,%3}, [%4];"
        : "=r"(r[0]), "=r"(r[1]), "=r"(r[2]), "=r"(r[3]) : "r"(addr));
}
__device__ __forceinline__ void mma_bf16(float* c, const uint32_t* a, const uint32_t* b) {
    asm volatile("mma.sync.aligned.m16n8k16.row.col.f32.bf16.bf16.f32 "
        "{%0,%1,%2,%3},{%4,%5,%6,%7},{%8,%9},{%0,%1,%2,%3};"
        : "+f"(c[0]), "+f"(c[1]), "+f"(c[2]), "+f"(c[3])
        : "r"(a[0]), "r"(a[1]), "r"(a[2]), "r"(a[3]), "r"(b[0]), "r"(b[1]));
}

// ================= device scratch =================
__device__ float         g_xm  [MROWS * Dd];
__device__ __nv_bfloat16 g_xmh [MROWS * Dd];
__device__ __nv_bfloat16 g_xml [MROWS * Dd];
__device__ float         g_qkv [MROWS * 3 * Dd];
__device__ __nv_bfloat16 g_ath [MROWS * Dd];
__device__ __nv_bfloat16 g_atl [MROWS * Dd];
__device__ __nv_bfloat16 g_ffh [MROWS * FF];
__device__ __nv_bfloat16 g_ffl [MROWS * FF];
__device__ float         g_tmp [MROWS * Dd];
__device__ float         g_cpb [HEADS * WIN2 * WIN2];
// transposed bf16 weights (hi/lo), per layer:
// [0) qkvT 768x256 | 196608) owT 256x256 | 262144) fw1T 1024x256 | 524288) fw2T 256x1024
#define WLSTRIDE 786432
__device__ __nv_bfloat16 g_wth [2 * WLSTRIDE];
__device__ __nv_bfloat16 g_wtl [2 * WLSTRIDE];

// ================= small helpers =================
__device__ __forceinline__ uint32_t pack_bf2(float a, float b) {
    return (uint32_t)__bfloat16_as_ushort(__float2bfloat16(a)) |
           ((uint32_t)__bfloat16_as_ushort(__float2bfloat16(b)) << 16);
}
__device__ __forceinline__ void split_f4(float4 v, uint2& hi, uint2& lo) {
    __nv_bfloat16 hx = __float2bfloat16(v.x), hy = __float2bfloat16(v.y);
    __nv_bfloat16 hz = __float2bfloat16(v.z), hw = __float2bfloat16(v.w);
    hi.x = (uint32_t)__bfloat16_as_ushort(hx) | ((uint32_t)__bfloat16_as_ushort(hy) << 16);
    hi.y = (uint32_t)__bfloat16_as_ushort(hz) | ((uint32_t)__bfloat16_as_ushort(hw) << 16);
    lo.x = pack_bf2(v.x - __bfloat162float(hx), v.y - __bfloat162float(hy));
    lo.y = pack_bf2(v.z - __bfloat162float(hz), v.w - __bfloat162float(hw));
}

// ================= add SPE =================
__global__ void add_spe_kernel(const float* __restrict__ x, const float* __restrict__ spe,
                               float* __restrict__ xm, __nv_bfloat16* __restrict__ xh,
                               __nv_bfloat16* __restrict__ xl, int n4) {
    int i = blockIdx.x * blockDim.x + threadIdx.x;
    if (i < n4) {
        float4 a = ((const float4*)x)[i];
        float4 b = ((const float4*)spe)[i];
        a.x += b.x; a.y += b.y; a.z += b.z; a.w += b.w;
        ((float4*)xm)[i] = a;
        uint2 h, l; split_f4(a, h, l);
        ((uint2*)xh)[i] = h;
        ((uint2*)xl)[i] = l;
    }
}

// ================= weight transpose + bf16 split: W[K,N] -> T[N,K], z = layer =================
__global__ void wtconv_kernel(const float* __restrict__ W, __nv_bfloat16* __restrict__ Th,
                              __nv_bfloat16* __restrict__ Tl, int K, int N,
                              size_t wstride, size_t tstride) {
    W  += (size_t)blockIdx.z * wstride;
    Th += (size_t)blockIdx.z * tstride;
    Tl += (size_t)blockIdx.z * tstride;
    __shared__ float t[32][33];
    int bn = blockIdx.x * 32, bk = blockIdx.y * 32;
    int tx = threadIdx.x, ty = threadIdx.y;
    #pragma unroll
    for (int j = 0; j < 32; j += 8)
        t[ty + j][tx] = W[(size_t)(bk + ty + j) * N + bn + tx];
    __syncthreads();
    #pragma unroll
    for (int j = 0; j < 32; j += 8) {
        float v = t[tx][ty + j];
        __nv_bfloat16 h = __float2bfloat16(v);
        size_t o = (size_t)(bn + ty + j) * K + bk + tx;
        Th[o] = h;
        Tl[o] = __float2bfloat16(v - __bfloat162float(h));
    }
}

// ================= CPB MLP =================
__global__ void cpb_kernel(const float* __restrict__ cw1, const float* __restrict__ cb1,
                           const float* __restrict__ cw2, const float* __restrict__ cb2,
                           float* __restrict__ cpb) {
    int p = blockIdx.x;
    int i = p / WIN2, j = p % WIN2;
    float dy = (float)(j / WIN - i / WIN);
    float dx = (float)(j % WIN - i % WIN);
    float r0 = ((dy > 0.f) - (dy < 0.f)) * log1pf(fabsf(dy));
    float r1 = ((dx > 0.f) - (dx < 0.f)) * log1pf(fabsf(dx));
    int tid = threadIdx.x;
    int c0 = tid, c1 = tid + 256;
    float h0 = fmaxf(r0 * cw1[c0] + r1 * cw1[CPBH + c0] + cb1[c0], 0.f);
    float h1 = fmaxf(r0 * cw1[c1] + r1 * cw1[CPBH + c1] + cb1[c1], 0.f);
    __shared__ float red[256];
    for (int h = 0; h < HEADS; h++) {
        red[tid] = h0 * cw2[c0 * HEADS + h] + h1 * cw2[c1 * HEADS + h];
        __syncthreads();
        for (int s = 128; s > 0; s >>= 1) {
            if (tid < s) red[tid] += red[tid + s];
            __syncthreads();
        }
        if (tid == 0) cpb[h * (WIN2 * WIN2) + p] = red[0] + cb2[h];
        __syncthreads();
    }
}

// ================= HMMA bf16-split GEMM (256x128 tile) =================
#define SAS      40                         // padded row stride (elems), 80B
#define AH_OFF   0
#define AL_OFF   20480                      // 256*80
#define BH_OFF   40960
#define BL_OFF   51200                      // +128*80
#define STAGE_B  61440
#define STAGES   3
#define GEMM_SMEM (STAGES * STAGE_B)        // 184320 B

template<int ACT, bool GATHER, int OUTMODE>
__global__ void __launch_bounds__(256, 1)
hgemm_kernel(const __nv_bfloat16* __restrict__ Ah, const __nv_bfloat16* __restrict__ Al,
             const __nv_bfloat16* __restrict__ Bth, const __nv_bfloat16* __restrict__ Btl,
             const float* __restrict__ bias, float* __restrict__ Cf,
             __nv_bfloat16* __restrict__ Ch, __nv_bfloat16* __restrict__ Cl,
             int Ntot, int K) {
    extern __shared__ char smem_raw[];
    const uint32_t sbase = smem_to_u32(smem_raw);
    const int tid  = threadIdx.x;
    const int lane = tid & 31, wid = tid >> 5;
    const int warpM = wid >> 1, warpN = wid & 1;   // 4x2
    const int bm = blockIdx.y * 256, bn = blockIdx.x * 128;

    const __nv_bfloat16 *pAh[4], *pAl[4], *pBh[2], *pBl[2];
    uint32_t aoff[4], boff[2];
    #pragma unroll
    for (int l = 0; l < 4; l++) {
        int c = tid + l * 256;
        int r = c >> 2, q = c & 3;
        int gm = bm + r;
        if (GATHER) {
            int b = gm / Nn, rem = gm - b * Nn;
            int h = rem / Wd, w = rem - h * Wd;
            h = (h + DISP) % Hh; w = (w + DISP) % Wd;
            gm = b * Nn + h * Wd + w;
        }
        pAh[l] = Ah + (size_t)gm * K + q * 8;
        pAl[l] = Al + (size_t)gm * K + q * 8;
        aoff[l] = (uint32_t)(r * (SAS * 2) + q * 16);
    }
    #pragma unroll
    for (int l = 0; l < 2; l++) {
        int c = tid + l * 256;
        int r = c >> 2, q = c & 3;
        pBh[l] = Bth + (size_t)(bn + r) * K + q * 8;
        pBl[l] = Btl + (size_t)(bn + r) * K + q * 8;
        boff[l] = (uint32_t)(r * (SAS * 2) + q * 16);
    }

    float acc[4][8][4];
    #pragma unroll
    for (int m = 0; m < 4; m++)
        #pragma unroll
        for (int n = 0; n < 8; n++)
            #pragma unroll
            for (int e = 0; e < 4; e++) acc[m][n][e] = 0.f;

    const int nch = K >> 5;

    auto load_stage = [&](int c, int sc) {
        uint32_t stg = sbase + (uint32_t)sc * STAGE_B;
        int kt = c << 5;
        #pragma unroll
        for (int l = 0; l < 4; l++) {
            CP_ASYNC_CG(stg + AH_OFF + aoff[l], pAh[l] + kt);
            CP_ASYNC_CG(stg + AL_OFF + aoff[l], pAl[l] + kt);
        }
        #pragma unroll
        for (int l = 0; l < 2; l++) {
            CP_ASYNC_CG(stg + BH_OFF + boff[l], pBh[l] + kt);
            CP_ASYNC_CG(stg + BL_OFF + boff[l], pBl[l] + kt);
        }
    };

    const int arow  = (lane & 15);
    const int ahalf = (lane >> 4);
    const int bidx  = lane & 7;
    const int bkh   = (lane >> 3) & 1;
    const int bsub  = lane >> 4;

    load_stage(0, 0);
    CP_ASYNC_COMMIT();
    if (nch > 1) load_stage(1, 1);
    CP_ASYNC_COMMIT();

    int sc = 0, scn = 2;
    for (int c = 0; c < nch; c++) {
        CP_ASYNC_WAIT(1);
        __syncthreads();
        if (c + 2 < nch) load_stage(c + 2, scn);
        CP_ASYNC_COMMIT();

        uint32_t stg = sbase + (uint32_t)sc * STAGE_B;
        #pragma unroll
        for (int ks = 0; ks < 2; ks++) {
            uint32_t ah[4][4], al[4][4], bh[8][2], bl[8][2];
            #pragma unroll
            for (int m = 0; m < 4; m++) {
                uint32_t off = (uint32_t)((warpM * 64 + m * 16 + arow) * (SAS * 2)
                                          + (ks * 16 + ahalf * 8) * 2);
                ldsm_x4(ah[m], stg + AH_OFF + off);
                ldsm_x4(al[m], stg + AL_OFF + off);
            }
            #pragma unroll
            for (int pr = 0; pr < 4; pr++) {
                uint32_t off = (uint32_t)((warpN * 64 + pr * 16 + bsub * 8 + bidx) * (SAS * 2)
                                          + (ks * 16 + bkh * 8) * 2);
                uint32_t t[4];
                ldsm_x4(t, stg + BH_OFF + off);
                bh[pr * 2][0] = t[0]; bh[pr * 2][1] = t[1];
                bh[pr * 2 + 1][0] = t[2]; bh[pr * 2 + 1][1] = t[3];
                ldsm_x4(t, stg + BL_OFF + off);
                bl[pr * 2][0] = t[0]; bl[pr * 2][1] = t[1];
                bl[pr * 2 + 1][0] = t[2]; bl[pr * 2 + 1][1] = t[3];
            }
            #pragma unroll
            for (int m = 0; m < 4; m++)
                #pragma unroll
                for (int n = 0; n < 8; n++) mma_bf16(acc[m][n], ah[m], bh[n]);
            #pragma unroll
            for (int m = 0; m < 4; m++)
                #pragma unroll
                for (int n = 0; n < 8; n++) mma_bf16(acc[m][n], ah[m], bl[n]);
            #pragma unroll
            for (int m = 0; m < 4; m++)
                #pragma unroll
                for (int n = 0; n < 8; n++) mma_bf16(acc[m][n], al[m], bh[n]);
        }
        sc = (sc == 2) ? 0 : sc + 1;
        scn = (scn == 2) ? 0 : scn + 1;
    }

    const int g = lane >> 2, q = lane & 3;
    #pragma unroll
    for (int m = 0; m < 4; m++) {
        #pragma unroll
        for (int n = 0; n < 8; n++) {
            int col = bn + warpN * 64 + n * 8 + 2 * q;
            float b0 = bias ? bias[col] : 0.f;
            float b1 = bias ? bias[col + 1] : 0.f;
            #pragma unroll
            for (int hrow = 0; hrow < 2; hrow++) {
                int row = bm + warpM * 64 + m * 16 + g + hrow * 8;
                float v0 = acc[m][n][hrow * 2 + 0] + b0;
                float v1 = acc[m][n][hrow * 2 + 1] + b1;
                if (ACT == 1) {
                    v0 = v0 * 0.5f * (1.f + erff(v0 * 0.7071067811865476f));
                    v1 = v1 * 0.5f * (1.f + erff(v1 * 0.7071067811865476f));
                }
                if (OUTMODE == 0) {
                    *(float2*)(Cf + (size_t)row * Ntot + col) = make_float2(v0, v1);
                } else {
                    __nv_bfloat16 h0 = __float2bfloat16(v0);
                    __nv_bfloat16 h1 = __float2bfloat16(v1);
                    *(uint32_t*)(Ch + (size_t)row * Ntot + col) =
                        (uint32_t)__bfloat16_as_ushort(h0) |
                        ((uint32_t)__bfloat16_as_ushort(h1) << 16);
                    *(uint32_t*)(Cl + (size_t)row * Ntot + col) =
                        pack_bf2(v0 - __bfloat162float(h0), v1 - __bfloat162float(h1));
                }
            }
        }
    }
}

// ================= window attention (float2-vectorized, emits bf16 hi/lo) =================
#define QS 34
#define DS 52
__global__ void __launch_bounds__(256)
attn_kernel(const float* __restrict__ qkv, const float* __restrict__ tau,
            const float* __restrict__ cpb, __nv_bfloat16* __restrict__ outh,
            __nv_bfloat16* __restrict__ outl, int shifted) {
    __shared__ float sq[64 * QS];
    __shared__ float sk[64 * QS];
    __shared__ float sv[49 * QS];
    __shared__ float sd[64 * DS];

    const int wi   = blockIdx.x;
    const int head = blockIdx.y;
    const int b    = blockIdx.z;
    const int wh = wi >> 3, ww = wi & 7;
    const int tid = threadIdx.x;

    for (int e = tid; e < 64 * 32; e += 256) {
        int r = e >> 5, d = e & 31;
        if (r < WIN2) {
            int i = r / WIN, j = r % WIN;
            int m = b * Nn + (wh * WIN + i) * Wd + (ww * WIN + j);
            const float* base = qkv + (size_t)m * 768 + head * HD + d;
            sq[r * QS + d] = base[0];
            sk[r * QS + d] = base[256];
            sv[r * QS + d] = base[512];
        } else {
            sq[r * QS + d] = 0.f;
            sk[r * QS + d] = 0.f;
        }
    }
    __syncthreads();

    for (int t = tid; t < 2 * WIN2; t += 256) {
        float* row = (t < WIN2) ? (sq + t * QS) : (sk + (t - WIN2) * QS);
        float s = 0.f;
        #pragma unroll
        for (int d = 0; d < HD; d += 2) {
            float2 v = *(float2*)(row + d);
            s += v.x * v.x + v.y * v.y;
        }
        float inv = 1.f / fmaxf(sqrtf(s), 1e-12f);
        #pragma unroll
        for (int d = 0; d < HD; d += 2) {
            float2 v = *(float2*)(row + d);
            v.x *= inv; v.y *= inv;
            *(float2*)(row + d) = v;
        }
    }
    __syncthreads();

    const float tscale = 1.f / fmaxf(tau[head], 0.01f);
    const int tx = tid & 15, ty = tid >> 4;

    float acc[4][4];
    #pragma unroll
    for (int u = 0; u < 4; u++)
        #pragma unroll
        for (int v = 0; v < 4; v++) acc[u][v] = 0.f;
    #pragma unroll
    for (int kk = 0; kk < HD; kk += 2) {
        float2 a2[4], b2[4];
        #pragma unroll
        for (int u = 0; u < 4; u++) a2[u] = *(float2*)&sq[(ty + u * 16) * QS + kk];
        #pragma unroll
        for (int v = 0; v < 4; v++) b2[v] = *(float2*)&sk[(tx + v * 16) * QS + kk];
        #pragma unroll
        for (int u = 0; u < 4; u++)
            #pragma unroll
            for (int v = 0; v < 4; v++)
                acc[u][v] += a2[u].x * b2[v].x + a2[u].y * b2[v].y;
    }
    #pragma unroll
    for (int u = 0; u < 4; u++) {
        int i = ty + u * 16;
        if (i >= WIN2) continue;
        #pragma unroll
        for (int v = 0; v < 4; v++) {
            int j = tx + v * 16;
            if (j >= WIN2) continue;
            float val = acc[u][v] * tscale + cpb[head * (WIN2 * WIN2) + i * WIN2 + j];
            if (shifted) {
                if (wh == NWH - 1 && ((i >= 28) != (j >= 28))) val = -1e30f;
                if (ww == NWH - 1 && (((i % WIN) >= 4) != ((j % WIN) >= 4))) val = -1e30f;
            }
            sd[i * DS + j] = val;
        }
    }
    __syncthreads();

    const int lane = tid & 31, wrp = tid >> 5;
    for (int r = wrp; r < WIN2; r += 8) {
        float v0 = sd[r * DS + lane];
        float v1 = (lane + 32 < WIN2) ? sd[r * DS + lane + 32] : -3e38f;
        float mx = fmaxf(v0, v1);
        #pragma unroll
        for (int o = 16; o > 0; o >>= 1) mx = fmaxf(mx, __shfl_xor_sync(~0u, mx, o));
        float e0 = __expf(v0 - mx);
        float e1 = (lane + 32 < WIN2) ? __expf(v1 - mx) : 0.f;
        float s = e0 + e1;
        #pragma unroll
        for (int o = 16; o > 0; o >>= 1) s += __shfl_xor_sync(~0u, s, o);
        float inv = 1.f / s;
        sd[r * DS + lane] = e0 * inv;
        if (lane + 32 < WIN2) sd[r * DS + lane + 32] = e1 * inv;
    }
    __syncthreads();

    float o2[4][2];
    #pragma unroll
    for (int u = 0; u < 4; u++) { o2[u][0] = 0.f; o2[u][1] = 0.f; }
    for (int j = 0; j < 48; j += 2) {
        float2 p2[4];
        #pragma unroll
        for (int u = 0; u < 4; u++) p2[u] = *(float2*)&sd[(ty + u * 16) * DS + j];
        float2 va = *(float2*)&sv[j * QS + tx * 2];
        float2 vb = *(float2*)&sv[(j + 1) * QS + tx * 2];
        #pragma unroll
        for (int u = 0; u < 4; u++) {
            o2[u][0] += p2[u].x * va.x + p2[u].y * vb.x;
            o2[u][1] += p2[u].x * va.y + p2[u].y * vb.y;
        }
    }
    {   // j = 48 remainder
        float2 vc = *(float2*)&sv[48 * QS + tx * 2];
        #pragma unroll
        for (int u = 0; u < 4; u++) {
            float p = sd[(ty + u * 16) * DS + 48];
            o2[u][0] += p * vc.x;
            o2[u][1] += p * vc.y;
        }
    }
    #pragma unroll
    for (int u = 0; u < 4; u++) {
        int i = ty + u * 16;
        if (i < WIN2) {
            int ii = i / WIN, jj = i % WIN;
            int m = b * Nn + (wh * WIN + ii) * Wd + (ww * WIN + jj);
            size_t off = (size_t)m * Dd + head * HD + tx * 2;
            __nv_bfloat16 h0 = __float2bfloat16(o2[u][0]);
            __nv_bfloat16 h1 = __float2bfloat16(o2[u][1]);
            *(uint32_t*)(outh + off) = (uint32_t)__bfloat16_as_ushort(h0) |
                                       ((uint32_t)__bfloat16_as_ushort(h1) << 16);
            *(uint32_t*)(outl + off) = pack_bf2(o2[u][0] - __bfloat162float(h0),
                                                o2[u][1] - __bfloat162float(h1));
        }
    }
}

// ================= LN + residual =================
__global__ void ln_residual_kernel(const float* __restrict__ A, const float* __restrict__ g,
                                   const float* __restrict__ be, float* __restrict__ xm,
                                   __nv_bfloat16* __restrict__ xh, __nv_bfloat16* __restrict__ xl,
                                   int gather) {
    int row = blockIdx.x * 8 + (threadIdx.x >> 5);
    int lane = threadIdx.x & 31;
    int src = row;
    if (gather) {
        int b = row / Nn, rem = row % Nn;
        int h = rem / Wd, w = rem % Wd;
        src = b * Nn + ((h + Hh - DISP) % Hh) * Wd + ((w + Wd - DISP) % Wd);
    }
    const float4* a4 = (const float4*)(A + (size_t)src * Dd);
    float4 v0 = a4[lane], v1 = a4[lane + 32];
    float s  = v0.x + v0.y + v0.z + v0.w + v1.x + v1.y + v1.z + v1.w;
    float s2 = v0.x*v0.x + v0.y*v0.y + v0.z*v0.z + v0.w*v0.w
             + v1.x*v1.x + v1.y*v1.y + v1.z*v1.z + v1.w*v1.w;
    #pragma unroll
    for (int o = 16; o > 0; o >>= 1) {
        s  += __shfl_xor_sync(~0u, s, o);
        s2 += __shfl_xor_sync(~0u, s2, o);
    }
    float mean = s * (1.f / Dd);
    float var  = s2 * (1.f / Dd) - mean * mean;
    float inv  = rsqrtf(var + EPSLN);

    float4 g0 = ((const float4*)g)[lane],  g1 = ((const float4*)g)[lane + 32];
    float4 b0 = ((const float4*)be)[lane], b1 = ((const float4*)be)[lane + 32];
    float4* x4 = (float4*)(xm + (size_t)row * Dd);
    float4 r0 = x4[lane], r1 = x4[lane + 32];
    r0.x += (v0.x - mean) * inv * g0.x + b0.x;
    r0.y += (v0.y - mean) * inv * g0.y + b0.y;
    r0.z += (v0.z - mean) * inv * g0.z + b0.z;
    r0.w += (v0.w - mean) * inv * g0.w + b0.w;
    r1.x += (v1.x - mean) * inv * g1.x + b1.x;
    r1.y += (v1.y - mean) * inv * g1.y + b1.y;
    r1.z += (v1.z - mean) * inv * g1.z + b1.z;
    r1.w += (v1.w - mean) * inv * g1.w + b1.w;
    x4[lane] = r0; x4[lane + 32] = r1;

    uint2 h, l;
    size_t e0 = (size_t)row * Dd + lane * 4;
    size_t e1 = e0 + 128;
    split_f4(r0, h, l);
    *(uint2*)(xh + e0) = h; *(uint2*)(xl + e0) = l;
    split_f4(r1, h, l);
    *(uint2*)(xh + e1) = h; *(uint2*)(xl + e1) = l;
}

// ================= final LN =================
__global__ void ln_final_kernel(const float* __restrict__ A, const float* __restrict__ g,
                                const float* __restrict__ be, float* __restrict__ out) {
    int row = blockIdx.x * 8 + (threadIdx.x >> 5);
    int lane = threadIdx.x & 31;
    const float4* a4 = (const float4*)(A + (size_t)row * Dd);
    float4 v0 = a4[lane], v1 = a4[lane + 32];
    float s  = v0.x + v0.y + v0.z + v0.w + v1.x + v1.y + v1.z + v1.w;
    float s2 = v0.x*v0.x + v0.y*v0.y + v0.z*v0.z + v0.w*v0.w
             + v1.x*v1.x + v1.y*v1.y + v1.z*v1.z + v1.w*v1.w;
    #pragma unroll
    for (int o = 16; o > 0; o >>= 1) {
        s  += __shfl_xor_sync(~0u, s, o);
        s2 += __shfl_xor_sync(~0u, s2, o);
    }
    float mean = s * (1.f / Dd);
    float var  = s2 * (1.f / Dd) - mean * mean;
    float inv  = rsqrtf(var + EPSLN);
    float4 g0 = ((const float4*)g)[lane],  g1 = ((const float4*)g)[lane + 32];
    float4 b0 = ((const float4*)be)[lane], b1 = ((const float4*)be)[lane + 32];
    float4 o0, o1;
    o0.x = (v0.x - mean) * inv * g0.x + b0.x;
    o0.y = (v0.y - mean) * inv * g0.y + b0.y;
    o0.z = (v0.z - mean) * inv * g0.z + b0.z;
    o0.w = (v0.w - mean) * inv * g0.w + b0.w;
    o1.x = (v1.x - mean) * inv * g1.x + b1.x;
    o1.y = (v1.y - mean) * inv * g1.y + b1.y;
    o1.z = (v1.z - mean) * inv * g1.z + b1.z;
    o1.w = (v1.w - mean) * inv * g1.w + b1.w;
    float4* out4 = (float4*)(out + (size_t)row * Dd);
    out4[lane] = o0; out4[lane + 32] = o1;
}

// ================= launch =================
extern "C" void kernel_launch(void* const* d_in, const int* in_sizes, int n_in,
                              void* d_out, int out_size) {
    const float* x    = (const float*)d_in[0];
    const float* spe  = (const float*)d_in[1];
    const float* qkvw = (const float*)d_in[2];
    const float* tau  = (const float*)d_in[3];
    const float* cw1  = (const float*)d_in[4];
    const float* cb1  = (const float*)d_in[5];
    const float* cw2  = (const float*)d_in[6];
    const float* cb2  = (const float*)d_in[7];
    const float* ow   = (const float*)d_in[8];
    const float* ob   = (const float*)d_in[9];
    const float* ln1g = (const float*)d_in[10];
    const float* ln1b = (const float*)d_in[11];
    const float* fw1  = (const float*)d_in[12];
    const float* fb1  = (const float*)d_in[13];
    const float* fw2  = (const float*)d_in[14];
    const float* fb2  = (const float*)d_in[15];
    const float* ln2g = (const float*)d_in[16];
    const float* ln2b = (const float*)d_in[17];
    const float* ng   = (const float*)d_in[18];
    const float* nb   = (const float*)d_in[19];
    float* out = (float*)d_out;

    float *xm, *qkv, *tmp, *cpb;
    __nv_bfloat16 *xmh, *xml, *ath, *atl, *ffh, *ffl, *wth, *wtl;
    cudaGetSymbolAddress((void**)&xm,  g_xm);
    cudaGetSymbolAddress((void**)&qkv, g_qkv);
    cudaGetSymbolAddress((void**)&tmp, g_tmp);
    cudaGetSymbolAddress((void**)&cpb, g_cpb);
    cudaGetSymbolAddress((void**)&xmh, g_xmh);
    cudaGetSymbolAddress((void**)&xml, g_xml);
    cudaGetSymbolAddress((void**)&ath, g_ath);
    cudaGetSymbolAddress((void**)&atl, g_atl);
    cudaGetSymbolAddress((void**)&ffh, g_ffh);
    cudaGetSymbolAddress((void**)&ffl, g_ffl);
    cudaGetSymbolAddress((void**)&wth, g_wth);
    cudaGetSymbolAddress((void**)&wtl, g_wtl);

    cudaFuncSetAttribute(hgemm_kernel<0, false, 0>, cudaFuncAttributeMaxDynamicSharedMemorySize, GEMM_SMEM);
    cudaFuncSetAttribute(hgemm_kernel<0, true,  0>, cudaFuncAttributeMaxDynamicSharedMemorySize, GEMM_SMEM);
    cudaFuncSetAttribute(hgemm_kernel<1, false, 1>, cudaFuncAttributeMaxDynamicSharedMemorySize, GEMM_SMEM);

    // weight transpose + bf16 split, both layers batched via z
    wtconv_kernel<<<dim3(24, 8, 2), dim3(32, 8)>>>(qkvw, wth,          wtl,          256, 768,
                                                   (size_t)Dd * 768, WLSTRIDE);
    wtconv_kernel<<<dim3(8,  8, 2), dim3(32, 8)>>>(ow,   wth + 196608, wtl + 196608, 256, 256,
                                                   (size_t)Dd * Dd,  WLSTRIDE);
    wtconv_kernel<<<dim3(32, 8, 2), dim3(32, 8)>>>(fw1,  wth + 262144, wtl + 262144, 256, 1024,
                                                   (size_t)Dd * FF,  WLSTRIDE);
    wtconv_kernel<<<dim3(8, 32, 2), dim3(32, 8)>>>(fw2,  wth + 524288, wtl + 524288, 1024, 256,
                                                   (size_t)FF * Dd,  WLSTRIDE);

    // xm = x + spe (+ bf16 split)
    {
        int n4 = MROWS * Dd / 4;
        add_spe_kernel<<<(n4 + 255) / 256, 256>>>(x, spe, xm, xmh, xml, n4);
    }

    const int lnBlocks = MROWS / 8;
    const int MT = MROWS / 256;   // 196
    for (int layer = 0; layer < 2; layer++) {
        int shifted = (layer == 1);
        size_t wo = (size_t)layer * WLSTRIDE;

        cpb_kernel<<<WIN2 * WIN2, 256>>>(cw1 + layer * 2 * CPBH, cb1 + layer * CPBH,
                                         cw2 + layer * CPBH * HEADS, cb2 + layer * HEADS, cpb);

        // qkv = (rolled) xm @ qkv_w -> fp32
        if (shifted)
            hgemm_kernel<0, true, 0><<<dim3(6, MT), 256, GEMM_SMEM>>>(
                xmh, xml, wth + wo, wtl + wo, nullptr, qkv, nullptr, nullptr, 768, 256);
        else
            hgemm_kernel<0, false, 0><<<dim3(6, MT), 256, GEMM_SMEM>>>(
                xmh, xml, wth + wo, wtl + wo, nullptr, qkv, nullptr, nullptr, 768, 256);

        attn_kernel<<<dim3(NW, HEADS, Bb), 256>>>(qkv, tau + layer * HEADS, cpb, ath, atl, shifted);

        // o-proj -> tmp (fp32)
        hgemm_kernel<0, false, 0><<<dim3(2, MT), 256, GEMM_SMEM>>>(
            ath, atl, wth + wo + 196608, wtl + wo + 196608, ob + layer * Dd,
            tmp, nullptr, nullptr, 256, 256);

        // xm += LN(oproj) (rolled back if shifted)
        ln_residual_kernel<<<lnBlocks, 256>>>(tmp, ln1g + layer * Dd, ln1b + layer * Dd,
                                              xm, xmh, xml, shifted);

        // ffn1: gelu(xm @ fw1 + fb1) -> bf16 hi/lo
        hgemm_kernel<1, false, 1><<<dim3(8, MT), 256, GEMM_SMEM>>>(
            xmh, xml, wth + wo + 262144, wtl + wo + 262144, fb1 + layer * FF,
            nullptr, ffh, ffl, 1024, 256);

        // ffn2 -> tmp (fp32)
        hgemm_kernel<0, false, 0><<<dim3(2, MT), 256, GEMM_SMEM>>>(
            ffh, ffl, wth + wo + 524288, wtl + wo + 524288, fb2 + layer * Dd,
            tmp, nullptr, nullptr, 256, 1024);

        // xm += LN(ffn2)
        ln_residual_kernel<<<lnBlocks, 256>>>(tmp, ln2g + layer * Dd, ln2b + layer * Dd,
                                              xm, xmh, xml, 0);
    }

    ln_final_kernel<<<MROWS / 8, 256>>>(xm, ng, nb, out);
}

// round 8
// speedup vs baseline: 1.2788x; 1.1864x over previous
#include <cuda_runtime.h>
#include <cuda_fp16.h>
#include <cstdint>
#include <math.h>

#define Bb     16
#define Hh     56
#define Wd     56
#define Nn     3136
#define Dd     256
#define HEADS  8
#define HD     32
#define WIN    7
#define WIN2   49
#define NWH    8
#define NW     64
#define DISP   3
#define FF     1024
#define CPBH   512
#define EPSLN  1e-5f
#define MROWS  50176   // B * N

// ================= PTX helpers (plain compute_103 features only) =================
__device__ __forceinline__ uint32_t smem_to_u32(const void* p) {
    uint32_t a;
    asm("{ .reg .u64 t; cvta.to.shared.u64 t, %1; cvt.u32.u64 %0, t; }" : "=r"(a) : "l"(p));
    return a;
}
#define CP_ASYNC_CG(dst, src) \
    asm volatile("cp.async.cg.shared.global [%0], [%1], 16;" :: "r"(dst), "l"(src))
#define CP_ASYNC_COMMIT() asm volatile("cp.async.commit_group;" ::: "memory")
#define CP_ASYNC_WAIT(n)  asm volatile("cp.async.wait_group %0;" :: "n"(n) : "memory")

__device__ __forceinline__ void ldsm_x4(uint32_t* r, uint32_t addr) {
    asm volatile("ldmatrix.sync.aligned.m8n8.x4.shared.b16 {%0,%1,%2,%3}, [%4];"
        : "=r"(r[0]), "=r"(r[1]), "=r"(r[2]), "=r"(r[3]) : "r"(addr));
}
__device__ __forceinline__ void mma_f16(float* c, const uint32_t* a, const uint32_t* b) {
    asm volatile("mma.sync.aligned.m16n8k16.row.col.f32.f16.f16.f32 "
        "{%0,%1,%2,%3},{%4,%5,%6,%7},{%8,%9},{%0,%1,%2,%3};"
        : "+f"(c[0]), "+f"(c[1]), "+f"(c[2]), "+f"(c[3])
        : "r"(a[0]), "r"(a[1]), "r"(a[2]), "r"(a[3]), "r"(b[0]), "r"(b[1]));
}

// ================= device scratch =================
__device__ float  g_xm  [MROWS * Dd];
__device__ __half g_xmh [MROWS * Dd];
__device__ __half g_xml [MROWS * Dd];
__device__ float  g_qkv [MROWS * 3 * Dd];
__device__ __half g_ath [MROWS * Dd];
__device__ __half g_atl [MROWS * Dd];
__device__ __half g_ffh [MROWS * FF];
__device__ __half g_ffl [MROWS * FF];
__device__ float  g_tmp [MROWS * Dd];
__device__ float  g_cpb [HEADS * WIN2 * WIN2];
// transposed fp16 weights (hi only), per layer:
// [0) qkvT 768x256 | 196608) owT 256x256 | 262144) fw1T 1024x256 | 524288) fw2T 256x1024
#define WLSTRIDE 786432
__device__ __half g_wth [2 * WLSTRIDE];

// ================= small helpers =================
__device__ __forceinline__ uint32_t pack_h2(float a, float b) {
    __half2 h = __floats2half2_rn(a, b);
    return *(uint32_t*)&h;
}
__device__ __forceinline__ void split_f4h(float4 v, uint2& hi, uint2& lo) {
    __half hx = __float2half_rn(v.x), hy = __float2half_rn(v.y);
    __half hz = __float2half_rn(v.z), hw = __float2half_rn(v.w);
    __half2 p01; p01.x = hx; p01.y = hy;
    __half2 p23; p23.x = hz; p23.y = hw;
    hi.x = *(uint32_t*)&p01;
    hi.y = *(uint32_t*)&p23;
    lo.x = pack_h2(v.x - __half2float(hx), v.y - __half2float(hy));
    lo.y = pack_h2(v.z - __half2float(hz), v.w - __half2float(hw));
}

// ================= add SPE =================
__global__ void add_spe_kernel(const float* __restrict__ x, const float* __restrict__ spe,
                               float* __restrict__ xm, __half* __restrict__ xh,
                               __half* __restrict__ xl, int n4) {
    int i = blockIdx.x * blockDim.x + threadIdx.x;
    if (i < n4) {
        float4 a = ((const float4*)x)[i];
        float4 b = ((const float4*)spe)[i];
        a.x += b.x; a.y += b.y; a.z += b.z; a.w += b.w;
        ((float4*)xm)[i] = a;
        uint2 h, l; split_f4h(a, h, l);
        ((uint2*)xh)[i] = h;
        ((uint2*)xl)[i] = l;
    }
}

// ================= weight transpose + fp16 round: W[K,N] -> T[N,K], z = layer =================
__global__ void wtconv_kernel(const float* __restrict__ W, __half* __restrict__ Th,
                              int K, int N, size_t wstride, size_t tstride) {
    W  += (size_t)blockIdx.z * wstride;
    Th += (size_t)blockIdx.z * tstride;
    __shared__ float t[32][33];
    int bn = blockIdx.x * 32, bk = blockIdx.y * 32;
    int tx = threadIdx.x, ty = threadIdx.y;
    #pragma unroll
    for (int j = 0; j < 32; j += 8)
        t[ty + j][tx] = W[(size_t)(bk + ty + j) * N + bn + tx];
    __syncthreads();
    #pragma unroll
    for (int j = 0; j < 32; j += 8) {
        Th[(size_t)(bn + ty + j) * K + bk + tx] = __float2half_rn(t[tx][ty + j]);
    }
}

// ================= CPB MLP =================
__global__ void cpb_kernel(const float* __restrict__ cw1, const float* __restrict__ cb1,
                           const float* __restrict__ cw2, const float* __restrict__ cb2,
                           float* __restrict__ cpb) {
    int p = blockIdx.x;
    int i = p / WIN2, j = p % WIN2;
    float dy = (float)(j / WIN - i / WIN);
    float dx = (float)(j % WIN - i % WIN);
    float r0 = ((dy > 0.f) - (dy < 0.f)) * log1pf(fabsf(dy));
    float r1 = ((dx > 0.f) - (dx < 0.f)) * log1pf(fabsf(dx));
    int tid = threadIdx.x;
    int c0 = tid, c1 = tid + 256;
    float h0 = fmaxf(r0 * cw1[c0] + r1 * cw1[CPBH + c0] + cb1[c0], 0.f);
    float h1 = fmaxf(r0 * cw1[c1] + r1 * cw1[CPBH + c1] + cb1[c1], 0.f);
    __shared__ float red[256];
    for (int h = 0; h < HEADS; h++) {
        red[tid] = h0 * cw2[c0 * HEADS + h] + h1 * cw2[c1 * HEADS + h];
        __syncthreads();
        for (int s = 128; s > 0; s >>= 1) {
            if (tid < s) red[tid] += red[tid + s];
            __syncthreads();
        }
        if (tid == 0) cpb[h * (WIN2 * WIN2) + p] = red[0] + cb2[h];
        __syncthreads();
    }
}

// ================= HMMA fp16 2-term GEMM (256x128 tile) =================
// C[M,Ntot] = (Ah+Al) @ Bh^T, B stored transposed [Ntot,K], fp16 weights.
#define SAS      40                         // padded row stride (elems), 80B
#define AH_OFF   0
#define AL_OFF   20480                      // 256*80
#define BH_OFF   40960                      // +256*80
#define STAGE_B  51200                      // 40960 + 128*80
#define STAGES   3
#define GEMM_SMEM (STAGES * STAGE_B)        // 153600 B

template<int ACT, bool GATHER, int OUTMODE>
__global__ void __launch_bounds__(256, 1)
hgemm_kernel(const __half* __restrict__ Ah, const __half* __restrict__ Al,
             const __half* __restrict__ Bth,
             const float* __restrict__ bias, float* __restrict__ Cf,
             __half* __restrict__ Ch, __half* __restrict__ Cl,
             int Ntot, int K) {
    extern __shared__ char smem_raw[];
    const uint32_t sbase = smem_to_u32(smem_raw);
    const int tid  = threadIdx.x;
    const int lane = tid & 31, wid = tid >> 5;
    const int warpM = wid >> 1, warpN = wid & 1;   // 4x2
    const int bm = blockIdx.y * 256, bn = blockIdx.x * 128;

    const __half *pAh[4], *pAl[4], *pBh[2];
    uint32_t aoff[4], boff[2];
    #pragma unroll
    for (int l = 0; l < 4; l++) {
        int c = tid + l * 256;
        int r = c >> 2, q = c & 3;
        int gm = bm + r;
        if (GATHER) {
            int b = gm / Nn, rem = gm - b * Nn;
            int h = rem / Wd, w = rem - h * Wd;
            h = (h + DISP) % Hh; w = (w + DISP) % Wd;
            gm = b * Nn + h * Wd + w;
        }
        pAh[l] = Ah + (size_t)gm * K + q * 8;
        pAl[l] = Al + (size_t)gm * K + q * 8;
        aoff[l] = (uint32_t)(r * (SAS * 2) + q * 16);
    }
    #pragma unroll
    for (int l = 0; l < 2; l++) {
        int c = tid + l * 256;
        int r = c >> 2, q = c & 3;
        pBh[l] = Bth + (size_t)(bn + r) * K + q * 8;
        boff[l] = (uint32_t)(r * (SAS * 2) + q * 16);
    }

    float acc[4][8][4];
    #pragma unroll
    for (int m = 0; m < 4; m++)
        #pragma unroll
        for (int n = 0; n < 8; n++)
            #pragma unroll
            for (int e = 0; e < 4; e++) acc[m][n][e] = 0.f;

    const int nch = K >> 5;

    auto load_stage = [&](int c, int sc) {
        uint32_t stg = sbase + (uint32_t)sc * STAGE_B;
        int kt = c << 5;
        #pragma unroll
        for (int l = 0; l < 4; l++) {
            CP_ASYNC_CG(stg + AH_OFF + aoff[l], pAh[l] + kt);
            CP_ASYNC_CG(stg + AL_OFF + aoff[l], pAl[l] + kt);
        }
        #pragma unroll
        for (int l = 0; l < 2; l++) {
            CP_ASYNC_CG(stg + BH_OFF + boff[l], pBh[l] + kt);
        }
    };

    const int arow  = (lane & 15);
    const int ahalf = (lane >> 4);
    const int bidx  = lane & 7;
    const int bkh   = (lane >> 3) & 1;
    const int bsub  = lane >> 4;

    load_stage(0, 0);
    CP_ASYNC_COMMIT();
    if (nch > 1) load_stage(1, 1);
    CP_ASYNC_COMMIT();

    int sc = 0, scn = 2;
    for (int c = 0; c < nch; c++) {
        CP_ASYNC_WAIT(1);
        __syncthreads();
        if (c + 2 < nch) load_stage(c + 2, scn);
        CP_ASYNC_COMMIT();

        uint32_t stg = sbase + (uint32_t)sc * STAGE_B;
        #pragma unroll
        for (int ks = 0; ks < 2; ks++) {
            uint32_t ah[4][4], al[4][4], bh[8][2];
            #pragma unroll
            for (int m = 0; m < 4; m++) {
                uint32_t off = (uint32_t)((warpM * 64 + m * 16 + arow) * (SAS * 2)
                                          + (ks * 16 + ahalf * 8) * 2);
                ldsm_x4(ah[m], stg + AH_OFF + off);
                ldsm_x4(al[m], stg + AL_OFF + off);
            }
            #pragma unroll
            for (int pr = 0; pr < 4; pr++) {
                uint32_t off = (uint32_t)((warpN * 64 + pr * 16 + bsub * 8 + bidx) * (SAS * 2)
                                          + (ks * 16 + bkh * 8) * 2);
                uint32_t t[4];
                ldsm_x4(t, stg + BH_OFF + off);
                bh[pr * 2][0] = t[0]; bh[pr * 2][1] = t[1];
                bh[pr * 2 + 1][0] = t[2]; bh[pr * 2 + 1][1] = t[3];
            }
            #pragma unroll
            for (int m = 0; m < 4; m++)
                #pragma unroll
                for (int n = 0; n < 8; n++) mma_f16(acc[m][n], ah[m], bh[n]);
            #pragma unroll
            for (int m = 0; m < 4; m++)
                #pragma unroll
                for (int n = 0; n < 8; n++) mma_f16(acc[m][n], al[m], bh[n]);
        }
        sc = (sc == 2) ? 0 : sc + 1;
        scn = (scn == 2) ? 0 : scn + 1;
    }

    const int g = lane >> 2, q = lane & 3;
    #pragma unroll
    for (int m = 0; m < 4; m++) {
        #pragma unroll
        for (int n = 0; n < 8; n++) {
            int col = bn + warpN * 64 + n * 8 + 2 * q;
            float b0 = bias ? bias[col] : 0.f;
            float b1 = bias ? bias[col + 1] : 0.f;
            #pragma unroll
            for (int hrow = 0; hrow < 2; hrow++) {
                int row = bm + warpM * 64 + m * 16 + g + hrow * 8;
                float v0 = acc[m][n][hrow * 2 + 0] + b0;
                float v1 = acc[m][n][hrow * 2 + 1] + b1;
                if (ACT == 1) {
                    v0 = v0 * 0.5f * (1.f + erff(v0 * 0.7071067811865476f));
                    v1 = v1 * 0.5f * (1.f + erff(v1 * 0.7071067811865476f));
                }
                if (OUTMODE == 0) {
                    *(float2*)(Cf + (size_t)row * Ntot + col) = make_float2(v0, v1);
                } else {
                    __half h0 = __float2half_rn(v0);
                    __half h1 = __float2half_rn(v1);
                    __half2 hp; hp.x = h0; hp.y = h1;
                    *(uint32_t*)(Ch + (size_t)row * Ntot + col) = *(uint32_t*)&hp;
                    *(uint32_t*)(Cl + (size_t)row * Ntot + col) =
                        pack_h2(v0 - __half2float(h0), v1 - __half2float(h1));
                }
            }
        }
    }
}

// ================= window attention (float2-vectorized, emits fp16 hi/lo) =================
#define QS 34
#define DS 52
__global__ void __launch_bounds__(256)
attn_kernel(const float* __restrict__ qkv, const float* __restrict__ tau,
            const float* __restrict__ cpb, __half* __restrict__ outh,
            __half* __restrict__ outl, int shifted) {
    __shared__ float sq[64 * QS];
    __shared__ float sk[64 * QS];
    __shared__ float sv[49 * QS];
    __shared__ float sd[64 * DS];

    const int wi   = blockIdx.x;
    const int head = blockIdx.y;
    const int b    = blockIdx.z;
    const int wh = wi >> 3, ww = wi & 7;
    const int tid = threadIdx.x;

    for (int e = tid; e < 64 * 32; e += 256) {
        int r = e >> 5, d = e & 31;
        if (r < WIN2) {
            int i = r / WIN, j = r % WIN;
            int m = b * Nn + (wh * WIN + i) * Wd + (ww * WIN + j);
            const float* base = qkv + (size_t)m * 768 + head * HD + d;
            sq[r * QS + d] = base[0];
            sk[r * QS + d] = base[256];
            sv[r * QS + d] = base[512];
        } else {
            sq[r * QS + d] = 0.f;
            sk[r * QS + d] = 0.f;
        }
    }
    __syncthreads();

    for (int t = tid; t < 2 * WIN2; t += 256) {
        float* row = (t < WIN2) ? (sq + t * QS) : (sk + (t - WIN2) * QS);
        float s = 0.f;
        #pragma unroll
        for (int d = 0; d < HD; d += 2) {
            float2 v = *(float2*)(row + d);
            s += v.x * v.x + v.y * v.y;
        }
        float inv = 1.f / fmaxf(sqrtf(s), 1e-12f);
        #pragma unroll
        for (int d = 0; d < HD; d += 2) {
            float2 v = *(float2*)(row + d);
            v.x *= inv; v.y *= inv;
            *(float2*)(row + d) = v;
        }
    }
    __syncthreads();

    const float tscale = 1.f / fmaxf(tau[head], 0.01f);
    const int tx = tid & 15, ty = tid >> 4;

    float acc[4][4];
    #pragma unroll
    for (int u = 0; u < 4; u++)
        #pragma unroll
        for (int v = 0; v < 4; v++) acc[u][v] = 0.f;
    #pragma unroll
    for (int kk = 0; kk < HD; kk += 2) {
        float2 a2[4], b2[4];
        #pragma unroll
        for (int u = 0; u < 4; u++) a2[u] = *(float2*)&sq[(ty + u * 16) * QS + kk];
        #pragma unroll
        for (int v = 0; v < 4; v++) b2[v] = *(float2*)&sk[(tx + v * 16) * QS + kk];
        #pragma unroll
        for (int u = 0; u < 4; u++)
            #pragma unroll
            for (int v = 0; v < 4; v++)
                acc[u][v] += a2[u].x * b2[v].x + a2[u].y * b2[v].y;
    }
    #pragma unroll
    for (int u = 0; u < 4; u++) {
        int i = ty + u * 16;
        if (i >= WIN2) continue;
        #pragma unroll
        for (int v = 0; v < 4; v++) {
            int j = tx + v * 16;
            if (j >= WIN2) continue;
            float val = acc[u][v] * tscale + cpb[head * (WIN2 * WIN2) + i * WIN2 + j];
            if (shifted) {
                if (wh == NWH - 1 && ((i >= 28) != (j >= 28))) val = -1e30f;
                if (ww == NWH - 1 && (((i % WIN) >= 4) != ((j % WIN) >= 4))) val = -1e30f;
            }
            sd[i * DS + j] = val;
        }
    }
    __syncthreads();

    const int lane = tid & 31, wrp = tid >> 5;
    for (int r = wrp; r < WIN2; r += 8) {
        float v0 = sd[r * DS + lane];
        float v1 = (lane + 32 < WIN2) ? sd[r * DS + lane + 32] : -3e38f;
        float mx = fmaxf(v0, v1);
        #pragma unroll
        for (int o = 16; o > 0; o >>= 1) mx = fmaxf(mx, __shfl_xor_sync(~0u, mx, o));
        float e0 = __expf(v0 - mx);
        float e1 = (lane + 32 < WIN2) ? __expf(v1 - mx) : 0.f;
        float s = e0 + e1;
        #pragma unroll
        for (int o = 16; o > 0; o >>= 1) s += __shfl_xor_sync(~0u, s, o);
        float inv = 1.f / s;
        sd[r * DS + lane] = e0 * inv;
        if (lane + 32 < WIN2) sd[r * DS + lane + 32] = e1 * inv;
    }
    __syncthreads();

    float o2[4][2];
    #pragma unroll
    for (int u = 0; u < 4; u++) { o2[u][0] = 0.f; o2[u][1] = 0.f; }
    for (int j = 0; j < 48; j += 2) {
        float2 p2[4];
        #pragma unroll
        for (int u = 0; u < 4; u++) p2[u] = *(float2*)&sd[(ty + u * 16) * DS + j];
        float2 va = *(float2*)&sv[j * QS + tx * 2];
        float2 vb = *(float2*)&sv[(j + 1) * QS + tx * 2];
        #pragma unroll
        for (int u = 0; u < 4; u++) {
            o2[u][0] += p2[u].x * va.x + p2[u].y * vb.x;
            o2[u][1] += p2[u].x * va.y + p2[u].y * vb.y;
        }
    }
    {   // j = 48 remainder
        float2 vc = *(float2*)&sv[48 * QS + tx * 2];
        #pragma unroll
        for (int u = 0; u < 4; u++) {
            float p = sd[(ty + u * 16) * DS + 48];
            o2[u][0] += p * vc.x;
            o2[u][1] += p * vc.y;
        }
    }
    #pragma unroll
    for (int u = 0; u < 4; u++) {
        int i = ty + u * 16;
        if (i < WIN2) {
            int ii = i / WIN, jj = i % WIN;
            int m = b * Nn + (wh * WIN + ii) * Wd + (ww * WIN + jj);
            size_t off = (size_t)m * Dd + head * HD + tx * 2;
            __half h0 = __float2half_rn(o2[u][0]);
            __half h1 = __float2half_rn(o2[u][1]);
            __half2 hp; hp.x = h0; hp.y = h1;
            *(uint32_t*)(outh + off) = *(uint32_t*)&hp;
            *(uint32_t*)(outl + off) = pack_h2(o2[u][0] - __half2float(h0),
                                               o2[u][1] - __half2float(h1));
        }
    }
}

// ================= LN + residual =================
__global__ void ln_residual_kernel(const float* __restrict__ A, const float* __restrict__ g,
                                   const float* __restrict__ be, float* __restrict__ xm,
                                   __half* __restrict__ xh, __half* __restrict__ xl,
                                   int gather) {
    int row = blockIdx.x * 8 + (threadIdx.x >> 5);
    int lane = threadIdx.x & 31;
    int src = row;
    if (gather) {
        int b = row / Nn, rem = row % Nn;
        int h = rem / Wd, w = rem % Wd;
        src = b * Nn + ((h + Hh - DISP) % Hh) * Wd + ((w + Wd - DISP) % Wd);
    }
    const float4* a4 = (const float4*)(A + (size_t)src * Dd);
    float4 v0 = a4[lane], v1 = a4[lane + 32];
    float s  = v0.x + v0.y + v0.z + v0.w + v1.x + v1.y + v1.z + v1.w;
    float s2 = v0.x*v0.x + v0.y*v0.y + v0.z*v0.z + v0.w*v0.w
             + v1.x*v1.x + v1.y*v1.y + v1.z*v1.z + v1.w*v1.w;
    #pragma unroll
    for (int o = 16; o > 0; o >>= 1) {
        s  += __shfl_xor_sync(~0u, s, o);
        s2 += __shfl_xor_sync(~0u, s2, o);
    }
    float mean = s * (1.f / Dd);
    float var  = s2 * (1.f / Dd) - mean * mean;
    float inv  = rsqrtf(var + EPSLN);

    float4 g0 = ((const float4*)g)[lane],  g1 = ((const float4*)g)[lane + 32];
    float4 b0 = ((const float4*)be)[lane], b1 = ((const float4*)be)[lane + 32];
    float4* x4 = (float4*)(xm + (size_t)row * Dd);
    float4 r0 = x4[lane], r1 = x4[lane + 32];
    r0.x += (v0.x - mean) * inv * g0.x + b0.x;
    r0.y += (v0.y - mean) * inv * g0.y + b0.y;
    r0.z += (v0.z - mean) * inv * g0.z + b0.z;
    r0.w += (v0.w - mean) * inv * g0.w + b0.w;
    r1.x += (v1.x - mean) * inv * g1.x + b1.x;
    r1.y += (v1.y - mean) * inv * g1.y + b1.y;
    r1.z += (v1.z - mean) * inv * g1.z + b1.z;
    r1.w += (v1.w - mean) * inv * g1.w + b1.w;
    x4[lane] = r0; x4[lane + 32] = r1;

    uint2 h, l;
    size_t e0 = (size_t)row * Dd + lane * 4;
    size_t e1 = e0 + 128;
    split_f4h(r0, h, l);
    *(uint2*)(xh + e0) = h; *(uint2*)(xl + e0) = l;
    split_f4h(r1, h, l);
    *(uint2*)(xh + e1) = h; *(uint2*)(xl + e1) = l;
}

// ================= final LN =================
__global__ void ln_final_kernel(const float* __restrict__ A, const float* __restrict__ g,
                                const float* __restrict__ be, float* __restrict__ out) {
    int row = blockIdx.x * 8 + (threadIdx.x >> 5);
    int lane = threadIdx.x & 31;
    const float4* a4 = (const float4*)(A + (size_t)row * Dd);
    float4 v0 = a4[lane], v1 = a4[lane + 32];
    float s  = v0.x + v0.y + v0.z + v0.w + v1.x + v1.y + v1.z + v1.w;
    float s2 = v0.x*v0.x + v0.y*v0.y + v0.z*v0.z + v0.w*v0.w
             + v1.x*v1.x + v1.y*v1.y + v1.z*v1.z + v1.w*v1.w;
    #pragma unroll
    for (int o = 16; o > 0; o >>= 1) {
        s  += __shfl_xor_sync(~0u, s, o);
        s2 += __shfl_xor_sync(~0u, s2, o);
    }
    float mean = s * (1.f / Dd);
    float var  = s2 * (1.f / Dd) - mean * mean;
    float inv  = rsqrtf(var + EPSLN);
    float4 g0 = ((const float4*)g)[lane],  g1 = ((const float4*)g)[lane + 32];
    float4 b0 = ((const float4*)be)[lane], b1 = ((const float4*)be)[lane + 32];
    float4 o0, o1;
    o0.x = (v0.x - mean) * inv * g0.x + b0.x;
    o0.y = (v0.y - mean) * inv * g0.y + b0.y;
    o0.z = (v0.z - mean) * inv * g0.z + b0.z;
    o0.w = (v0.w - mean) * inv * g0.w + b0.w;
    o1.x = (v1.x - mean) * inv * g1.x + b1.x;
    o1.y = (v1.y - mean) * inv * g1.y + b1.y;
    o1.z = (v1.z - mean) * inv * g1.z + b1.z;
    o1.w = (v1.w - mean) * inv * g1.w + b1.w;
    float4* out4 = (float4*)(out + (size_t)row * Dd);
    out4[lane] = o0; out4[lane + 32] = o1;
}

// ================= launch =================
extern "C" void kernel_launch(void* const* d_in, const int* in_sizes, int n_in,
                              void* d_out, int out_size) {
    const float* x    = (const float*)d_in[0];
    const float* spe  = (const float*)d_in[1];
    const float* qkvw = (const float*)d_in[2];
    const float* tau  = (const float*)d_in[3];
    const float* cw1  = (const float*)d_in[4];
    const float* cb1  = (const float*)d_in[5];
    const float* cw2  = (const float*)d_in[6];
    const float* cb2  = (const float*)d_in[7];
    const float* ow   = (const float*)d_in[8];
    const float* ob   = (const float*)d_in[9];
    const float* ln1g = (const float*)d_in[10];
    const float* ln1b = (const float*)d_in[11];
    const float* fw1  = (const float*)d_in[12];
    const float* fb1  = (const float*)d_in[13];
    const float* fw2  = (const float*)d_in[14];
    const float* fb2  = (const float*)d_in[15];
    const float* ln2g = (const float*)d_in[16];
    const float* ln2b = (const float*)d_in[17];
    const float* ng   = (const float*)d_in[18];
    const float* nb   = (const float*)d_in[19];
    float* out = (float*)d_out;

    float *xm, *qkv, *tmp, *cpb;
    __half *xmh, *xml, *ath, *atl, *ffh, *ffl, *wth;
    cudaGetSymbolAddress((void**)&xm,  g_xm);
    cudaGetSymbolAddress((void**)&qkv, g_qkv);
    cudaGetSymbolAddress((void**)&tmp, g_tmp);
    cudaGetSymbolAddress((void**)&cpb, g_cpb);
    cudaGetSymbolAddress((void**)&xmh, g_xmh);
    cudaGetSymbolAddress((void**)&xml, g_xml);
    cudaGetSymbolAddress((void**)&ath, g_ath);
    cudaGetSymbolAddress((void**)&atl, g_atl);
    cudaGetSymbolAddress((void**)&ffh, g_ffh);
    cudaGetSymbolAddress((void**)&ffl, g_ffl);
    cudaGetSymbolAddress((void**)&wth, g_wth);

    cudaFuncSetAttribute(hgemm_kernel<0, false, 0>, cudaFuncAttributeMaxDynamicSharedMemorySize, GEMM_SMEM);
    cudaFuncSetAttribute(hgemm_kernel<0, true,  0>, cudaFuncAttributeMaxDynamicSharedMemorySize, GEMM_SMEM);
    cudaFuncSetAttribute(hgemm_kernel<1, false, 1>, cudaFuncAttributeMaxDynamicSharedMemorySize, GEMM_SMEM);

    // weight transpose + fp16 round, both layers batched via z
    wtconv_kernel<<<dim3(24, 8, 2), dim3(32, 8)>>>(qkvw, wth,          256, 768,
                                                   (size_t)Dd * 768, WLSTRIDE);
    wtconv_kernel<<<dim3(8,  8, 2), dim3(32, 8)>>>(ow,   wth + 196608, 256, 256,
                                                   (size_t)Dd * Dd,  WLSTRIDE);
    wtconv_kernel<<<dim3(32, 8, 2), dim3(32, 8)>>>(fw1,  wth + 262144, 256, 1024,
                                                   (size_t)Dd * FF,  WLSTRIDE);
    wtconv_kernel<<<dim3(8, 32, 2), dim3(32, 8)>>>(fw2,  wth + 524288, 1024, 256,
                                                   (size_t)FF * Dd,  WLSTRIDE);

    // xm = x + spe (+ fp16 split)
    {
        int n4 = MROWS * Dd / 4;
        add_spe_kernel<<<(n4 + 255) / 256, 256>>>(x, spe, xm, xmh, xml, n4);
    }

    const int lnBlocks = MROWS / 8;
    const int MT = MROWS / 256;   // 196
    for (int layer = 0; layer < 2; layer++) {
        int shifted = (layer == 1);
        size_t wo = (size_t)layer * WLSTRIDE;

        cpb_kernel<<<WIN2 * WIN2, 256>>>(cw1 + layer * 2 * CPBH, cb1 + layer * CPBH,
                                         cw2 + layer * CPBH * HEADS, cb2 + layer * HEADS, cpb);

        // qkv = (rolled) xm @ qkv_w -> fp32
        if (shifted)
            hgemm_kernel<0, true, 0><<<dim3(6, MT), 256, GEMM_SMEM>>>(
                xmh, xml, wth + wo, nullptr, qkv, nullptr, nullptr, 768, 256);
        else
            hgemm_kernel<0, false, 0><<<dim3(6, MT), 256, GEMM_SMEM>>>(
                xmh, xml, wth + wo, nullptr, qkv, nullptr, nullptr, 768, 256);

        attn_kernel<<<dim3(NW, HEADS, Bb), 256>>>(qkv, tau + layer * HEADS, cpb, ath, atl, shifted);

        // o-proj -> tmp (fp32)
        hgemm_kernel<0, false, 0><<<dim3(2, MT), 256, GEMM_SMEM>>>(
            ath, atl, wth + wo + 196608, ob + layer * Dd,
            tmp, nullptr, nullptr, 256, 256);

        // xm += LN(oproj) (rolled back if shifted)
        ln_residual_kernel<<<lnBlocks, 256>>>(tmp, ln1g + layer * Dd, ln1b + layer * Dd,
                                              xm, xmh, xml, shifted);

        // ffn1: gelu(xm @ fw1 + fb1) -> fp16 hi/lo
        hgemm_kernel<1, false, 1><<<dim3(8, MT), 256, GEMM_SMEM>>>(
            xmh, xml, wth + wo + 262144, fb1 + layer * FF,
            nullptr, ffh, ffl, 1024, 256);

        // ffn2 -> tmp (fp32)
        hgemm_kernel<0, false, 0><<<dim3(2, MT), 256, GEMM_SMEM>>>(
            ffh, ffl, wth + wo + 524288, fb2 + layer * Dd,
            tmp, nullptr, nullptr, 256, 1024);

        // xm += LN(ffn2)
        ln_residual_kernel<<<lnBlocks, 256>>>(tmp, ln2g + layer * Dd, ln2b + layer * Dd,
                                              xm, xmh, xml, 0);
    }

    ln_final_kernel<<<MROWS / 8, 256>>>(xm, ng, nb, out);
}

// round 9
// speedup vs baseline: 1.2903x; 1.0090x over previous
#include <cuda_runtime.h>
#include <cuda_fp16.h>
#include <cstdint>
#include <math.h>

#define Bb     16
#define Hh     56
#define Wd     56
#define Nn     3136
#define Dd     256
#define HEADS  8
#define HD     32
#define WIN    7
#define WIN2   49
#define NWH    8
#define NW     64
#define DISP   3
#define FF     1024
#define CPBH   512
#define EPSLN  1e-5f
#define MROWS  50176   // B * N
#define MTILES 196     // MROWS / 256

// ================= PTX helpers (plain compute_103 features only) =================
__device__ __forceinline__ uint32_t smem_to_u32(const void* p) {
    uint32_t a;
    asm("{ .reg .u64 t; cvta.to.shared.u64 t, %1; cvt.u32.u64 %0, t; }" : "=r"(a) : "l"(p));
    return a;
}
#define CP_ASYNC_CG(dst, src) \
    asm volatile("cp.async.cg.shared.global [%0], [%1], 16;" :: "r"(dst), "l"(src))
#define CP_ASYNC_COMMIT() asm volatile("cp.async.commit_group;" ::: "memory")
#define CP_ASYNC_WAIT(n)  asm volatile("cp.async.wait_group %0;" :: "n"(n) : "memory")

__device__ __forceinline__ void ldsm_x4(uint32_t* r, uint32_t addr) {
    asm volatile("ldmatrix.sync.aligned.m8n8.x4.shared.b16 {%0,%1,%2,%3}, [%4];"
        : "=r"(r[0]), "=r"(r[1]), "=r"(r[2]), "=r"(r[3]) : "r"(addr));
}
__device__ __forceinline__ void mma_f16(float* c, const uint32_t* a, const uint32_t* b) {
    asm volatile("mma.sync.aligned.m16n8k16.row.col.f32.f16.f16.f32 "
        "{%0,%1,%2,%3},{%4,%5,%6,%7},{%8,%9},{%0,%1,%2,%3};"
        : "+f"(c[0]), "+f"(c[1]), "+f"(c[2]), "+f"(c[3])
        : "r"(a[0]), "r"(a[1]), "r"(a[2]), "r"(a[3]), "r"(b[0]), "r"(b[1]));
}

// ================= device scratch =================
__device__ float  g_xm  [MROWS * Dd];
__device__ __half g_xmh [MROWS * Dd];
__device__ __half g_xml [MROWS * Dd];
__device__ float  g_qkv [MROWS * 3 * Dd];
__device__ __half g_ath [MROWS * Dd];
__device__ __half g_atl [MROWS * Dd];
__device__ __half g_ffh [MROWS * FF];
__device__ __half g_ffl [MROWS * FF];
__device__ float  g_tmp [MROWS * Dd];
__device__ float  g_cpb [HEADS * WIN2 * WIN2];
// transposed fp16 weights (hi only), per layer:
// [0) qkvT 768x256 | 196608) owT 256x256 | 262144) fw1T 1024x256 | 524288) fw2T 256x1024
#define WLSTRIDE 786432
__device__ __half g_wth [2 * WLSTRIDE];

// ================= small helpers =================
__device__ __forceinline__ uint32_t pack_h2(float a, float b) {
    __half2 h = __floats2half2_rn(a, b);
    return *(uint32_t*)&h;
}
__device__ __forceinline__ void split_f4h(float4 v, uint2& hi, uint2& lo) {
    __half hx = __float2half_rn(v.x), hy = __float2half_rn(v.y);
    __half hz = __float2half_rn(v.z), hw = __float2half_rn(v.w);
    __half2 p01; p01.x = hx; p01.y = hy;
    __half2 p23; p23.x = hz; p23.y = hw;
    hi.x = *(uint32_t*)&p01;
    hi.y = *(uint32_t*)&p23;
    lo.x = pack_h2(v.x - __half2float(hx), v.y - __half2float(hy));
    lo.y = pack_h2(v.z - __half2float(hz), v.w - __half2float(hw));
}

// ================= add SPE =================
__global__ void add_spe_kernel(const float* __restrict__ x, const float* __restrict__ spe,
                               float* __restrict__ xm, __half* __restrict__ xh,
                               __half* __restrict__ xl, int n4) {
    int i = blockIdx.x * blockDim.x + threadIdx.x;
    if (i < n4) {
        float4 a = ((const float4*)x)[i];
        float4 b = ((const float4*)spe)[i];
        a.x += b.x; a.y += b.y; a.z += b.z; a.w += b.w;
        ((float4*)xm)[i] = a;
        uint2 h, l; split_f4h(a, h, l);
        ((uint2*)xh)[i] = h;
        ((uint2*)xl)[i] = l;
    }
}

// ================= weight transpose + fp16 round: W[K,N] -> T[N,K], z = layer =================
__global__ void wtconv_kernel(const float* __restrict__ W, __half* __restrict__ Th,
                              int K, int N, size_t wstride, size_t tstride) {
    W  += (size_t)blockIdx.z * wstride;
    Th += (size_t)blockIdx.z * tstride;
    __shared__ float t[32][33];
    int bn = blockIdx.x * 32, bk = blockIdx.y * 32;
    int tx = threadIdx.x, ty = threadIdx.y;
    #pragma unroll
    for (int j = 0; j < 32; j += 8)
        t[ty + j][tx] = W[(size_t)(bk + ty + j) * N + bn + tx];
    __syncthreads();
    #pragma unroll
    for (int j = 0; j < 32; j += 8) {
        Th[(size_t)(bn + ty + j) * K + bk + tx] = __float2half_rn(t[tx][ty + j]);
    }
}

// ================= CPB MLP =================
__global__ void cpb_kernel(const float* __restrict__ cw1, const float* __restrict__ cb1,
                           const float* __restrict__ cw2, const float* __restrict__ cb2,
                           float* __restrict__ cpb) {
    int p = blockIdx.x;
    int i = p / WIN2, j = p % WIN2;
    float dy = (float)(j / WIN - i / WIN);
    float dx = (float)(j % WIN - i % WIN);
    float r0 = ((dy > 0.f) - (dy < 0.f)) * log1pf(fabsf(dy));
    float r1 = ((dx > 0.f) - (dx < 0.f)) * log1pf(fabsf(dx));
    int tid = threadIdx.x;
    int c0 = tid, c1 = tid + 256;
    float h0 = fmaxf(r0 * cw1[c0] + r1 * cw1[CPBH + c0] + cb1[c0], 0.f);
    float h1 = fmaxf(r0 * cw1[c1] + r1 * cw1[CPBH + c1] + cb1[c1], 0.f);
    __shared__ float red[256];
    for (int h = 0; h < HEADS; h++) {
        red[tid] = h0 * cw2[c0 * HEADS + h] + h1 * cw2[c1 * HEADS + h];
        __syncthreads();
        for (int s = 128; s > 0; s >>= 1) {
            if (tid < s) red[tid] += red[tid + s];
            __syncthreads();
        }
        if (tid == 0) cpb[h * (WIN2 * WIN2) + p] = red[0] + cb2[h];
        __syncthreads();
    }
}

// ================= shared epilogue =================
template<int ACT, int OUTMODE>
__device__ __forceinline__ void gemm_epilogue(
    float acc[4][8][4], int bm, int bn, int warpM, int warpN, int lane,
    const float* __restrict__ bias, float* __restrict__ Cf,
    __half* __restrict__ Ch, __half* __restrict__ Cl, int Ntot) {
    const int g = lane >> 2, q = lane & 3;
    #pragma unroll
    for (int m = 0; m < 4; m++) {
        #pragma unroll
        for (int n = 0; n < 8; n++) {
            int col = bn + warpN * 64 + n * 8 + 2 * q;
            float b0 = bias ? bias[col] : 0.f;
            float b1 = bias ? bias[col + 1] : 0.f;
            #pragma unroll
            for (int hrow = 0; hrow < 2; hrow++) {
                int row = bm + warpM * 64 + m * 16 + g + hrow * 8;
                float v0 = acc[m][n][hrow * 2 + 0] + b0;
                float v1 = acc[m][n][hrow * 2 + 1] + b1;
                if (ACT == 1) {
                    v0 = v0 * 0.5f * (1.f + erff(v0 * 0.7071067811865476f));
                    v1 = v1 * 0.5f * (1.f + erff(v1 * 0.7071067811865476f));
                }
                if (OUTMODE == 0) {
                    *(float2*)(Cf + (size_t)row * Ntot + col) = make_float2(v0, v1);
                } else {
                    __half h0 = __float2half_rn(v0);
                    __half h1 = __float2half_rn(v1);
                    __half2 hp; hp.x = h0; hp.y = h1;
                    *(uint32_t*)(Ch + (size_t)row * Ntot + col) = *(uint32_t*)&hp;
                    *(uint32_t*)(Cl + (size_t)row * Ntot + col) =
                        pack_h2(v0 - __half2float(h0), v1 - __half2float(h1));
                }
            }
        }
    }
}

// ================= persistent-B HMMA GEMM, K = 256 fixed =================
// B panel (128 x 256 fp16) resident in smem; CTA loops over M tiles mt = g, g+G, ...
#define SAS      40                          // A chunk row stride (elems), 80B
#define PA_STAGE 40960                       // A stage: hi 20480 + lo 20480
#define PB_STRIDE 264                        // B row stride (elems), 528B
#define PB_BYTES (128 * PB_STRIDE * 2)       // 67584
#define PGEMM_SMEM (PB_BYTES + 3 * PA_STAGE) // 190464

template<int ACT, bool GATHER, int OUTMODE>
__global__ void __launch_bounds__(256, 1)
hgemm_persist_kernel(const __half* __restrict__ Ah, const __half* __restrict__ Al,
                     const __half* __restrict__ Bth,
                     const float* __restrict__ bias, float* __restrict__ Cf,
                     __half* __restrict__ Ch, __half* __restrict__ Cl,
                     int Ntot, int G) {
    extern __shared__ char smem_raw[];
    const uint32_t sB = smem_to_u32(smem_raw);
    const uint32_t sA = sB + PB_BYTES;
    const int tid  = threadIdx.x;
    const int lane = tid & 31, wid = tid >> 5;
    const int warpM = wid >> 1, warpN = wid & 1;   // 4x2
    const int bn = blockIdx.x * 128;
    const int g  = blockIdx.y;

    // ---- load B panel once (128 rows x 512B) ----
    #pragma unroll
    for (int it = 0; it < 16; it++) {
        int idx = tid + it * 256;            // 4096 16B-chunks
        int n = idx >> 5, q = idx & 31;
        CP_ASYNC_CG(sB + (uint32_t)(n * (PB_STRIDE * 2) + q * 16),
                    Bth + (size_t)(bn + n) * 256 + q * 8);
    }
    CP_ASYNC_COMMIT();

    // per-thread A slot geometry (row within tile, 16B column)
    int arow_s[4], acol_s[4];
    uint32_t aoff[4];
    #pragma unroll
    for (int l = 0; l < 4; l++) {
        int c = tid + l * 256;
        int r = c >> 2, q = c & 3;
        arow_s[l] = r; acol_s[l] = q * 8;
        aoff[l] = (uint32_t)(r * (SAS * 2) + q * 16);
    }

    const int ntl = (MTILES - 1 - g) / G + 1;      // tiles for this CTA
    const int total_cc = ntl * 8;

    auto issue = [&](int cc, int sc) {
        int tile = cc >> 3, c = cc & 7;
        int bm = (g + tile * G) * 256;
        uint32_t stg = sA + (uint32_t)sc * PA_STAGE;
        int kt = c << 5;
        #pragma unroll
        for (int l = 0; l < 4; l++) {
            int gm = bm + arow_s[l];
            if (GATHER) {
                int b = gm / Nn, rem = gm - b * Nn;
                int h = rem / Wd, w = rem - h * Wd;
                h = (h + DISP) % Hh; w = (w + DISP) % Wd;
                gm = b * Nn + h * Wd + w;
            }
            size_t base = (size_t)gm * 256 + kt + acol_s[l];
            CP_ASYNC_CG(stg + aoff[l],         Ah + base);
            CP_ASYNC_CG(stg + 20480 + aoff[l], Al + base);
        }
    };

    float acc[4][8][4];
    #pragma unroll
    for (int m = 0; m < 4; m++)
        #pragma unroll
        for (int n = 0; n < 8; n++)
            #pragma unroll
            for (int e = 0; e < 4; e++) acc[m][n][e] = 0.f;

    const int arow  = (lane & 15);
    const int ahalf = (lane >> 4);
    const int bidx  = lane & 7;
    const int bkh   = (lane >> 3) & 1;
    const int bsub  = lane >> 4;

    issue(0, 0); CP_ASYNC_COMMIT();
    if (total_cc > 1) issue(1, 1);
    CP_ASYNC_COMMIT();

    int sc = 0, scn = 2;
    for (int cc = 0; cc < total_cc; cc++) {
        CP_ASYNC_WAIT(1);
        __syncthreads();
        if (cc + 2 < total_cc) issue(cc + 2, scn);
        CP_ASYNC_COMMIT();

        uint32_t stg = sA + (uint32_t)sc * PA_STAGE;
        const int c = cc & 7;                 // chunk within tile (k base = c*32)
        #pragma unroll
        for (int ks = 0; ks < 2; ks++) {
            const int kg = c * 2 + ks;        // global 16-K step, 0..15
            uint32_t ah[4][4], al[4][4], bh[8][2];
            #pragma unroll
            for (int m = 0; m < 4; m++) {
                uint32_t off = (uint32_t)((warpM * 64 + m * 16 + arow) * (SAS * 2)
                                          + (ks * 16 + ahalf * 8) * 2);
                ldsm_x4(ah[m], stg + off);
                ldsm_x4(al[m], stg + 20480 + off);
            }
            #pragma unroll
            for (int pr = 0; pr < 4; pr++) {
                uint32_t off = (uint32_t)((warpN * 64 + pr * 16 + bsub * 8 + bidx) * (PB_STRIDE * 2)
                                          + (kg * 16 + bkh * 8) * 2);
                uint32_t t[4];
                ldsm_x4(t, sB + off);
                bh[pr * 2][0] = t[0]; bh[pr * 2][1] = t[1];
                bh[pr * 2 + 1][0] = t[2]; bh[pr * 2 + 1][1] = t[3];
            }
            #pragma unroll
            for (int m = 0; m < 4; m++)
                #pragma unroll
                for (int n = 0; n < 8; n++) mma_f16(acc[m][n], ah[m], bh[n]);
            #pragma unroll
            for (int m = 0; m < 4; m++)
                #pragma unroll
                for (int n = 0; n < 8; n++) mma_f16(acc[m][n], al[m], bh[n]);
        }
        sc = (sc == 2) ? 0 : sc + 1;
        scn = (scn == 2) ? 0 : scn + 1;

        if (c == 7) {
            int bm = (g + (cc >> 3) * G) * 256;
            gemm_epilogue<ACT, OUTMODE>(acc, bm, bn, warpM, warpN, lane,
                                        bias, Cf, Ch, Cl, Ntot);
            #pragma unroll
            for (int m = 0; m < 4; m++)
                #pragma unroll
                for (int n = 0; n < 8; n++)
                    #pragma unroll
                    for (int e = 0; e < 4; e++) acc[m][n][e] = 0.f;
        }
    }
}

// ================= streaming HMMA GEMM (for K=1024 ffn2) =================
#define AH_OFF   0
#define AL_OFF   20480
#define BH_OFF   40960
#define STAGE_B  51200
#define GEMM_SMEM (3 * STAGE_B)              // 153600

template<int ACT, int OUTMODE>
__global__ void __launch_bounds__(256, 1)
hgemm_kernel(const __half* __restrict__ Ah, const __half* __restrict__ Al,
             const __half* __restrict__ Bth,
             const float* __restrict__ bias, float* __restrict__ Cf,
             __half* __restrict__ Ch, __half* __restrict__ Cl,
             int Ntot, int K) {
    extern __shared__ char smem_raw[];
    const uint32_t sbase = smem_to_u32(smem_raw);
    const int tid  = threadIdx.x;
    const int lane = tid & 31, wid = tid >> 5;
    const int warpM = wid >> 1, warpN = wid & 1;
    const int bm = blockIdx.y * 256, bn = blockIdx.x * 128;

    const __half *pAh[4], *pAl[4], *pBh[2];
    uint32_t aoff[4], boff[2];
    #pragma unroll
    for (int l = 0; l < 4; l++) {
        int c = tid + l * 256;
        int r = c >> 2, q = c & 3;
        pAh[l] = Ah + (size_t)(bm + r) * K + q * 8;
        pAl[l] = Al + (size_t)(bm + r) * K + q * 8;
        aoff[l] = (uint32_t)(r * (SAS * 2) + q * 16);
    }
    #pragma unroll
    for (int l = 0; l < 2; l++) {
        int c = tid + l * 256;
        int r = c >> 2, q = c & 3;
        pBh[l] = Bth + (size_t)(bn + r) * K + q * 8;
        boff[l] = (uint32_t)(r * (SAS * 2) + q * 16);
    }

    float acc[4][8][4];
    #pragma unroll
    for (int m = 0; m < 4; m++)
        #pragma unroll
        for (int n = 0; n < 8; n++)
            #pragma unroll
            for (int e = 0; e < 4; e++) acc[m][n][e] = 0.f;

    const int nch = K >> 5;

    auto load_stage = [&](int c, int sc) {
        uint32_t stg = sbase + (uint32_t)sc * STAGE_B;
        int kt = c << 5;
        #pragma unroll
        for (int l = 0; l < 4; l++) {
            CP_ASYNC_CG(stg + AH_OFF + aoff[l], pAh[l] + kt);
            CP_ASYNC_CG(stg + AL_OFF + aoff[l], pAl[l] + kt);
        }
        #pragma unroll
        for (int l = 0; l < 2; l++) {
            CP_ASYNC_CG(stg + BH_OFF + boff[l], pBh[l] + kt);
        }
    };

    const int arow  = (lane & 15);
    const int ahalf = (lane >> 4);
    const int bidx  = lane & 7;
    const int bkh   = (lane >> 3) & 1;
    const int bsub  = lane >> 4;

    load_stage(0, 0);
    CP_ASYNC_COMMIT();
    if (nch > 1) load_stage(1, 1);
    CP_ASYNC_COMMIT();

    int sc = 0, scn = 2;
    for (int c = 0; c < nch; c++) {
        CP_ASYNC_WAIT(1);
        __syncthreads();
        if (c + 2 < nch) load_stage(c + 2, scn);
        CP_ASYNC_COMMIT();

        uint32_t stg = sbase + (uint32_t)sc * STAGE_B;
        #pragma unroll
        for (int ks = 0; ks < 2; ks++) {
            uint32_t ah[4][4], al[4][4], bh[8][2];
            #pragma unroll
            for (int m = 0; m < 4; m++) {
                uint32_t off = (uint32_t)((warpM * 64 + m * 16 + arow) * (SAS * 2)
                                          + (ks * 16 + ahalf * 8) * 2);
                ldsm_x4(ah[m], stg + AH_OFF + off);
                ldsm_x4(al[m], stg + AL_OFF + off);
            }
            #pragma unroll
            for (int pr = 0; pr < 4; pr++) {
                uint32_t off = (uint32_t)((warpN * 64 + pr * 16 + bsub * 8 + bidx) * (SAS * 2)
                                          + (ks * 16 + bkh * 8) * 2);
                uint32_t t[4];
                ldsm_x4(t, stg + BH_OFF + off);
                bh[pr * 2][0] = t[0]; bh[pr * 2][1] = t[1];
                bh[pr * 2 + 1][0] = t[2]; bh[pr * 2 + 1][1] = t[3];
            }
            #pragma unroll
            for (int m = 0; m < 4; m++)
                #pragma unroll
                for (int n = 0; n < 8; n++) mma_f16(acc[m][n], ah[m], bh[n]);
            #pragma unroll
            for (int m = 0; m < 4; m++)
                #pragma unroll
                for (int n = 0; n < 8; n++) mma_f16(acc[m][n], al[m], bh[n]);
        }
        sc = (sc == 2) ? 0 : sc + 1;
        scn = (scn == 2) ? 0 : scn + 1;
    }

    gemm_epilogue<ACT, OUTMODE>(acc, bm, bn, warpM, warpN, lane, bias, Cf, Ch, Cl, Ntot);
}

// ================= window attention (float2-vectorized, emits fp16 hi/lo) =================
#define QS 34
#define DS 52
__global__ void __launch_bounds__(256)
attn_kernel(const float* __restrict__ qkv, const float* __restrict__ tau,
            const float* __restrict__ cpb, __half* __restrict__ outh,
            __half* __restrict__ outl, int shifted) {
    __shared__ float sq[64 * QS];
    __shared__ float sk[64 * QS];
    __shared__ float sv[49 * QS];
    __shared__ float sd[64 * DS];

    const int wi   = blockIdx.x;
    const int head = blockIdx.y;
    const int b    = blockIdx.z;
    const int wh = wi >> 3, ww = wi & 7;
    const int tid = threadIdx.x;

    for (int e = tid; e < 64 * 32; e += 256) {
        int r = e >> 5, d = e & 31;
        if (r < WIN2) {
            int i = r / WIN, j = r % WIN;
            int m = b * Nn + (wh * WIN + i) * Wd + (ww * WIN + j);
            const float* base = qkv + (size_t)m * 768 + head * HD + d;
            sq[r * QS + d] = base[0];
            sk[r * QS + d] = base[256];
            sv[r * QS + d] = base[512];
        } else {
            sq[r * QS + d] = 0.f;
            sk[r * QS + d] = 0.f;
        }
    }
    __syncthreads();

    for (int t = tid; t < 2 * WIN2; t += 256) {
        float* row = (t < WIN2) ? (sq + t * QS) : (sk + (t - WIN2) * QS);
        float s = 0.f;
        #pragma unroll
        for (int d = 0; d < HD; d += 2) {
            float2 v = *(float2*)(row + d);
            s += v.x * v.x + v.y * v.y;
        }
        float inv = 1.f / fmaxf(sqrtf(s), 1e-12f);
        #pragma unroll
        for (int d = 0; d < HD; d += 2) {
            float2 v = *(float2*)(row + d);
            v.x *= inv; v.y *= inv;
            *(float2*)(row + d) = v;
        }
    }
    __syncthreads();

    const float tscale = 1.f / fmaxf(tau[head], 0.01f);
    const int tx = tid & 15, ty = tid >> 4;

    float acc[4][4];
    #pragma unroll
    for (int u = 0; u < 4; u++)
        #pragma unroll
        for (int v = 0; v < 4; v++) acc[u][v] = 0.f;
    #pragma unroll
    for (int kk = 0; kk < HD; kk += 2) {
        float2 a2[4], b2[4];
        #pragma unroll
        for (int u = 0; u < 4; u++) a2[u] = *(float2*)&sq[(ty + u * 16) * QS + kk];
        #pragma unroll
        for (int v = 0; v < 4; v++) b2[v] = *(float2*)&sk[(tx + v * 16) * QS + kk];
        #pragma unroll
        for (int u = 0; u < 4; u++)
            #pragma unroll
            for (int v = 0; v < 4; v++)
                acc[u][v] += a2[u].x * b2[v].x + a2[u].y * b2[v].y;
    }
    #pragma unroll
    for (int u = 0; u < 4; u++) {
        int i = ty + u * 16;
        if (i >= WIN2) continue;
        #pragma unroll
        for (int v = 0; v < 4; v++) {
            int j = tx + v * 16;
            if (j >= WIN2) continue;
            float val = acc[u][v] * tscale + cpb[head * (WIN2 * WIN2) + i * WIN2 + j];
            if (shifted) {
                if (wh == NWH - 1 && ((i >= 28) != (j >= 28))) val = -1e30f;
                if (ww == NWH - 1 && (((i % WIN) >= 4) != ((j % WIN) >= 4))) val = -1e30f;
            }
            sd[i * DS + j] = val;
        }
    }
    __syncthreads();

    const int lane = tid & 31, wrp = tid >> 5;
    for (int r = wrp; r < WIN2; r += 8) {
        float v0 = sd[r * DS + lane];
        float v1 = (lane + 32 < WIN2) ? sd[r * DS + lane + 32] : -3e38f;
        float mx = fmaxf(v0, v1);
        #pragma unroll
        for (int o = 16; o > 0; o >>= 1) mx = fmaxf(mx, __shfl_xor_sync(~0u, mx, o));
        float e0 = __expf(v0 - mx);
        float e1 = (lane + 32 < WIN2) ? __expf(v1 - mx) : 0.f;
        float s = e0 + e1;
        #pragma unroll
        for (int o = 16; o > 0; o >>= 1) s += __shfl_xor_sync(~0u, s, o);
        float inv = 1.f / s;
        sd[r * DS + lane] = e0 * inv;
        if (lane + 32 < WIN2) sd[r * DS + lane + 32] = e1 * inv;
    }
    __syncthreads();

    float o2[4][2];
    #pragma unroll
    for (int u = 0; u < 4; u++) { o2[u][0] = 0.f; o2[u][1] = 0.f; }
    for (int j = 0; j < 48; j += 2) {
        float2 p2[4];
        #pragma unroll
        for (int u = 0; u < 4; u++) p2[u] = *(float2*)&sd[(ty + u * 16) * DS + j];
        float2 va = *(float2*)&sv[j * QS + tx * 2];
        float2 vb = *(float2*)&sv[(j + 1) * QS + tx * 2];
        #pragma unroll
        for (int u = 0; u < 4; u++) {
            o2[u][0] += p2[u].x * va.x + p2[u].y * vb.x;
            o2[u][1] += p2[u].x * va.y + p2[u].y * vb.y;
        }
    }
    {
        float2 vc = *(float2*)&sv[48 * QS + tx * 2];
        #pragma unroll
        for (int u = 0; u < 4; u++) {
            float p = sd[(ty + u * 16) * DS + 48];
            o2[u][0] += p * vc.x;
            o2[u][1] += p * vc.y;
        }
    }
    #pragma unroll
    for (int u = 0; u < 4; u++) {
        int i = ty + u * 16;
        if (i < WIN2) {
            int ii = i / WIN, jj = i % WIN;
            int m = b * Nn + (wh * WIN + ii) * Wd + (ww * WIN + jj);
            size_t off = (size_t)m * Dd + head * HD + tx * 2;
            __half h0 = __float2half_rn(o2[u][0]);
            __half h1 = __float2half_rn(o2[u][1]);
            __half2 hp; hp.x = h0; hp.y = h1;
            *(uint32_t*)(outh + off) = *(uint32_t*)&hp;
            *(uint32_t*)(outl + off) = pack_h2(o2[u][0] - __half2float(h0),
                                               o2[u][1] - __half2float(h1));
        }
    }
}

// ================= LN + residual =================
__global__ void ln_residual_kernel(const float* __restrict__ A, const float* __restrict__ g,
                                   const float* __restrict__ be, float* __restrict__ xm,
                                   __half* __restrict__ xh, __half* __restrict__ xl,
                                   int gather) {
    int row = blockIdx.x * 8 + (threadIdx.x >> 5);
    int lane = threadIdx.x & 31;
    int src = row;
    if (gather) {
        int b = row / Nn, rem = row % Nn;
        int h = rem / Wd, w = rem % Wd;
        src = b * Nn + ((h + Hh - DISP) % Hh) * Wd + ((w + Wd - DISP) % Wd);
    }
    const float4* a4 = (const float4*)(A + (size_t)src * Dd);
    float4 v0 = a4[lane], v1 = a4[lane + 32];
    float s  = v0.x + v0.y + v0.z + v0.w + v1.x + v1.y + v1.z + v1.w;
    float s2 = v0.x*v0.x + v0.y*v0.y + v0.z*v0.z + v0.w*v0.w
             + v1.x*v1.x + v1.y*v1.y + v1.z*v1.z + v1.w*v1.w;
    #pragma unroll
    for (int o = 16; o > 0; o >>= 1) {
        s  += __shfl_xor_sync(~0u, s, o);
        s2 += __shfl_xor_sync(~0u, s2, o);
    }
    float mean = s * (1.f / Dd);
    float var  = s2 * (1.f / Dd) - mean * mean;
    float inv  = rsqrtf(var + EPSLN);

    float4 g0 = ((const float4*)g)[lane],  g1 = ((const float4*)g)[lane + 32];
    float4 b0 = ((const float4*)be)[lane], b1 = ((const float4*)be)[lane + 32];
    float4* x4 = (float4*)(xm + (size_t)row * Dd);
    float4 r0 = x4[lane], r1 = x4[lane + 32];
    r0.x += (v0.x - mean) * inv * g0.x + b0.x;
    r0.y += (v0.y - mean) * inv * g0.y + b0.y;
    r0.z += (v0.z - mean) * inv * g0.z + b0.z;
    r0.w += (v0.w - mean) * inv * g0.w + b0.w;
    r1.x += (v1.x - mean) * inv * g1.x + b1.x;
    r1.y += (v1.y - mean) * inv * g1.y + b1.y;
    r1.z += (v1.z - mean) * inv * g1.z + b1.z;
    r1.w += (v1.w - mean) * inv * g1.w + b1.w;
    x4[lane] = r0; x4[lane + 32] = r1;

    uint2 h, l;
    size_t e0 = (size_t)row * Dd + lane * 4;
    size_t e1 = e0 + 128;
    split_f4h(r0, h, l);
    *(uint2*)(xh + e0) = h; *(uint2*)(xl + e0) = l;
    split_f4h(r1, h, l);
    *(uint2*)(xh + e1) = h; *(uint2*)(xl + e1) = l;
}

// ================= final LN =================
__global__ void ln_final_kernel(const float* __restrict__ A, const float* __restrict__ g,
                                const float* __restrict__ be, float* __restrict__ out) {
    int row = blockIdx.x * 8 + (threadIdx.x >> 5);
    int lane = threadIdx.x & 31;
    const float4* a4 = (const float4*)(A + (size_t)row * Dd);
    float4 v0 = a4[lane], v1 = a4[lane + 32];
    float s  = v0.x + v0.y + v0.z + v0.w + v1.x + v1.y + v1.z + v1.w;
    float s2 = v0.x*v0.x + v0.y*v0.y + v0.z*v0.z + v0.w*v0.w
             + v1.x*v1.x + v1.y*v1.y + v1.z*v1.z + v1.w*v1.w;
    #pragma unroll
    for (int o = 16; o > 0; o >>= 1) {
        s  += __shfl_xor_sync(~0u, s, o);
        s2 += __shfl_xor_sync(~0u, s2, o);
    }
    float mean = s * (1.f / Dd);
    float var  = s2 * (1.f / Dd) - mean * mean;
    float inv  = rsqrtf(var + EPSLN);
    float4 g0 = ((const float4*)g)[lane],  g1 = ((const float4*)g)[lane + 32];
    float4 b0 = ((const float4*)be)[lane], b1 = ((const float4*)be)[lane + 32];
    float4 o0, o1;
    o0.x = (v0.x - mean) * inv * g0.x + b0.x;
    o0.y = (v0.y - mean) * inv * g0.y + b0.y;
    o0.z = (v0.z - mean) * inv * g0.z + b0.z;
    o0.w = (v0.w - mean) * inv * g0.w + b0.w;
    o1.x = (v1.x - mean) * inv * g1.x + b1.x;
    o1.y = (v1.y - mean) * inv * g1.y + b1.y;
    o1.z = (v1.z - mean) * inv * g1.z + b1.z;
    o1.w = (v1.w - mean) * inv * g1.w + b1.w;
    float4* out4 = (float4*)(out + (size_t)row * Dd);
    out4[lane] = o0; out4[lane + 32] = o1;
}

// ================= launch =================
extern "C" void kernel_launch(void* const* d_in, const int* in_sizes, int n_in,
                              void* d_out, int out_size) {
    const float* x    = (const float*)d_in[0];
    const float* spe  = (const float*)d_in[1];
    const float* qkvw = (const float*)d_in[2];
    const float* tau  = (const float*)d_in[3];
    const float* cw1  = (const float*)d_in[4];
    const float* cb1  = (const float*)d_in[5];
    const float* cw2  = (const float*)d_in[6];
    const float* cb2  = (const float*)d_in[7];
    const float* ow   = (const float*)d_in[8];
    const float* ob   = (const float*)d_in[9];
    const float* ln1g = (const float*)d_in[10];
    const float* ln1b = (const float*)d_in[11];
    const float* fw1  = (const float*)d_in[12];
    const float* fb1  = (const float*)d_in[13];
    const float* fw2  = (const float*)d_in[14];
    const float* fb2  = (const float*)d_in[15];
    const float* ln2g = (const float*)d_in[16];
    const float* ln2b = (const float*)d_in[17];
    const float* ng   = (const float*)d_in[18];
    const float* nb   = (const float*)d_in[19];
    float* out = (float*)d_out;

    float *xm, *qkv, *tmp, *cpb;
    __half *xmh, *xml, *ath, *atl, *ffh, *ffl, *wth;
    cudaGetSymbolAddress((void**)&xm,  g_xm);
    cudaGetSymbolAddress((void**)&qkv, g_qkv);
    cudaGetSymbolAddress((void**)&tmp, g_tmp);
    cudaGetSymbolAddress((void**)&cpb, g_cpb);
    cudaGetSymbolAddress((void**)&xmh, g_xmh);
    cudaGetSymbolAddress((void**)&xml, g_xml);
    cudaGetSymbolAddress((void**)&ath, g_ath);
    cudaGetSymbolAddress((void**)&atl, g_atl);
    cudaGetSymbolAddress((void**)&ffh, g_ffh);
    cudaGetSymbolAddress((void**)&ffl, g_ffl);
    cudaGetSymbolAddress((void**)&wth, g_wth);

    cudaFuncSetAttribute(hgemm_persist_kernel<0, false, 0>, cudaFuncAttributeMaxDynamicSharedMemorySize, PGEMM_SMEM);
    cudaFuncSetAttribute(hgemm_persist_kernel<0, true,  0>, cudaFuncAttributeMaxDynamicSharedMemorySize, PGEMM_SMEM);
    cudaFuncSetAttribute(hgemm_persist_kernel<1, false, 1>, cudaFuncAttributeMaxDynamicSharedMemorySize, PGEMM_SMEM);
    cudaFuncSetAttribute(hgemm_kernel<0, 0>, cudaFuncAttributeMaxDynamicSharedMemorySize, GEMM_SMEM);

    // weight transpose + fp16 round, both layers batched via z
    wtconv_kernel<<<dim3(24, 8, 2), dim3(32, 8)>>>(qkvw, wth,          256, 768,
                                                   (size_t)Dd * 768, WLSTRIDE);
    wtconv_kernel<<<dim3(8,  8, 2), dim3(32, 8)>>>(ow,   wth + 196608, 256, 256,
                                                   (size_t)Dd * Dd,  WLSTRIDE);
    wtconv_kernel<<<dim3(32, 8, 2), dim3(32, 8)>>>(fw1,  wth + 262144, 256, 1024,
                                                   (size_t)Dd * FF,  WLSTRIDE);
    wtconv_kernel<<<dim3(8, 32, 2), dim3(32, 8)>>>(fw2,  wth + 524288, 1024, 256,
                                                   (size_t)FF * Dd,  WLSTRIDE);

    // xm = x + spe (+ fp16 split)
    {
        int n4 = MROWS * Dd / 4;
        add_spe_kernel<<<(n4 + 255) / 256, 256>>>(x, spe, xm, xmh, xml, n4);
    }

    const int lnBlocks = MROWS / 8;
    for (int layer = 0; layer < 2; layer++) {
        int shifted = (layer == 1);
        size_t wo = (size_t)layer * WLSTRIDE;

        cpb_kernel<<<WIN2 * WIN2, 256>>>(cw1 + layer * 2 * CPBH, cb1 + layer * CPBH,
                                         cw2 + layer * CPBH * HEADS, cb2 + layer * HEADS, cpb);

        // qkv = (rolled) xm @ qkv_w -> fp32   (persistent, 6 x 24 = 144 CTAs)
        if (shifted)
            hgemm_persist_kernel<0, true, 0><<<dim3(6, 24), 256, PGEMM_SMEM>>>(
                xmh, xml, wth + wo, nullptr, qkv, nullptr, nullptr, 768, 24);
        else
            hgemm_persist_kernel<0, false, 0><<<dim3(6, 24), 256, PGEMM_SMEM>>>(
                xmh, xml, wth + wo, nullptr, qkv, nullptr, nullptr, 768, 24);

        attn_kernel<<<dim3(NW, HEADS, Bb), 256>>>(qkv, tau + layer * HEADS, cpb, ath, atl, shifted);

        // o-proj -> tmp (fp32)   (persistent, 2 x 74 = 148 CTAs)
        hgemm_persist_kernel<0, false, 0><<<dim3(2, 74), 256, PGEMM_SMEM>>>(
            ath, atl, wth + wo + 196608, ob + layer * Dd,
            tmp, nullptr, nullptr, 256, 74);

        // xm += LN(oproj) (rolled back if shifted)
        ln_residual_kernel<<<lnBlocks, 256>>>(tmp, ln1g + layer * Dd, ln1b + layer * Dd,
                                              xm, xmh, xml, shifted);

        // ffn1: gelu(xm @ fw1 + fb1) -> fp16 hi/lo   (persistent, 8 x 18 = 144 CTAs)
        hgemm_persist_kernel<1, false, 1><<<dim3(8, 18), 256, PGEMM_SMEM>>>(
            xmh, xml, wth + wo + 262144, fb1 + layer * FF,
            nullptr, ffh, ffl, 1024, 18);

        // ffn2 -> tmp (fp32)   (streaming, K=1024)
        hgemm_kernel<0, 0><<<dim3(2, MROWS / 256), 256, GEMM_SMEM>>>(
            ffh, ffl, wth + wo + 524288, fb2 + layer * Dd,
            tmp, nullptr, nullptr, 256, 1024);

        // xm += LN(ffn2)
        ln_residual_kernel<<<lnBlocks, 256>>>(tmp, ln2g + layer * Dd, ln2b + layer * Dd,
                                              xm, xmh, xml, 0);
    }

    ln_final_kernel<<<MROWS / 8, 256>>>(xm, ng, nb, out);
}

// round 10
// speedup vs baseline: 1.7786x; 1.3785x over previous
#include <cuda_runtime.h>
#include <cuda_fp16.h>
#include <cstdint>
#include <math.h>

#define Bb     16
#define Hh     56
#define Wd     56
#define Nn     3136
#define Dd     256
#define HEADS  8
#define HD     32
#define WIN    7
#define WIN2   49
#define NWH    8
#define NW     64
#define DISP   3
#define FF     1024
#define CPBH   512
#define EPSLN  1e-5f
#define MROWS  50176   // B * N
#define MTILES 196     // MROWS / 256

// ================= PTX helpers =================
__device__ __forceinline__ uint32_t smem_to_u32(const void* p) {
    uint32_t a;
    asm("{ .reg .u64 t; cvta.to.shared.u64 t, %1; cvt.u32.u64 %0, t; }" : "=r"(a) : "l"(p));
    return a;
}
#define CP_ASYNC_CG(dst, src) \
    asm volatile("cp.async.cg.shared.global [%0], [%1], 16;" :: "r"(dst), "l"(src))
#define CP_ASYNC_COMMIT() asm volatile("cp.async.commit_group;" ::: "memory")
#define CP_ASYNC_WAIT(n)  asm volatile("cp.async.wait_group %0;" :: "n"(n) : "memory")

__device__ __forceinline__ void ldsm_x4(uint32_t* r, uint32_t addr) {
    asm volatile("ldmatrix.sync.aligned.m8n8.x4.shared.b16 {%0,%1,%2,%3}, [%4];"
        : "=r"(r[0]), "=r"(r[1]), "=r"(r[2]), "=r"(r[3]) : "r"(addr));
}
__device__ __forceinline__ void mma_f16(float* c, const uint32_t* a, const uint32_t* b) {
    asm volatile("mma.sync.aligned.m16n8k16.row.col.f32.f16.f16.f32 "
        "{%0,%1,%2,%3},{%4,%5,%6,%7},{%8,%9},{%0,%1,%2,%3};"
        : "+f"(c[0]), "+f"(c[1]), "+f"(c[2]), "+f"(c[3])
        : "r"(a[0]), "r"(a[1]), "r"(a[2]), "r"(a[3]), "r"(b[0]), "r"(b[1]));
}

// ================= device scratch =================
__device__ float  g_xm  [MROWS * Dd];
__device__ __half g_xmh [MROWS * Dd];
__device__ __half g_qkv [MROWS * 3 * Dd];
__device__ __half g_ath [MROWS * Dd];
__device__ __half g_ffh [MROWS * FF];
__device__ float  g_tmp [MROWS * Dd];
__device__ float  g_cpb [HEADS * WIN2 * WIN2];
// transposed fp16 weights, per layer:
// [0) qkvT 768x256 | 196608) owT 256x256 | 262144) fw1T 1024x256 | 524288) fw2T 256x1024
#define WLSTRIDE 786432
__device__ __half g_wth [2 * WLSTRIDE];

// ================= small helpers =================
__device__ __forceinline__ uint32_t pack_h2(float a, float b) {
    __half2 h = __floats2half2_rn(a, b);
    return *(uint32_t*)&h;
}

// ================= add SPE =================
__global__ void add_spe_kernel(const float* __restrict__ x, const float* __restrict__ spe,
                               float* __restrict__ xm, __half* __restrict__ xh, int n4) {
    int i = blockIdx.x * blockDim.x + threadIdx.x;
    if (i < n4) {
        float4 a = ((const float4*)x)[i];
        float4 b = ((const float4*)spe)[i];
        a.x += b.x; a.y += b.y; a.z += b.z; a.w += b.w;
        ((float4*)xm)[i] = a;
        uint2 h;
        h.x = pack_h2(a.x, a.y);
        h.y = pack_h2(a.z, a.w);
        ((uint2*)xh)[i] = h;
    }
}

// ================= weight transpose + fp16 round: W[K,N] -> T[N,K], z = layer =================
__global__ void wtconv_kernel(const float* __restrict__ W, __half* __restrict__ Th,
                              int K, int N, size_t wstride, size_t tstride) {
    W  += (size_t)blockIdx.z * wstride;
    Th += (size_t)blockIdx.z * tstride;
    __shared__ float t[32][33];
    int bn = blockIdx.x * 32, bk = blockIdx.y * 32;
    int tx = threadIdx.x, ty = threadIdx.y;
    #pragma unroll
    for (int j = 0; j < 32; j += 8)
        t[ty + j][tx] = W[(size_t)(bk + ty + j) * N + bn + tx];
    __syncthreads();
    #pragma unroll
    for (int j = 0; j < 32; j += 8) {
        Th[(size_t)(bn + ty + j) * K + bk + tx] = __float2half_rn(t[tx][ty + j]);
    }
}

// ================= CPB MLP =================
__global__ void cpb_kernel(const float* __restrict__ cw1, const float* __restrict__ cb1,
                           const float* __restrict__ cw2, const float* __restrict__ cb2,
                           float* __restrict__ cpb) {
    int p = blockIdx.x;
    int i = p / WIN2, j = p % WIN2;
    float dy = (float)(j / WIN - i / WIN);
    float dx = (float)(j % WIN - i % WIN);
    float r0 = ((dy > 0.f) - (dy < 0.f)) * log1pf(fabsf(dy));
    float r1 = ((dx > 0.f) - (dx < 0.f)) * log1pf(fabsf(dx));
    int tid = threadIdx.x;
    int c0 = tid, c1 = tid + 256;
    float h0 = fmaxf(r0 * cw1[c0] + r1 * cw1[CPBH + c0] + cb1[c0], 0.f);
    float h1 = fmaxf(r0 * cw1[c1] + r1 * cw1[CPBH + c1] + cb1[c1], 0.f);
    __shared__ float red[256];
    for (int h = 0; h < HEADS; h++) {
        red[tid] = h0 * cw2[c0 * HEADS + h] + h1 * cw2[c1 * HEADS + h];
        __syncthreads();
        for (int s = 128; s > 0; s >>= 1) {
            if (tid < s) red[tid] += red[tid + s];
            __syncthreads();
        }
        if (tid == 0) cpb[h * (WIN2 * WIN2) + p] = red[0] + cb2[h];
        __syncthreads();
    }
}

// ================= shared epilogue =================
// OUTMODE 0: fp32 Cf; 1: fp16 Ch
template<int ACT, int OUTMODE>
__device__ __forceinline__ void gemm_epilogue(
    float acc[4][8][4], int bm, int bn, int warpM, int warpN, int lane,
    const float* __restrict__ bias, float* __restrict__ Cf,
    __half* __restrict__ Ch, int Ntot) {
    const int g = lane >> 2, q = lane & 3;
    #pragma unroll
    for (int m = 0; m < 4; m++) {
        #pragma unroll
        for (int n = 0; n < 8; n++) {
            int col = bn + warpN * 64 + n * 8 + 2 * q;
            float b0 = bias ? bias[col] : 0.f;
            float b1 = bias ? bias[col + 1] : 0.f;
            #pragma unroll
            for (int hrow = 0; hrow < 2; hrow++) {
                int row = bm + warpM * 64 + m * 16 + g + hrow * 8;
                float v0 = acc[m][n][hrow * 2 + 0] + b0;
                float v1 = acc[m][n][hrow * 2 + 1] + b1;
                if (ACT == 1) {
                    v0 = v0 * 0.5f * (1.f + erff(v0 * 0.7071067811865476f));
                    v1 = v1 * 0.5f * (1.f + erff(v1 * 0.7071067811865476f));
                }
                if (OUTMODE == 0) {
                    *(float2*)(Cf + (size_t)row * Ntot + col) = make_float2(v0, v1);
                } else {
                    *(uint32_t*)(Ch + (size_t)row * Ntot + col) = pack_h2(v0, v1);
                }
            }
        }
    }
}

// ================= persistent-B HMMA GEMM, K = 256 fixed, pure fp16 =================
#define SAS      40                          // A chunk row stride (elems), 80B
#define PA_STAGE 20480                       // A stage (hi only)
#define PSTAGES  4
#define PB_STRIDE 264
#define PB_BYTES (128 * PB_STRIDE * 2)       // 67584
#define PGEMM_SMEM (PB_BYTES + PSTAGES * PA_STAGE)  // 149504

template<int ACT, bool GATHER, int OUTMODE>
__global__ void __launch_bounds__(256, 1)
hgemm_persist_kernel(const __half* __restrict__ Ah, const __half* __restrict__ Bth,
                     const float* __restrict__ bias, float* __restrict__ Cf,
                     __half* __restrict__ Ch, int Ntot, int G) {
    extern __shared__ char smem_raw[];
    const uint32_t sB = smem_to_u32(smem_raw);
    const uint32_t sA = sB + PB_BYTES;
    const int tid  = threadIdx.x;
    const int lane = tid & 31, wid = tid >> 5;
    const int warpM = wid >> 1, warpN = wid & 1;
    const int bn = blockIdx.x * 128;
    const int g  = blockIdx.y;

    // ---- load B panel once ----
    #pragma unroll
    for (int it = 0; it < 16; it++) {
        int idx = tid + it * 256;
        int n = idx >> 5, q = idx & 31;
        CP_ASYNC_CG(sB + (uint32_t)(n * (PB_STRIDE * 2) + q * 16),
                    Bth + (size_t)(bn + n) * 256 + q * 8);
    }
    CP_ASYNC_COMMIT();

    int arow_s[4], acol_s[4];
    uint32_t aoff[4];
    #pragma unroll
    for (int l = 0; l < 4; l++) {
        int c = tid + l * 256;
        int r = c >> 2, q = c & 3;
        arow_s[l] = r; acol_s[l] = q * 8;
        aoff[l] = (uint32_t)(r * (SAS * 2) + q * 16);
    }

    const int ntl = (MTILES - 1 - g) / G + 1;
    const int total_cc = ntl * 8;

    auto issue = [&](int cc) {
        int tile = cc >> 3, c = cc & 7;
        int bm = (g + tile * G) * 256;
        uint32_t stg = sA + (uint32_t)(cc & 3) * PA_STAGE;
        int kt = c << 5;
        #pragma unroll
        for (int l = 0; l < 4; l++) {
            int gm = bm + arow_s[l];
            if (GATHER) {
                int b = gm / Nn, rem = gm - b * Nn;
                int h = rem / Wd, w = rem - h * Wd;
                h = (h + DISP) % Hh; w = (w + DISP) % Wd;
                gm = b * Nn + h * Wd + w;
            }
            CP_ASYNC_CG(stg + aoff[l], Ah + (size_t)gm * 256 + kt + acol_s[l]);
        }
    };

    float acc[4][8][4];
    #pragma unroll
    for (int m = 0; m < 4; m++)
        #pragma unroll
        for (int n = 0; n < 8; n++)
            #pragma unroll
            for (int e = 0; e < 4; e++) acc[m][n][e] = 0.f;

    const int arow  = (lane & 15);
    const int ahalf = (lane >> 4);
    const int bidx  = lane & 7;
    const int bkh   = (lane >> 3) & 1;
    const int bsub  = lane >> 4;

    issue(0); CP_ASYNC_COMMIT();
    if (total_cc > 1) issue(1);
    CP_ASYNC_COMMIT();
    if (total_cc > 2) issue(2);
    CP_ASYNC_COMMIT();

    for (int cc = 0; cc < total_cc; cc++) {
        CP_ASYNC_WAIT(2);
        __syncthreads();
        if (cc + 3 < total_cc) issue(cc + 3);
        CP_ASYNC_COMMIT();

        uint32_t stg = sA + (uint32_t)(cc & 3) * PA_STAGE;
        const int c = cc & 7;
        #pragma unroll
        for (int ks = 0; ks < 2; ks++) {
            const int kg = c * 2 + ks;
            uint32_t ah[4][4], bh[8][2];
            #pragma unroll
            for (int m = 0; m < 4; m++) {
                uint32_t off = (uint32_t)((warpM * 64 + m * 16 + arow) * (SAS * 2)
                                          + (ks * 16 + ahalf * 8) * 2);
                ldsm_x4(ah[m], stg + off);
            }
            #pragma unroll
            for (int pr = 0; pr < 4; pr++) {
                uint32_t off = (uint32_t)((warpN * 64 + pr * 16 + bsub * 8 + bidx) * (PB_STRIDE * 2)
                                          + (kg * 16 + bkh * 8) * 2);
                uint32_t t[4];
                ldsm_x4(t, sB + off);
                bh[pr * 2][0] = t[0]; bh[pr * 2][1] = t[1];
                bh[pr * 2 + 1][0] = t[2]; bh[pr * 2 + 1][1] = t[3];
            }
            #pragma unroll
            for (int m = 0; m < 4; m++)
                #pragma unroll
                for (int n = 0; n < 8; n++) mma_f16(acc[m][n], ah[m], bh[n]);
        }

        if (c == 7) {
            int bm = (g + (cc >> 3) * G) * 256;
            gemm_epilogue<ACT, OUTMODE>(acc, bm, bn, warpM, warpN, lane,
                                        bias, Cf, Ch, Ntot);
            #pragma unroll
            for (int m = 0; m < 4; m++)
                #pragma unroll
                for (int n = 0; n < 8; n++)
                    #pragma unroll
                    for (int e = 0; e < 4; e++) acc[m][n][e] = 0.f;
        }
    }
}

// ================= streaming HMMA GEMM (K=1024 ffn2), pure fp16 =================
#define AH_OFF   0
#define BH_OFF   20480
#define STAGE_B  30720
#define GEMM_SMEM (4 * STAGE_B)              // 122880

template<int ACT, int OUTMODE>
__global__ void __launch_bounds__(256, 1)
hgemm_kernel(const __half* __restrict__ Ah, const __half* __restrict__ Bth,
             const float* __restrict__ bias, float* __restrict__ Cf,
             __half* __restrict__ Ch, int Ntot, int K) {
    extern __shared__ char smem_raw[];
    const uint32_t sbase = smem_to_u32(smem_raw);
    const int tid  = threadIdx.x;
    const int lane = tid & 31, wid = tid >> 5;
    const int warpM = wid >> 1, warpN = wid & 1;
    const int bm = blockIdx.y * 256, bn = blockIdx.x * 128;

    const __half *pAh[4], *pBh[2];
    uint32_t aoff[4], boff[2];
    #pragma unroll
    for (int l = 0; l < 4; l++) {
        int c = tid + l * 256;
        int r = c >> 2, q = c & 3;
        pAh[l] = Ah + (size_t)(bm + r) * K + q * 8;
        aoff[l] = (uint32_t)(r * (SAS * 2) + q * 16);
    }
    #pragma unroll
    for (int l = 0; l < 2; l++) {
        int c = tid + l * 256;
        int r = c >> 2, q = c & 3;
        pBh[l] = Bth + (size_t)(bn + r) * K + q * 8;
        boff[l] = (uint32_t)(r * (SAS * 2) + q * 16);
    }

    float acc[4][8][4];
    #pragma unroll
    for (int m = 0; m < 4; m++)
        #pragma unroll
        for (int n = 0; n < 8; n++)
            #pragma unroll
            for (int e = 0; e < 4; e++) acc[m][n][e] = 0.f;

    const int nch = K >> 5;

    auto load_stage = [&](int c) {
        uint32_t stg = sbase + (uint32_t)(c & 3) * STAGE_B;
        int kt = c << 5;
        #pragma unroll
        for (int l = 0; l < 4; l++)
            CP_ASYNC_CG(stg + AH_OFF + aoff[l], pAh[l] + kt);
        #pragma unroll
        for (int l = 0; l < 2; l++)
            CP_ASYNC_CG(stg + BH_OFF + boff[l], pBh[l] + kt);
    };

    const int arow  = (lane & 15);
    const int ahalf = (lane >> 4);
    const int bidx  = lane & 7;
    const int bkh   = (lane >> 3) & 1;
    const int bsub  = lane >> 4;

    load_stage(0); CP_ASYNC_COMMIT();
    if (nch > 1) load_stage(1);
    CP_ASYNC_COMMIT();
    if (nch > 2) load_stage(2);
    CP_ASYNC_COMMIT();

    for (int c = 0; c < nch; c++) {
        CP_ASYNC_WAIT(2);
        __syncthreads();
        if (c + 3 < nch) load_stage(c + 3);
        CP_ASYNC_COMMIT();

        uint32_t stg = sbase + (uint32_t)(c & 3) * STAGE_B;
        #pragma unroll
        for (int ks = 0; ks < 2; ks++) {
            uint32_t ah[4][4], bh[8][2];
            #pragma unroll
            for (int m = 0; m < 4; m++) {
                uint32_t off = (uint32_t)((warpM * 64 + m * 16 + arow) * (SAS * 2)
                                          + (ks * 16 + ahalf * 8) * 2);
                ldsm_x4(ah[m], stg + AH_OFF + off);
            }
            #pragma unroll
            for (int pr = 0; pr < 4; pr++) {
                uint32_t off = (uint32_t)((warpN * 64 + pr * 16 + bsub * 8 + bidx) * (SAS * 2)
                                          + (ks * 16 + bkh * 8) * 2);
                uint32_t t[4];
                ldsm_x4(t, stg + BH_OFF + off);
                bh[pr * 2][0] = t[0]; bh[pr * 2][1] = t[1];
                bh[pr * 2 + 1][0] = t[2]; bh[pr * 2 + 1][1] = t[3];
            }
            #pragma unroll
            for (int m = 0; m < 4; m++)
                #pragma unroll
                for (int n = 0; n < 8; n++) mma_f16(acc[m][n], ah[m], bh[n]);
        }
    }

    gemm_epilogue<ACT, OUTMODE>(acc, bm, bn, warpM, warpN, lane, bias, Cf, Ch, Ntot);
}

// ================= window attention (reads fp16 qkv, emits fp16) =================
#define QS 34
#define DS 52
__global__ void __launch_bounds__(256)
attn_kernel(const __half* __restrict__ qkv, const float* __restrict__ tau,
            const float* __restrict__ cpb, __half* __restrict__ outh, int shifted) {
    __shared__ float sq[64 * QS];
    __shared__ float sk[64 * QS];
    __shared__ float sv[49 * QS];
    __shared__ float sd[64 * DS];

    const int wi   = blockIdx.x;
    const int head = blockIdx.y;
    const int b    = blockIdx.z;
    const int wh = wi >> 3, ww = wi & 7;
    const int tid = threadIdx.x;

    for (int e = tid; e < 64 * 32; e += 256) {
        int r = e >> 5, d = e & 31;
        if (r < WIN2) {
            int i = r / WIN, j = r % WIN;
            int m = b * Nn + (wh * WIN + i) * Wd + (ww * WIN + j);
            const __half* base = qkv + (size_t)m * 768 + head * HD + d;
            sq[r * QS + d] = __half2float(base[0]);
            sk[r * QS + d] = __half2float(base[256]);
            sv[r * QS + d] = __half2float(base[512]);
        } else {
            sq[r * QS + d] = 0.f;
            sk[r * QS + d] = 0.f;
        }
    }
    __syncthreads();

    for (int t = tid; t < 2 * WIN2; t += 256) {
        float* row = (t < WIN2) ? (sq + t * QS) : (sk + (t - WIN2) * QS);
        float s = 0.f;
        #pragma unroll
        for (int d = 0; d < HD; d += 2) {
            float2 v = *(float2*)(row + d);
            s += v.x * v.x + v.y * v.y;
        }
        float inv = 1.f / fmaxf(sqrtf(s), 1e-12f);
        #pragma unroll
        for (int d = 0; d < HD; d += 2) {
            float2 v = *(float2*)(row + d);
            v.x *= inv; v.y *= inv;
            *(float2*)(row + d) = v;
        }
    }
    __syncthreads();

    const float tscale = 1.f / fmaxf(tau[head], 0.01f);
    const int tx = tid & 15, ty = tid >> 4;

    float acc[4][4];
    #pragma unroll
    for (int u = 0; u < 4; u++)
        #pragma unroll
        for (int v = 0; v < 4; v++) acc[u][v] = 0.f;
    #pragma unroll
    for (int kk = 0; kk < HD; kk += 2) {
        float2 a2[4], b2[4];
        #pragma unroll
        for (int u = 0; u < 4; u++) a2[u] = *(float2*)&sq[(ty + u * 16) * QS + kk];
        #pragma unroll
        for (int v = 0; v < 4; v++) b2[v] = *(float2*)&sk[(tx + v * 16) * QS + kk];
        #pragma unroll
        for (int u = 0; u < 4; u++)
            #pragma unroll
            for (int v = 0; v < 4; v++)
                acc[u][v] += a2[u].x * b2[v].x + a2[u].y * b2[v].y;
    }
    #pragma unroll
    for (int u = 0; u < 4; u++) {
        int i = ty + u * 16;
        if (i >= WIN2) continue;
        #pragma unroll
        for (int v = 0; v < 4; v++) {
            int j = tx + v * 16;
            if (j >= WIN2) continue;
            float val = acc[u][v] * tscale + cpb[head * (WIN2 * WIN2) + i * WIN2 + j];
            if (shifted) {
                if (wh == NWH - 1 && ((i >= 28) != (j >= 28))) val = -1e30f;
                if (ww == NWH - 1 && (((i % WIN) >= 4) != ((j % WIN) >= 4))) val = -1e30f;
            }
            sd[i * DS + j] = val;
        }
    }
    __syncthreads();

    const int lane = tid & 31, wrp = tid >> 5;
    for (int r = wrp; r < WIN2; r += 8) {
        float v0 = sd[r * DS + lane];
        float v1 = (lane + 32 < WIN2) ? sd[r * DS + lane + 32] : -3e38f;
        float mx = fmaxf(v0, v1);
        #pragma unroll
        for (int o = 16; o > 0; o >>= 1) mx = fmaxf(mx, __shfl_xor_sync(~0u, mx, o));
        float e0 = __expf(v0 - mx);
        float e1 = (lane + 32 < WIN2) ? __expf(v1 - mx) : 0.f;
        float s = e0 + e1;
        #pragma unroll
        for (int o = 16; o > 0; o >>= 1) s += __shfl_xor_sync(~0u, s, o);
        float inv = 1.f / s;
        sd[r * DS + lane] = e0 * inv;
        if (lane + 32 < WIN2) sd[r * DS + lane + 32] = e1 * inv;
    }
    __syncthreads();

    float o2[4][2];
    #pragma unroll
    for (int u = 0; u < 4; u++) { o2[u][0] = 0.f; o2[u][1] = 0.f; }
    for (int j = 0; j < 48; j += 2) {
        float2 p2[4];
        #pragma unroll
        for (int u = 0; u < 4; u++) p2[u] = *(float2*)&sd[(ty + u * 16) * DS + j];
        float2 va = *(float2*)&sv[j * QS + tx * 2];
        float2 vb = *(float2*)&sv[(j + 1) * QS + tx * 2];
        #pragma unroll
        for (int u = 0; u < 4; u++) {
            o2[u][0] += p2[u].x * va.x + p2[u].y * vb.x;
            o2[u][1] += p2[u].x * va.y + p2[u].y * vb.y;
        }
    }
    {
        float2 vc = *(float2*)&sv[48 * QS + tx * 2];
        #pragma unroll
        for (int u = 0; u < 4; u++) {
            float p = sd[(ty + u * 16) * DS + 48];
            o2[u][0] += p * vc.x;
            o2[u][1] += p * vc.y;
        }
    }
    #pragma unroll
    for (int u = 0; u < 4; u++) {
        int i = ty + u * 16;
        if (i < WIN2) {
            int ii = i / WIN, jj = i % WIN;
            int m = b * Nn + (wh * WIN + ii) * Wd + (ww * WIN + jj);
            size_t off = (size_t)m * Dd + head * HD + tx * 2;
            *(uint32_t*)(outh + off) = pack_h2(o2[u][0], o2[u][1]);
        }
    }
}

// ================= LN + residual =================
__global__ void ln_residual_kernel(const float* __restrict__ A, const float* __restrict__ g,
                                   const float* __restrict__ be, float* __restrict__ xm,
                                   __half* __restrict__ xh, int gather) {
    int row = blockIdx.x * 8 + (threadIdx.x >> 5);
    int lane = threadIdx.x & 31;
    int src = row;
    if (gather) {
        int b = row / Nn, rem = row % Nn;
        int h = rem / Wd, w = rem % Wd;
        src = b * Nn + ((h + Hh - DISP) % Hh) * Wd + ((w + Wd - DISP) % Wd);
    }
    const float4* a4 = (const float4*)(A + (size_t)src * Dd);
    float4 v0 = a4[lane], v1 = a4[lane + 32];
    float s  = v0.x + v0.y + v0.z + v0.w + v1.x + v1.y + v1.z + v1.w;
    float s2 = v0.x*v0.x + v0.y*v0.y + v0.z*v0.z + v0.w*v0.w
             + v1.x*v1.x + v1.y*v1.y + v1.z*v1.z + v1.w*v1.w;
    #pragma unroll
    for (int o = 16; o > 0; o >>= 1) {
        s  += __shfl_xor_sync(~0u, s, o);
        s2 += __shfl_xor_sync(~0u, s2, o);
    }
    float mean = s * (1.f / Dd);
    float var  = s2 * (1.f / Dd) - mean * mean;
    float inv  = rsqrtf(var + EPSLN);

    float4 g0 = ((const float4*)g)[lane],  g1 = ((const float4*)g)[lane + 32];
    float4 b0 = ((const float4*)be)[lane], b1 = ((const float4*)be)[lane + 32];
    float4* x4 = (float4*)(xm + (size_t)row * Dd);
    float4 r0 = x4[lane], r1 = x4[lane + 32];
    r0.x += (v0.x - mean) * inv * g0.x + b0.x;
    r0.y += (v0.y - mean) * inv * g0.y + b0.y;
    r0.z += (v0.z - mean) * inv * g0.z + b0.z;
    r0.w += (v0.w - mean) * inv * g0.w + b0.w;
    r1.x += (v1.x - mean) * inv * g1.x + b1.x;
    r1.y += (v1.y - mean) * inv * g1.y + b1.y;
    r1.z += (v1.z - mean) * inv * g1.z + b1.z;
    r1.w += (v1.w - mean) * inv * g1.w + b1.w;
    x4[lane] = r0; x4[lane + 32] = r1;

    size_t e0 = (size_t)row * Dd + lane * 4;
    size_t e1 = e0 + 128;
    uint2 h;
    h.x = pack_h2(r0.x, r0.y); h.y = pack_h2(r0.z, r0.w);
    *(uint2*)(xh + e0) = h;
    h.x = pack_h2(r1.x, r1.y); h.y = pack_h2(r1.z, r1.w);
    *(uint2*)(xh + e1) = h;
}

// ================= final LN =================
__global__ void ln_final_kernel(const float* __restrict__ A, const float* __restrict__ g,
                                const float* __restrict__ be, float* __restrict__ out) {
    int row = blockIdx.x * 8 + (threadIdx.x >> 5);
    int lane = threadIdx.x & 31;
    const float4* a4 = (const float4*)(A + (size_t)row * Dd);
    float4 v0 = a4[lane], v1 = a4[lane + 32];
    float s  = v0.x + v0.y + v0.z + v0.w + v1.x + v1.y + v1.z + v1.w;
    float s2 = v0.x*v0.x + v0.y*v0.y + v0.z*v0.z + v0.w*v0.w
             + v1.x*v1.x + v1.y*v1.y + v1.z*v1.z + v1.w*v1.w;
    #pragma unroll
    for (int o = 16; o > 0; o >>= 1) {
        s  += __shfl_xor_sync(~0u, s, o);
        s2 += __shfl_xor_sync(~0u, s2, o);
    }
    float mean = s * (1.f / Dd);
    float var  = s2 * (1.f / Dd) - mean * mean;
    float inv  = rsqrtf(var + EPSLN);
    float4 g0 = ((const float4*)g)[lane],  g1 = ((const float4*)g)[lane + 32];
    float4 b0 = ((const float4*)be)[lane], b1 = ((const float4*)be)[lane + 32];
    float4 o0, o1;
    o0.x = (v0.x - mean) * inv * g0.x + b0.x;
    o0.y = (v0.y - mean) * inv * g0.y + b0.y;
    o0.z = (v0.z - mean) * inv * g0.z + b0.z;
    o0.w = (v0.w - mean) * inv * g0.w + b0.w;
    o1.x = (v1.x - mean) * inv * g1.x + b1.x;
    o1.y = (v1.y - mean) * inv * g1.y + b1.y;
    o1.z = (v1.z - mean) * inv * g1.z + b1.z;
    o1.w = (v1.w - mean) * inv * g1.w + b1.w;
    float4* out4 = (float4*)(out + (size_t)row * Dd);
    out4[lane] = o0; out4[lane + 32] = o1;
}

// ================= launch =================
extern "C" void kernel_launch(void* const* d_in, const int* in_sizes, int n_in,
                              void* d_out, int out_size) {
    const float* x    = (const float*)d_in[0];
    const float* spe  = (const float*)d_in[1];
    const float* qkvw = (const float*)d_in[2];
    const float* tau  = (const float*)d_in[3];
    const float* cw1  = (const float*)d_in[4];
    const float* cb1  = (const float*)d_in[5];
    const float* cw2  = (const float*)d_in[6];
    const float* cb2  = (const float*)d_in[7];
    const float* ow   = (const float*)d_in[8];
    const float* ob   = (const float*)d_in[9];
    const float* ln1g = (const float*)d_in[10];
    const float* ln1b = (const float*)d_in[11];
    const float* fw1  = (const float*)d_in[12];
    const float* fb1  = (const float*)d_in[13];
    const float* fw2  = (const float*)d_in[14];
    const float* fb2  = (const float*)d_in[15];
    const float* ln2g = (const float*)d_in[16];
    const float* ln2b = (const float*)d_in[17];
    const float* ng   = (const float*)d_in[18];
    const float* nb   = (const float*)d_in[19];
    float* out = (float*)d_out;

    float *xm, *tmp, *cpb;
    __half *xmh, *qkv, *ath, *ffh, *wth;
    cudaGetSymbolAddress((void**)&xm,  g_xm);
    cudaGetSymbolAddress((void**)&tmp, g_tmp);
    cudaGetSymbolAddress((void**)&cpb, g_cpb);
    cudaGetSymbolAddress((void**)&xmh, g_xmh);
    cudaGetSymbolAddress((void**)&qkv, g_qkv);
    cudaGetSymbolAddress((void**)&ath, g_ath);
    cudaGetSymbolAddress((void**)&ffh, g_ffh);
    cudaGetSymbolAddress((void**)&wth, g_wth);

    cudaFuncSetAttribute(hgemm_persist_kernel<0, false, 1>, cudaFuncAttributeMaxDynamicSharedMemorySize, PGEMM_SMEM);
    cudaFuncSetAttribute(hgemm_persist_kernel<0, true,  1>, cudaFuncAttributeMaxDynamicSharedMemorySize, PGEMM_SMEM);
    cudaFuncSetAttribute(hgemm_persist_kernel<0, false, 0>, cudaFuncAttributeMaxDynamicSharedMemorySize, PGEMM_SMEM);
    cudaFuncSetAttribute(hgemm_persist_kernel<1, false, 1>, cudaFuncAttributeMaxDynamicSharedMemorySize, PGEMM_SMEM);
    cudaFuncSetAttribute(hgemm_kernel<0, 0>, cudaFuncAttributeMaxDynamicSharedMemorySize, GEMM_SMEM);

    // weight transpose + fp16 round, both layers batched via z
    wtconv_kernel<<<dim3(24, 8, 2), dim3(32, 8)>>>(qkvw, wth,          256, 768,
                                                   (size_t)Dd * 768, WLSTRIDE);
    wtconv_kernel<<<dim3(8,  8, 2), dim3(32, 8)>>>(ow,   wth + 196608, 256, 256,
                                                   (size_t)Dd * Dd,  WLSTRIDE);
    wtconv_kernel<<<dim3(32, 8, 2), dim3(32, 8)>>>(fw1,  wth + 262144, 256, 1024,
                                                   (size_t)Dd * FF,  WLSTRIDE);
    wtconv_kernel<<<dim3(8, 32, 2), dim3(32, 8)>>>(fw2,  wth + 524288, 1024, 256,
                                                   (size_t)FF * Dd,  WLSTRIDE);

    // xm = x + spe (+ fp16)
    {
        int n4 = MROWS * Dd / 4;
        add_spe_kernel<<<(n4 + 255) / 256, 256>>>(x, spe, xm, xmh, n4);
    }

    const int lnBlocks = MROWS / 8;
    for (int layer = 0; layer < 2; layer++) {
        int shifted = (layer == 1);
        size_t wo = (size_t)layer * WLSTRIDE;

        cpb_kernel<<<WIN2 * WIN2, 256>>>(cw1 + layer * 2 * CPBH, cb1 + layer * CPBH,
                                         cw2 + layer * CPBH * HEADS, cb2 + layer * HEADS, cpb);

        // qkv = (rolled) xm @ qkv_w -> fp16   (persistent, 6 x 24 = 144 CTAs)
        if (shifted)
            hgemm_persist_kernel<0, true, 1><<<dim3(6, 24), 256, PGEMM_SMEM>>>(
                xmh, wth + wo, nullptr, nullptr, qkv, 768, 24);
        else
            hgemm_persist_kernel<0, false, 1><<<dim3(6, 24), 256, PGEMM_SMEM>>>(
                xmh, wth + wo, nullptr, nullptr, qkv, 768, 24);

        attn_kernel<<<dim3(NW, HEADS, Bb), 256>>>(qkv, tau + layer * HEADS, cpb, ath, shifted);

        // o-proj -> tmp (fp32)   (persistent, 2 x 74 = 148 CTAs)
        hgemm_persist_kernel<0, false, 0><<<dim3(2, 74), 256, PGEMM_SMEM>>>(
            ath, wth + wo + 196608, ob + layer * Dd, tmp, nullptr, 256, 74);

        // xm += LN(oproj) (rolled back if shifted)
        ln_residual_kernel<<<lnBlocks, 256>>>(tmp, ln1g + layer * Dd, ln1b + layer * Dd,
                                              xm, xmh, shifted);

        // ffn1: gelu(xm @ fw1 + fb1) -> fp16   (persistent, 8 x 18 = 144 CTAs)
        hgemm_persist_kernel<1, false, 1><<<dim3(8, 18), 256, PGEMM_SMEM>>>(
            xmh, wth + wo + 262144, fb1 + layer * FF, nullptr, ffh, 1024, 18);

        // ffn2 -> tmp (fp32)   (streaming, K=1024)
        hgemm_kernel<0, 0><<<dim3(2, MROWS / 256), 256, GEMM_SMEM>>>(
            ffh, wth + wo + 524288, fb2 + layer * Dd, tmp, nullptr, 256, 1024);

        // xm += LN(ffn2)
        ln_residual_kernel<<<lnBlocks, 256>>>(tmp, ln2g + layer * Dd, ln2b + layer * Dd,
                                              xm, xmh, 0);
    }

    ln_final_kernel<<<MROWS / 8, 256>>>(xm, ng, nb, out);
}

// round 11
// speedup vs baseline: 1.8629x; 1.0474x over previous
#include <cuda_runtime.h>
#include <cuda_fp16.h>
#include <cstdint>
#include <math.h>

#define Bb     16
#define Hh     56
#define Wd     56
#define Nn     3136
#define Dd     256
#define HEADS  8
#define HD     32
#define WIN    7
#define WIN2   49
#define NWH    8
#define NW     64
#define DISP   3
#define FF     1024
#define CPBH   512
#define EPSLN  1e-5f
#define MROWS  50176   // B * N
#define MTILES 196     // MROWS / 256

// ================= PTX helpers =================
__device__ __forceinline__ uint32_t smem_to_u32(const void* p) {
    uint32_t a;
    asm("{ .reg .u64 t; cvta.to.shared.u64 t, %1; cvt.u32.u64 %0, t; }" : "=r"(a) : "l"(p));
    return a;
}
#define CP_ASYNC_CG(dst, src) \
    asm volatile("cp.async.cg.shared.global [%0], [%1], 16;" :: "r"(dst), "l"(src))
#define CP_ASYNC_COMMIT() asm volatile("cp.async.commit_group;" ::: "memory")
#define CP_ASYNC_WAIT(n)  asm volatile("cp.async.wait_group %0;" :: "n"(n) : "memory")

__device__ __forceinline__ void ldsm_x4(uint32_t* r, uint32_t addr) {
    asm volatile("ldmatrix.sync.aligned.m8n8.x4.shared.b16 {%0,%1,%2,%3}, [%4];"
        : "=r"(r[0]), "=r"(r[1]), "=r"(r[2]), "=r"(r[3]) : "r"(addr));
}
__device__ __forceinline__ void mma_f16(float* c, const uint32_t* a, const uint32_t* b) {
    asm volatile("mma.sync.aligned.m16n8k16.row.col.f32.f16.f16.f32 "
        "{%0,%1,%2,%3},{%4,%5,%6,%7},{%8,%9},{%0,%1,%2,%3};"
        : "+f"(c[0]), "+f"(c[1]), "+f"(c[2]), "+f"(c[3])
        : "r"(a[0]), "r"(a[1]), "r"(a[2]), "r"(a[3]), "r"(b[0]), "r"(b[1]));
}

// ================= device scratch =================
__device__ float  g_xm  [MROWS * Dd];
__device__ __half g_xmh [MROWS * Dd];
__device__ __half g_qkv [MROWS * 3 * Dd];
__device__ __half g_ath [MROWS * Dd];
__device__ __half g_ffh [MROWS * FF];
__device__ __half g_tmp [MROWS * Dd];
__device__ float  g_cpb [HEADS * WIN2 * WIN2];
// transposed fp16 weights, per layer:
// [0) qkvT 768x256 | 196608) owT 256x256 | 262144) fw1T 1024x256 | 524288) fw2T 256x1024
#define WLSTRIDE 786432
__device__ __half g_wth [2 * WLSTRIDE];

// ================= small helpers =================
__device__ __forceinline__ uint32_t pack_h2(float a, float b) {
    __half2 h = __floats2half2_rn(a, b);
    return *(uint32_t*)&h;
}

// ================= add SPE =================
__global__ void add_spe_kernel(const float* __restrict__ x, const float* __restrict__ spe,
                               float* __restrict__ xm, __half* __restrict__ xh, int n4) {
    int i = blockIdx.x * blockDim.x + threadIdx.x;
    if (i < n4) {
        float4 a = ((const float4*)x)[i];
        float4 b = ((const float4*)spe)[i];
        a.x += b.x; a.y += b.y; a.z += b.z; a.w += b.w;
        ((float4*)xm)[i] = a;
        uint2 h;
        h.x = pack_h2(a.x, a.y);
        h.y = pack_h2(a.z, a.w);
        ((uint2*)xh)[i] = h;
    }
}

// ================= weight transpose + fp16 round: W[K,N] -> T[N,K], z = layer =================
__global__ void wtconv_kernel(const float* __restrict__ W, __half* __restrict__ Th,
                              int K, int N, size_t wstride, size_t tstride) {
    W  += (size_t)blockIdx.z * wstride;
    Th += (size_t)blockIdx.z * tstride;
    __shared__ float t[32][33];
    int bn = blockIdx.x * 32, bk = blockIdx.y * 32;
    int tx = threadIdx.x, ty = threadIdx.y;
    #pragma unroll
    for (int j = 0; j < 32; j += 8)
        t[ty + j][tx] = W[(size_t)(bk + ty + j) * N + bn + tx];
    __syncthreads();
    #pragma unroll
    for (int j = 0; j < 32; j += 8) {
        Th[(size_t)(bn + ty + j) * K + bk + tx] = __float2half_rn(t[tx][ty + j]);
    }
}

// ================= CPB MLP =================
__global__ void cpb_kernel(const float* __restrict__ cw1, const float* __restrict__ cb1,
                           const float* __restrict__ cw2, const float* __restrict__ cb2,
                           float* __restrict__ cpb) {
    int p = blockIdx.x;
    int i = p / WIN2, j = p % WIN2;
    float dy = (float)(j / WIN - i / WIN);
    float dx = (float)(j % WIN - i % WIN);
    float r0 = ((dy > 0.f) - (dy < 0.f)) * log1pf(fabsf(dy));
    float r1 = ((dx > 0.f) - (dx < 0.f)) * log1pf(fabsf(dx));
    int tid = threadIdx.x;
    int c0 = tid, c1 = tid + 256;
    float h0 = fmaxf(r0 * cw1[c0] + r1 * cw1[CPBH + c0] + cb1[c0], 0.f);
    float h1 = fmaxf(r0 * cw1[c1] + r1 * cw1[CPBH + c1] + cb1[c1], 0.f);
    __shared__ float red[256];
    for (int h = 0; h < HEADS; h++) {
        red[tid] = h0 * cw2[c0 * HEADS + h] + h1 * cw2[c1 * HEADS + h];
        __syncthreads();
        for (int s = 128; s > 0; s >>= 1) {
            if (tid < s) red[tid] += red[tid + s];
            __syncthreads();
        }
        if (tid == 0) cpb[h * (WIN2 * WIN2) + p] = red[0] + cb2[h];
        __syncthreads();
    }
}

// ================= shared epilogue =================
// OUTMODE 0: fp32 Cf; 1: fp16 Ch
template<int ACT, int OUTMODE>
__device__ __forceinline__ void gemm_epilogue(
    float acc[4][8][4], int bm, int bn, int warpM, int warpN, int lane,
    const float* __restrict__ bias, float* __restrict__ Cf,
    __half* __restrict__ Ch, int Ntot) {
    const int g = lane >> 2, q = lane & 3;
    #pragma unroll
    for (int m = 0; m < 4; m++) {
        #pragma unroll
        for (int n = 0; n < 8; n++) {
            int col = bn + warpN * 64 + n * 8 + 2 * q;
            float b0 = bias ? bias[col] : 0.f;
            float b1 = bias ? bias[col + 1] : 0.f;
            #pragma unroll
            for (int hrow = 0; hrow < 2; hrow++) {
                int row = bm + warpM * 64 + m * 16 + g + hrow * 8;
                float v0 = acc[m][n][hrow * 2 + 0] + b0;
                float v1 = acc[m][n][hrow * 2 + 1] + b1;
                if (ACT == 1) {
                    v0 = v0 * 0.5f * (1.f + erff(v0 * 0.7071067811865476f));
                    v1 = v1 * 0.5f * (1.f + erff(v1 * 0.7071067811865476f));
                }
                if (OUTMODE == 0) {
                    *(float2*)(Cf + (size_t)row * Ntot + col) = make_float2(v0, v1);
                } else {
                    *(uint32_t*)(Ch + (size_t)row * Ntot + col) = pack_h2(v0, v1);
                }
            }
        }
    }
}

// ================= persistent-B HMMA GEMM, K = 256 fixed, pure fp16 =================
#define SAS      40
#define PA_STAGE 20480
#define PSTAGES  4
#define PB_STRIDE 264
#define PB_BYTES (128 * PB_STRIDE * 2)
#define PGEMM_SMEM (PB_BYTES + PSTAGES * PA_STAGE)  // 149504

template<int ACT, bool GATHER, int OUTMODE>
__global__ void __launch_bounds__(256, 1)
hgemm_persist_kernel(const __half* __restrict__ Ah, const __half* __restrict__ Bth,
                     const float* __restrict__ bias, float* __restrict__ Cf,
                     __half* __restrict__ Ch, int Ntot, int G) {
    extern __shared__ char smem_raw[];
    const uint32_t sB = smem_to_u32(smem_raw);
    const uint32_t sA = sB + PB_BYTES;
    const int tid  = threadIdx.x;
    const int lane = tid & 31, wid = tid >> 5;
    const int warpM = wid >> 1, warpN = wid & 1;
    const int bn = blockIdx.x * 128;
    const int g  = blockIdx.y;

    #pragma unroll
    for (int it = 0; it < 16; it++) {
        int idx = tid + it * 256;
        int n = idx >> 5, q = idx & 31;
        CP_ASYNC_CG(sB + (uint32_t)(n * (PB_STRIDE * 2) + q * 16),
                    Bth + (size_t)(bn + n) * 256 + q * 8);
    }
    CP_ASYNC_COMMIT();

    int arow_s[4], acol_s[4];
    uint32_t aoff[4];
    #pragma unroll
    for (int l = 0; l < 4; l++) {
        int c = tid + l * 256;
        int r = c >> 2, q = c & 3;
        arow_s[l] = r; acol_s[l] = q * 8;
        aoff[l] = (uint32_t)(r * (SAS * 2) + q * 16);
    }

    const int ntl = (MTILES - 1 - g) / G + 1;
    const int total_cc = ntl * 8;

    auto issue = [&](int cc) {
        int tile = cc >> 3, c = cc & 7;
        int bm = (g + tile * G) * 256;
        uint32_t stg = sA + (uint32_t)(cc & 3) * PA_STAGE;
        int kt = c << 5;
        #pragma unroll
        for (int l = 0; l < 4; l++) {
            int gm = bm + arow_s[l];
            if (GATHER) {
                int b = gm / Nn, rem = gm - b * Nn;
                int h = rem / Wd, w = rem - h * Wd;
                h = (h + DISP) % Hh; w = (w + DISP) % Wd;
                gm = b * Nn + h * Wd + w;
            }
            CP_ASYNC_CG(stg + aoff[l], Ah + (size_t)gm * 256 + kt + acol_s[l]);
        }
    };

    float acc[4][8][4];
    #pragma unroll
    for (int m = 0; m < 4; m++)
        #pragma unroll
        for (int n = 0; n < 8; n++)
            #pragma unroll
            for (int e = 0; e < 4; e++) acc[m][n][e] = 0.f;

    const int arow  = (lane & 15);
    const int ahalf = (lane >> 4);
    const int bidx  = lane & 7;
    const int bkh   = (lane >> 3) & 1;
    const int bsub  = lane >> 4;

    issue(0); CP_ASYNC_COMMIT();
    if (total_cc > 1) issue(1);
    CP_ASYNC_COMMIT();
    if (total_cc > 2) issue(2);
    CP_ASYNC_COMMIT();

    for (int cc = 0; cc < total_cc; cc++) {
        CP_ASYNC_WAIT(2);
        __syncthreads();
        if (cc + 3 < total_cc) issue(cc + 3);
        CP_ASYNC_COMMIT();

        uint32_t stg = sA + (uint32_t)(cc & 3) * PA_STAGE;
        const int c = cc & 7;
        #pragma unroll
        for (int ks = 0; ks < 2; ks++) {
            const int kg = c * 2 + ks;
            uint32_t ah[4][4], bh[8][2];
            #pragma unroll
            for (int m = 0; m < 4; m++) {
                uint32_t off = (uint32_t)((warpM * 64 + m * 16 + arow) * (SAS * 2)
                                          + (ks * 16 + ahalf * 8) * 2);
                ldsm_x4(ah[m], stg + off);
            }
            #pragma unroll
            for (int pr = 0; pr < 4; pr++) {
                uint32_t off = (uint32_t)((warpN * 64 + pr * 16 + bsub * 8 + bidx) * (PB_STRIDE * 2)
                                          + (kg * 16 + bkh * 8) * 2);
                uint32_t t[4];
                ldsm_x4(t, sB + off);
                bh[pr * 2][0] = t[0]; bh[pr * 2][1] = t[1];
                bh[pr * 2 + 1][0] = t[2]; bh[pr * 2 + 1][1] = t[3];
            }
            #pragma unroll
            for (int m = 0; m < 4; m++)
                #pragma unroll
                for (int n = 0; n < 8; n++) mma_f16(acc[m][n], ah[m], bh[n]);
        }

        if (c == 7) {
            int bm = (g + (cc >> 3) * G) * 256;
            gemm_epilogue<ACT, OUTMODE>(acc, bm, bn, warpM, warpN, lane,
                                        bias, Cf, Ch, Ntot);
            #pragma unroll
            for (int m = 0; m < 4; m++)
                #pragma unroll
                for (int n = 0; n < 8; n++)
                    #pragma unroll
                    for (int e = 0; e < 4; e++) acc[m][n][e] = 0.f;
        }
    }
}

// ================= streaming HMMA GEMM (K=1024 ffn2), pure fp16 =================
#define AH_OFF   0
#define BH_OFF   20480
#define STAGE_B  30720
#define GEMM_SMEM (4 * STAGE_B)

template<int ACT, int OUTMODE>
__global__ void __launch_bounds__(256, 1)
hgemm_kernel(const __half* __restrict__ Ah, const __half* __restrict__ Bth,
             const float* __restrict__ bias, float* __restrict__ Cf,
             __half* __restrict__ Ch, int Ntot, int K) {
    extern __shared__ char smem_raw[];
    const uint32_t sbase = smem_to_u32(smem_raw);
    const int tid  = threadIdx.x;
    const int lane = tid & 31, wid = tid >> 5;
    const int warpM = wid >> 1, warpN = wid & 1;
    const int bm = blockIdx.y * 256, bn = blockIdx.x * 128;

    const __half *pAh[4], *pBh[2];
    uint32_t aoff[4], boff[2];
    #pragma unroll
    for (int l = 0; l < 4; l++) {
        int c = tid + l * 256;
        int r = c >> 2, q = c & 3;
        pAh[l] = Ah + (size_t)(bm + r) * K + q * 8;
        aoff[l] = (uint32_t)(r * (SAS * 2) + q * 16);
    }
    #pragma unroll
    for (int l = 0; l < 2; l++) {
        int c = tid + l * 256;
        int r = c >> 2, q = c & 3;
        pBh[l] = Bth + (size_t)(bn + r) * K + q * 8;
        boff[l] = (uint32_t)(r * (SAS * 2) + q * 16);
    }

    float acc[4][8][4];
    #pragma unroll
    for (int m = 0; m < 4; m++)
        #pragma unroll
        for (int n = 0; n < 8; n++)
            #pragma unroll
            for (int e = 0; e < 4; e++) acc[m][n][e] = 0.f;

    const int nch = K >> 5;

    auto load_stage = [&](int c) {
        uint32_t stg = sbase + (uint32_t)(c & 3) * STAGE_B;
        int kt = c << 5;
        #pragma unroll
        for (int l = 0; l < 4; l++)
            CP_ASYNC_CG(stg + AH_OFF + aoff[l], pAh[l] + kt);
        #pragma unroll
        for (int l = 0; l < 2; l++)
            CP_ASYNC_CG(stg + BH_OFF + boff[l], pBh[l] + kt);
    };

    const int arow  = (lane & 15);
    const int ahalf = (lane >> 4);
    const int bidx  = lane & 7;
    const int bkh   = (lane >> 3) & 1;
    const int bsub  = lane >> 4;

    load_stage(0); CP_ASYNC_COMMIT();
    if (nch > 1) load_stage(1);
    CP_ASYNC_COMMIT();
    if (nch > 2) load_stage(2);
    CP_ASYNC_COMMIT();

    for (int c = 0; c < nch; c++) {
        CP_ASYNC_WAIT(2);
        __syncthreads();
        if (c + 3 < nch) load_stage(c + 3);
        CP_ASYNC_COMMIT();

        uint32_t stg = sbase + (uint32_t)(c & 3) * STAGE_B;
        #pragma unroll
        for (int ks = 0; ks < 2; ks++) {
            uint32_t ah[4][4], bh[8][2];
            #pragma unroll
            for (int m = 0; m < 4; m++) {
                uint32_t off = (uint32_t)((warpM * 64 + m * 16 + arow) * (SAS * 2)
                                          + (ks * 16 + ahalf * 8) * 2);
                ldsm_x4(ah[m], stg + AH_OFF + off);
            }
            #pragma unroll
            for (int pr = 0; pr < 4; pr++) {
                uint32_t off = (uint32_t)((warpN * 64 + pr * 16 + bsub * 8 + bidx) * (SAS * 2)
                                          + (ks * 16 + bkh * 8) * 2);
                uint32_t t[4];
                ldsm_x4(t, stg + BH_OFF + off);
                bh[pr * 2][0] = t[0]; bh[pr * 2][1] = t[1];
                bh[pr * 2 + 1][0] = t[2]; bh[pr * 2 + 1][1] = t[3];
            }
            #pragma unroll
            for (int m = 0; m < 4; m++)
                #pragma unroll
                for (int n = 0; n < 8; n++) mma_f16(acc[m][n], ah[m], bh[n]);
        }
    }

    gemm_epilogue<ACT, OUTMODE>(acc, bm, bn, warpM, warpN, lane, bias, Cf, Ch, Ntot);
}

// ================= window attention (uint4 fp16 loads, emits fp16) =================
#define QS 34
#define DS 52
__global__ void __launch_bounds__(256)
attn_kernel(const __half* __restrict__ qkv, const float* __restrict__ tau,
            const float* __restrict__ cpb, __half* __restrict__ outh, int shifted) {
    __shared__ float sq[64 * QS];
    __shared__ float sk[64 * QS];
    __shared__ float sv[49 * QS];
    __shared__ float sd[64 * DS];

    const int wi   = blockIdx.x;
    const int head = blockIdx.y;
    const int b    = blockIdx.z;
    const int wh = wi >> 3, ww = wi & 7;
    const int tid = threadIdx.x;

    // vectorized load: 49 rows x 3 tensors x 4 uint4-chunks (8 halves each)
    for (int e = tid; e < WIN2 * 12; e += 256) {
        int t = e / (WIN2 * 4);
        int rem = e - t * (WIN2 * 4);
        int r = rem >> 2, c = rem & 3;
        int i = r / WIN, j = r % WIN;
        int m = b * Nn + (wh * WIN + i) * Wd + (ww * WIN + j);
        uint4 u = *(const uint4*)(qkv + (size_t)m * 768 + t * 256 + head * HD + c * 8);
        float* dst = (t == 0 ? sq : (t == 1 ? sk : sv)) + r * QS + c * 8;
        const __half2* hp = (const __half2*)&u;
        #pragma unroll
        for (int kk = 0; kk < 4; kk++) {
            float2 f = __half22float2(hp[kk]);
            *(float2*)(dst + kk * 2) = f;
        }
    }
    // zero-pad rows 49..63 of q,k
    for (int e = tid; e < 15 * 32; e += 256) {
        int r = WIN2 + (e >> 5), d = e & 31;
        sq[r * QS + d] = 0.f;
        sk[r * QS + d] = 0.f;
    }
    __syncthreads();

    for (int t = tid; t < 2 * WIN2; t += 256) {
        float* row = (t < WIN2) ? (sq + t * QS) : (sk + (t - WIN2) * QS);
        float s = 0.f;
        #pragma unroll
        for (int d = 0; d < HD; d += 2) {
            float2 v = *(float2*)(row + d);
            s += v.x * v.x + v.y * v.y;
        }
        float inv = 1.f / fmaxf(sqrtf(s), 1e-12f);
        #pragma unroll
        for (int d = 0; d < HD; d += 2) {
            float2 v = *(float2*)(row + d);
            v.x *= inv; v.y *= inv;
            *(float2*)(row + d) = v;
        }
    }
    __syncthreads();

    const float tscale = 1.f / fmaxf(tau[head], 0.01f);
    const int tx = tid & 15, ty = tid >> 4;

    float acc[4][4];
    #pragma unroll
    for (int u = 0; u < 4; u++)
        #pragma unroll
        for (int v = 0; v < 4; v++) acc[u][v] = 0.f;
    #pragma unroll
    for (int kk = 0; kk < HD; kk += 2) {
        float2 a2[4], b2[4];
        #pragma unroll
        for (int u = 0; u < 4; u++) a2[u] = *(float2*)&sq[(ty + u * 16) * QS + kk];
        #pragma unroll
        for (int v = 0; v < 4; v++) b2[v] = *(float2*)&sk[(tx + v * 16) * QS + kk];
        #pragma unroll
        for (int u = 0; u < 4; u++)
            #pragma unroll
            for (int v = 0; v < 4; v++)
                acc[u][v] += a2[u].x * b2[v].x + a2[u].y * b2[v].y;
    }
    #pragma unroll
    for (int u = 0; u < 4; u++) {
        int i = ty + u * 16;
        if (i >= WIN2) continue;
        #pragma unroll
        for (int v = 0; v < 4; v++) {
            int j = tx + v * 16;
            if (j >= WIN2) continue;
            float val = acc[u][v] * tscale + cpb[head * (WIN2 * WIN2) + i * WIN2 + j];
            if (shifted) {
                if (wh == NWH - 1 && ((i >= 28) != (j >= 28))) val = -1e30f;
                if (ww == NWH - 1 && (((i % WIN) >= 4) != ((j % WIN) >= 4))) val = -1e30f;
            }
            sd[i * DS + j] = val;
        }
    }
    __syncthreads();

    const int lane = tid & 31, wrp = tid >> 5;
    for (int r = wrp; r < WIN2; r += 8) {
        float v0 = sd[r * DS + lane];
        float v1 = (lane + 32 < WIN2) ? sd[r * DS + lane + 32] : -3e38f;
        float mx = fmaxf(v0, v1);
        #pragma unroll
        for (int o = 16; o > 0; o >>= 1) mx = fmaxf(mx, __shfl_xor_sync(~0u, mx, o));
        float e0 = __expf(v0 - mx);
        float e1 = (lane + 32 < WIN2) ? __expf(v1 - mx) : 0.f;
        float s = e0 + e1;
        #pragma unroll
        for (int o = 16; o > 0; o >>= 1) s += __shfl_xor_sync(~0u, s, o);
        float inv = 1.f / s;
        sd[r * DS + lane] = e0 * inv;
        if (lane + 32 < WIN2) sd[r * DS + lane + 32] = e1 * inv;
    }
    __syncthreads();

    float o2[4][2];
    #pragma unroll
    for (int u = 0; u < 4; u++) { o2[u][0] = 0.f; o2[u][1] = 0.f; }
    for (int j = 0; j < 48; j += 2) {
        float2 p2[4];
        #pragma unroll
        for (int u = 0; u < 4; u++) p2[u] = *(float2*)&sd[(ty + u * 16) * DS + j];
        float2 va = *(float2*)&sv[j * QS + tx * 2];
        float2 vb = *(float2*)&sv[(j + 1) * QS + tx * 2];
        #pragma unroll
        for (int u = 0; u < 4; u++) {
            o2[u][0] += p2[u].x * va.x + p2[u].y * vb.x;
            o2[u][1] += p2[u].x * va.y + p2[u].y * vb.y;
        }
    }
    {
        float2 vc = *(float2*)&sv[48 * QS + tx * 2];
        #pragma unroll
        for (int u = 0; u < 4; u++) {
            float p = sd[(ty + u * 16) * DS + 48];
            o2[u][0] += p * vc.x;
            o2[u][1] += p * vc.y;
        }
    }
    #pragma unroll
    for (int u = 0; u < 4; u++) {
        int i = ty + u * 16;
        if (i < WIN2) {
            int ii = i / WIN, jj = i % WIN;
            int m = b * Nn + (wh * WIN + ii) * Wd + (ww * WIN + jj);
            size_t off = (size_t)m * Dd + head * HD + tx * 2;
            *(uint32_t*)(outh + off) = pack_h2(o2[u][0], o2[u][1]);
        }
    }
}

// ================= LN + residual (reads fp16 A) =================
__global__ void ln_residual_kernel(const __half* __restrict__ A, const float* __restrict__ g,
                                   const float* __restrict__ be, float* __restrict__ xm,
                                   __half* __restrict__ xh, int gather) {
    int row = blockIdx.x * 8 + (threadIdx.x >> 5);
    int lane = threadIdx.x & 31;
    int src = row;
    if (gather) {
        int b = row / Nn, rem = row % Nn;
        int h = rem / Wd, w = rem % Wd;
        src = b * Nn + ((h + Hh - DISP) % Hh) * Wd + ((w + Wd - DISP) % Wd);
    }
    // lane handles columns [lane*8, lane*8+8)
    uint4 av = ((const uint4*)(A + (size_t)src * Dd))[lane];
    const __half2* hp = (const __half2*)&av;
    float vals[8];
    #pragma unroll
    for (int k = 0; k < 4; k++) {
        float2 f = __half22float2(hp[k]);
        vals[2 * k] = f.x; vals[2 * k + 1] = f.y;
    }
    float s = 0.f, s2 = 0.f;
    #pragma unroll
    for (int k = 0; k < 8; k++) { s += vals[k]; s2 += vals[k] * vals[k]; }
    #pragma unroll
    for (int o = 16; o > 0; o >>= 1) {
        s  += __shfl_xor_sync(~0u, s, o);
        s2 += __shfl_xor_sync(~0u, s2, o);
    }
    float mean = s * (1.f / Dd);
    float var  = s2 * (1.f / Dd) - mean * mean;
    float inv  = rsqrtf(var + EPSLN);

    float4 g0 = ((const float4*)g)[lane * 2],  g1 = ((const float4*)g)[lane * 2 + 1];
    float4 b0 = ((const float4*)be)[lane * 2], b1 = ((const float4*)be)[lane * 2 + 1];
    float4* x4 = (float4*)(xm + (size_t)row * Dd);
    float4 r0 = x4[lane * 2], r1 = x4[lane * 2 + 1];
    r0.x += (vals[0] - mean) * inv * g0.x + b0.x;
    r0.y += (vals[1] - mean) * inv * g0.y + b0.y;
    r0.z += (vals[2] - mean) * inv * g0.z + b0.z;
    r0.w += (vals[3] - mean) * inv * g0.w + b0.w;
    r1.x += (vals[4] - mean) * inv * g1.x + b1.x;
    r1.y += (vals[5] - mean) * inv * g1.y + b1.y;
    r1.z += (vals[6] - mean) * inv * g1.z + b1.z;
    r1.w += (vals[7] - mean) * inv * g1.w + b1.w;
    x4[lane * 2] = r0; x4[lane * 2 + 1] = r1;

    uint2 h;
    size_t e0 = (size_t)row * Dd + lane * 8;
    h.x = pack_h2(r0.x, r0.y); h.y = pack_h2(r0.z, r0.w);
    *(uint2*)(xh + e0) = h;
    h.x = pack_h2(r1.x, r1.y); h.y = pack_h2(r1.z, r1.w);
    *(uint2*)(xh + e0 + 4) = h;
}

// ================= final LN =================
__global__ void ln_final_kernel(const float* __restrict__ A, const float* __restrict__ g,
                                const float* __restrict__ be, float* __restrict__ out) {
    int row = blockIdx.x * 8 + (threadIdx.x >> 5);
    int lane = threadIdx.x & 31;
    const float4* a4 = (const float4*)(A + (size_t)row * Dd);
    float4 v0 = a4[lane], v1 = a4[lane + 32];
    float s  = v0.x + v0.y + v0.z + v0.w + v1.x + v1.y + v1.z + v1.w;
    float s2 = v0.x*v0.x + v0.y*v0.y + v0.z*v0.z + v0.w*v0.w
             + v1.x*v1.x + v1.y*v1.y + v1.z*v1.z + v1.w*v1.w;
    #pragma unroll
    for (int o = 16; o > 0; o >>= 1) {
        s  += __shfl_xor_sync(~0u, s, o);
        s2 += __shfl_xor_sync(~0u, s2, o);
    }
    float mean = s * (1.f / Dd);
    float var  = s2 * (1.f / Dd) - mean * mean;
    float inv  = rsqrtf(var + EPSLN);
    float4 g0 = ((const float4*)g)[lane],  g1 = ((const float4*)g)[lane + 32];
    float4 b0 = ((const float4*)be)[lane], b1 = ((const float4*)be)[lane + 32];
    float4 o0, o1;
    o0.x = (v0.x - mean) * inv * g0.x + b0.x;
    o0.y = (v0.y - mean) * inv * g0.y + b0.y;
    o0.z = (v0.z - mean) * inv * g0.z + b0.z;
    o0.w = (v0.w - mean) * inv * g0.w + b0.w;
    o1.x = (v1.x - mean) * inv * g1.x + b1.x;
    o1.y = (v1.y - mean) * inv * g1.y + b1.y;
    o1.z = (v1.z - mean) * inv * g1.z + b1.z;
    o1.w = (v1.w - mean) * inv * g1.w + b1.w;
    float4* out4 = (float4*)(out + (size_t)row * Dd);
    out4[lane] = o0; out4[lane + 32] = o1;
}

// ================= launch =================
extern "C" void kernel_launch(void* const* d_in, const int* in_sizes, int n_in,
                              void* d_out, int out_size) {
    const float* x    = (const float*)d_in[0];
    const float* spe  = (const float*)d_in[1];
    const float* qkvw = (const float*)d_in[2];
    const float* tau  = (const float*)d_in[3];
    const float* cw1  = (const float*)d_in[4];
    const float* cb1  = (const float*)d_in[5];
    const float* cw2  = (const float*)d_in[6];
    const float* cb2  = (const float*)d_in[7];
    const float* ow   = (const float*)d_in[8];
    const float* ob   = (const float*)d_in[9];
    const float* ln1g = (const float*)d_in[10];
    const float* ln1b = (const float*)d_in[11];
    const float* fw1  = (const float*)d_in[12];
    const float* fb1  = (const float*)d_in[13];
    const float* fw2  = (const float*)d_in[14];
    const float* fb2  = (const float*)d_in[15];
    const float* ln2g = (const float*)d_in[16];
    const float* ln2b = (const float*)d_in[17];
    const float* ng   = (const float*)d_in[18];
    const float* nb   = (const float*)d_in[19];
    float* out = (float*)d_out;

    float *xm, *cpb;
    __half *xmh, *qkv, *ath, *ffh, *tmph, *wth;
    cudaGetSymbolAddress((void**)&xm,   g_xm);
    cudaGetSymbolAddress((void**)&cpb,  g_cpb);
    cudaGetSymbolAddress((void**)&xmh,  g_xmh);
    cudaGetSymbolAddress((void**)&qkv,  g_qkv);
    cudaGetSymbolAddress((void**)&ath,  g_ath);
    cudaGetSymbolAddress((void**)&ffh,  g_ffh);
    cudaGetSymbolAddress((void**)&tmph, g_tmp);
    cudaGetSymbolAddress((void**)&wth,  g_wth);

    cudaFuncSetAttribute(hgemm_persist_kernel<0, false, 1>, cudaFuncAttributeMaxDynamicSharedMemorySize, PGEMM_SMEM);
    cudaFuncSetAttribute(hgemm_persist_kernel<0, true,  1>, cudaFuncAttributeMaxDynamicSharedMemorySize, PGEMM_SMEM);
    cudaFuncSetAttribute(hgemm_persist_kernel<1, false, 1>, cudaFuncAttributeMaxDynamicSharedMemorySize, PGEMM_SMEM);
    cudaFuncSetAttribute(hgemm_kernel<0, 1>, cudaFuncAttributeMaxDynamicSharedMemorySize, GEMM_SMEM);

    // weight transpose + fp16 round, both layers batched via z
    wtconv_kernel<<<dim3(24, 8, 2), dim3(32, 8)>>>(qkvw, wth,          256, 768,
                                                   (size_t)Dd * 768, WLSTRIDE);
    wtconv_kernel<<<dim3(8,  8, 2), dim3(32, 8)>>>(ow,   wth + 196608, 256, 256,
                                                   (size_t)Dd * Dd,  WLSTRIDE);
    wtconv_kernel<<<dim3(32, 8, 2), dim3(32, 8)>>>(fw1,  wth + 262144, 256, 1024,
                                                   (size_t)Dd * FF,  WLSTRIDE);
    wtconv_kernel<<<dim3(8, 32, 2), dim3(32, 8)>>>(fw2,  wth + 524288, 1024, 256,
                                                   (size_t)FF * Dd,  WLSTRIDE);

    // xm = x + spe (+ fp16)
    {
        int n4 = MROWS * Dd / 4;
        add_spe_kernel<<<(n4 + 255) / 256, 256>>>(x, spe, xm, xmh, n4);
    }

    const int lnBlocks = MROWS / 8;
    for (int layer = 0; layer < 2; layer++) {
        int shifted = (layer == 1);
        size_t wo = (size_t)layer * WLSTRIDE;

        cpb_kernel<<<WIN2 * WIN2, 256>>>(cw1 + layer * 2 * CPBH, cb1 + layer * CPBH,
                                         cw2 + layer * CPBH * HEADS, cb2 + layer * HEADS, cpb);

        // qkv = (rolled) xm @ qkv_w -> fp16   (persistent, 6 x 24 = 144 CTAs)
        if (shifted)
            hgemm_persist_kernel<0, true, 1><<<dim3(6, 24), 256, PGEMM_SMEM>>>(
                xmh, wth + wo, nullptr, nullptr, qkv, 768, 24);
        else
            hgemm_persist_kernel<0, false, 1><<<dim3(6, 24), 256, PGEMM_SMEM>>>(
                xmh, wth + wo, nullptr, nullptr, qkv, 768, 24);

        attn_kernel<<<dim3(NW, HEADS, Bb), 256>>>(qkv, tau + layer * HEADS, cpb, ath, shifted);

        // o-proj -> tmp (fp16)   (persistent, 2 x 74 = 148 CTAs)
        hgemm_persist_kernel<0, false, 1><<<dim3(2, 74), 256, PGEMM_SMEM>>>(
            ath, wth + wo + 196608, ob + layer * Dd, nullptr, tmph, 256, 74);

        // xm += LN(oproj) (rolled back if shifted)
        ln_residual_kernel<<<lnBlocks, 256>>>(tmph, ln1g + layer * Dd, ln1b + layer * Dd,
                                              xm, xmh, shifted);

        // ffn1: gelu(xm @ fw1 + fb1) -> fp16   (persistent, 8 x 18 = 144 CTAs)
        hgemm_persist_kernel<1, false, 1><<<dim3(8, 18), 256, PGEMM_SMEM>>>(
            xmh, wth + wo + 262144, fb1 + layer * FF, nullptr, ffh, 1024, 18);

        // ffn2 -> tmp (fp16)   (streaming, K=1024)
        hgemm_kernel<0, 1><<<dim3(2, MROWS / 256), 256, GEMM_SMEM>>>(
            ffh, wth + wo + 524288, fb2 + layer * Dd, nullptr, tmph, 256, 1024);

        // xm += LN(ffn2)
        ln_residual_kernel<<<lnBlocks, 256>>>(tmph, ln2g + layer * Dd, ln2b + layer * Dd,
                                              xm, xmh, 0);
    }

    ln_final_kernel<<<MROWS / 8, 256>>>(xm, ng, nb, out);
}